// round 1
// baseline (speedup 1.0000x reference)
#include <cuda_runtime.h>
#include <math.h>
#include <stdint.h>

#define N_NODES 100000
#define N_EDGES 1600000
#define NFEAT   256
#define NHID    64
#define NHEADS  4
#define NCLASS  40
#define WH2LD   64          // padded width for layer-2 logits
#define LALPHA  0.2f
#define FULLMASK 0xffffffffu

// ---------------- scratch (static device globals; no allocation) ----------------
__device__ float g_Wcat[256 * 256];                    // packed W_heads -> [K=256][C=256]
__device__ float g_W2[256 * WH2LD];                    // W_out zero-padded to 64 cols
__device__ float g_Wh1[(size_t)N_NODES * 256];         // layer1 projected features
__device__ float g_x[(size_t)N_NODES * 256];           // layer1 output (elu, concat heads)
__device__ float g_Wh2[(size_t)N_NODES * WH2LD];       // layer2 logits (pre-attention)
__device__ float4 g_s1src[N_NODES];                    // per-node per-head src scores
__device__ float4 g_s1dst[N_NODES];
__device__ float g_s2src[N_NODES];
__device__ float g_s2dst[N_NODES];
__device__ int g_deg[N_NODES + 1];
__device__ int g_off[N_NODES + 1];
__device__ int g_cursor[N_NODES];
__device__ int g_eid[N_EDGES];
__device__ int g_bsum[128];
__device__ int g_bsum2[128];

// ---------------- helpers ----------------
__device__ __forceinline__ float wredmax(float v) {
#pragma unroll
    for (int o = 16; o; o >>= 1) v = fmaxf(v, __shfl_xor_sync(FULLMASK, v, o));
    return v;
}
__device__ __forceinline__ float wredsum(float v) {
#pragma unroll
    for (int o = 16; o; o >>= 1) v += __shfl_xor_sync(FULLMASK, v, o);
    return v;
}
__device__ __forceinline__ float lrelu(float x) { return x > 0.f ? x : LALPHA * x; }

// ---------------- weight packing ----------------
// Wcat[k][c] = W_heads[c>>6][k][c&63], so Wh1 = h @ Wcat gives concatenated heads.
__global__ void pack_w1(const float* __restrict__ Wh) {
    int idx = blockIdx.x * blockDim.x + threadIdx.x;
    if (idx >= 256 * 256) return;
    int k = idx >> 8, c = idx & 255;
    int head = c >> 6, j = c & 63;
    g_Wcat[idx] = Wh[head * (256 * 64) + k * 64 + j];
}
__global__ void pack_w2(const float* __restrict__ Wo) {
    int idx = blockIdx.x * blockDim.x + threadIdx.x;
    if (idx >= 256 * WH2LD) return;
    int k = idx >> 6, c = idx & 63;
    g_W2[idx] = (c < NCLASS) ? Wo[k * NCLASS + c] : 0.f;
}

// ---------------- generic SGEMM: C[M x BN*gridx] = A[M x K] @ B[K x ldb] ----------------
// BM=128, TK=8, TM=8; 256 threads.
template <int BN, int TN>
__global__ void sgemm_kernel(const float* __restrict__ A, const float* __restrict__ B,
                             float* __restrict__ C, int M, int K, int ldb, int ldc) {
    __shared__ float As[8][128];
    __shared__ float Bs[8][BN];
    const int tid = threadIdx.x;
    const int brow = blockIdx.y * 128;
    const int bcol = blockIdx.x * BN;
    const int tx = tid % (BN / TN);
    const int ty = tid / (BN / TN);

    float acc[8][TN];
#pragma unroll
    for (int i = 0; i < 8; i++)
#pragma unroll
        for (int j = 0; j < TN; j++) acc[i][j] = 0.f;

    const int aRow = tid >> 1;
    const int aCol = (tid & 1) * 4;

    for (int k0 = 0; k0 < K; k0 += 8) {
        float4 av = make_float4(0.f, 0.f, 0.f, 0.f);
        int gr = brow + aRow;
        if (gr < M) av = *(const float4*)(A + (size_t)gr * K + k0 + aCol);
        As[aCol + 0][aRow] = av.x;
        As[aCol + 1][aRow] = av.y;
        As[aCol + 2][aRow] = av.z;
        As[aCol + 3][aRow] = av.w;
#pragma unroll
        for (int i = tid; i < 8 * BN; i += 256) {
            int r = i / BN, c = i % BN;
            Bs[r][c] = B[(size_t)(k0 + r) * ldb + bcol + c];
        }
        __syncthreads();
#pragma unroll
        for (int k = 0; k < 8; k++) {
            float ar[8], br[TN];
#pragma unroll
            for (int i = 0; i < 8; i++) ar[i] = As[k][ty * 8 + i];
#pragma unroll
            for (int j = 0; j < TN; j++) br[j] = Bs[k][tx * TN + j];
#pragma unroll
            for (int i = 0; i < 8; i++)
#pragma unroll
                for (int j = 0; j < TN; j++) acc[i][j] += ar[i] * br[j];
        }
        __syncthreads();
    }
#pragma unroll
    for (int i = 0; i < 8; i++) {
        int gr = brow + ty * 8 + i;
        if (gr >= M) continue;
#pragma unroll
        for (int j = 0; j < TN; j++)
            C[(size_t)gr * ldc + bcol + tx * TN + j] = acc[i][j];
    }
}

// ---------------- per-node attention scores, layer 1 ----------------
// warp per (node, head): s_src = Wh[v, h*64:h*64+64] . a[h][:64], s_dst with a[h][64:128]
__global__ void scores1_kernel(const float* __restrict__ a_heads) {
    int gw = blockIdx.x * 8 + (threadIdx.x >> 5);
    int lane = threadIdx.x & 31;
    if (gw >= N_NODES * NHEADS) return;
    int v = gw >> 2, head = gw & 3;
    const float2 wv = ((const float2*)(g_Wh1 + (size_t)v * 256 + head * 64))[lane];
    const float* ah = a_heads + head * 128;
    float2 as = ((const float2*)ah)[lane];
    float2 ad = ((const float2*)(ah + 64))[lane];
    float p = wv.x * as.x + wv.y * as.y;
    float q = wv.x * ad.x + wv.y * ad.y;
    p = wredsum(p);
    q = wredsum(q);
    if (lane == 0) {
        ((float*)g_s1src)[v * 4 + head] = p;
        ((float*)g_s1dst)[v * 4 + head] = q;
    }
}

// ---------------- CSR build ----------------
__global__ void zero_csr() {
    int i = blockIdx.x * blockDim.x + threadIdx.x;
    if (i <= N_NODES) g_deg[i] = 0;
    if (i < N_NODES) g_cursor[i] = 0;
}
__global__ void count_kernel(const int* __restrict__ dst) {
    int e = blockIdx.x * blockDim.x + threadIdx.x;
    if (e < N_EDGES) atomicAdd(&g_deg[dst[e]], 1);
}
__global__ void scan1_kernel(int n) {  // exclusive scan g_deg -> g_off, block sums to g_bsum
    __shared__ int s[1024];
    int tid = threadIdx.x;
    int gid = blockIdx.x * 1024 + tid;
    int v = (gid < n) ? g_deg[gid] : 0;
    s[tid] = v;
    __syncthreads();
    int t = v;
    for (int d = 1; d < 1024; d <<= 1) {
        int add = (tid >= d) ? s[tid - d] : 0;
        __syncthreads();
        t += add;
        s[tid] = t;
        __syncthreads();
    }
    if (gid < n) g_off[gid] = t - v;
    if (tid == 1023) g_bsum[blockIdx.x] = t;
}
__global__ void scan2_kernel(int nb) {  // exclusive scan of block sums
    __shared__ int s[128];
    int tid = threadIdx.x;
    int v = (tid < nb) ? g_bsum[tid] : 0;
    s[tid] = v;
    __syncthreads();
    int t = v;
    for (int d = 1; d < 128; d <<= 1) {
        int add = (tid >= d) ? s[tid - d] : 0;
        __syncthreads();
        t += add;
        s[tid] = t;
        __syncthreads();
    }
    if (tid < nb) g_bsum2[tid] = t - v;
}
__global__ void scan3_kernel(int n) {
    int i = blockIdx.x * blockDim.x + threadIdx.x;
    if (i < n) g_off[i] += g_bsum2[i >> 10];
}
__global__ void fill_kernel(const int* __restrict__ dst) {
    int e = blockIdx.x * blockDim.x + threadIdx.x;
    if (e >= N_EDGES) return;
    int d = dst[e];
    int pos = g_off[d] + atomicAdd(&g_cursor[d], 1);
    g_eid[pos] = e;
}

// ---------------- layer-1 aggregation: warp per dst node, all 4 heads ----------------
__global__ void agg1_kernel(const int* __restrict__ srcArr) {
    __shared__ float4 sw[8][32];
    __shared__ int ssm[8][32];
    int gw = blockIdx.x * 8 + (threadIdx.x >> 5);
    int lane = threadIdx.x & 31;
    int wl = threadIdx.x >> 5;
    if (gw >= N_NODES) return;
    const int v = gw;
    const int off0 = g_off[v];
    const int deg = g_off[v + 1] - off0;
    const float4 sd = g_s1dst[v];

    // pass 1: per-head max
    float4 mx = make_float4(-3e38f, -3e38f, -3e38f, -3e38f);
    for (int j = lane; j < deg; j += 32) {
        int e = g_eid[off0 + j];
        float4 ss = g_s1src[srcArr[e]];
        mx.x = fmaxf(mx.x, lrelu(ss.x + sd.x));
        mx.y = fmaxf(mx.y, lrelu(ss.y + sd.y));
        mx.z = fmaxf(mx.z, lrelu(ss.z + sd.z));
        mx.w = fmaxf(mx.w, lrelu(ss.w + sd.w));
    }
    mx.x = wredmax(mx.x); mx.y = wredmax(mx.y);
    mx.z = wredmax(mx.z); mx.w = wredmax(mx.w);

    // pass 2: per-head denom
    float4 dn = make_float4(0.f, 0.f, 0.f, 0.f);
    for (int j = lane; j < deg; j += 32) {
        int e = g_eid[off0 + j];
        float4 ss = g_s1src[srcArr[e]];
        dn.x += __expf(lrelu(ss.x + sd.x) - mx.x);
        dn.y += __expf(lrelu(ss.y + sd.y) - mx.y);
        dn.z += __expf(lrelu(ss.z + sd.z) - mx.z);
        dn.w += __expf(lrelu(ss.w + sd.w) - mx.w);
    }
    dn.x = wredsum(dn.x); dn.y = wredsum(dn.y);
    dn.z = wredsum(dn.z); dn.w = wredsum(dn.w);
    float4 inv;
    inv.x = deg > 0 ? 1.f / dn.x : 0.f;
    inv.y = deg > 0 ? 1.f / dn.y : 0.f;
    inv.z = deg > 0 ? 1.f / dn.z : 0.f;
    inv.w = deg > 0 ? 1.f / dn.w : 0.f;

    // pass 3: weighted gather-accumulate. lane owns cols [lane*8, lane*8+8) -> head lane>>3
    float4 a0 = make_float4(0.f, 0.f, 0.f, 0.f);
    float4 a1 = make_float4(0.f, 0.f, 0.f, 0.f);
    const int hsel = lane >> 3;
    const float4* whbase = (const float4*)g_Wh1;

    for (int base = 0; base < deg; base += 32) {
        int j = base + lane;
        float4 w4 = make_float4(0.f, 0.f, 0.f, 0.f);
        int s = 0;
        if (j < deg) {
            int e = g_eid[off0 + j];
            s = srcArr[e];
            float4 ss = g_s1src[s];
            w4.x = __expf(lrelu(ss.x + sd.x) - mx.x) * inv.x;
            w4.y = __expf(lrelu(ss.y + sd.y) - mx.y) * inv.y;
            w4.z = __expf(lrelu(ss.z + sd.z) - mx.z) * inv.z;
            w4.w = __expf(lrelu(ss.w + sd.w) - mx.w) * inv.w;
        }
        sw[wl][lane] = w4;
        ssm[wl][lane] = s;
        __syncwarp();
        int cnt = min(32, deg - base);
        for (int k = 0; k < cnt; k++) {
            int sk = ssm[wl][k];
            float wk = ((const float*)(sw[wl] + k))[hsel];
            const float4* row = whbase + (size_t)sk * 64 + lane * 2;
            float4 r0 = row[0];
            float4 r1 = row[1];
            a0.x += wk * r0.x; a0.y += wk * r0.y; a0.z += wk * r0.z; a0.w += wk * r0.w;
            a1.x += wk * r1.x; a1.y += wk * r1.y; a1.z += wk * r1.z; a1.w += wk * r1.w;
        }
        __syncwarp();
    }

    // ELU + store
    a0.x = a0.x > 0.f ? a0.x : expm1f(a0.x);
    a0.y = a0.y > 0.f ? a0.y : expm1f(a0.y);
    a0.z = a0.z > 0.f ? a0.z : expm1f(a0.z);
    a0.w = a0.w > 0.f ? a0.w : expm1f(a0.w);
    a1.x = a1.x > 0.f ? a1.x : expm1f(a1.x);
    a1.y = a1.y > 0.f ? a1.y : expm1f(a1.y);
    a1.z = a1.z > 0.f ? a1.z : expm1f(a1.z);
    a1.w = a1.w > 0.f ? a1.w : expm1f(a1.w);
    float4* xr = (float4*)(g_x + (size_t)v * 256) + lane * 2;
    xr[0] = a0;
    xr[1] = a1;
}

// ---------------- layer-2 scores ----------------
__global__ void scores2_kernel(const float* __restrict__ a_out) {
    int gw = blockIdx.x * 8 + (threadIdx.x >> 5);
    int lane = threadIdx.x & 31;
    if (gw >= N_NODES) return;
    int v = gw;
    float w0 = g_Wh2[(size_t)v * WH2LD + lane];
    float w1 = (lane < 8) ? g_Wh2[(size_t)v * WH2LD + 32 + lane] : 0.f;
    float p = w0 * a_out[lane] + ((lane < 8) ? w1 * a_out[32 + lane] : 0.f);
    float q = w0 * a_out[NCLASS + lane] + ((lane < 8) ? w1 * a_out[NCLASS + 32 + lane] : 0.f);
    p = wredsum(p);
    q = wredsum(q);
    if (lane == 0) {
        g_s2src[v] = p;
        g_s2dst[v] = q;
    }
}

// ---------------- layer-2 aggregation + fused log_softmax ----------------
__global__ void agg2_kernel(const int* __restrict__ srcArr, float* __restrict__ out) {
    int gw = blockIdx.x * 8 + (threadIdx.x >> 5);
    int lane = threadIdx.x & 31;
    if (gw >= N_NODES) return;
    const int v = gw;
    const int off0 = g_off[v];
    const int deg = g_off[v + 1] - off0;
    const float sd = g_s2dst[v];

    float mx = -3e38f;
    for (int j = lane; j < deg; j += 32) {
        int e = g_eid[off0 + j];
        mx = fmaxf(mx, lrelu(g_s2src[srcArr[e]] + sd));
    }
    mx = wredmax(mx);

    float dn = 0.f;
    for (int j = lane; j < deg; j += 32) {
        int e = g_eid[off0 + j];
        dn += __expf(lrelu(g_s2src[srcArr[e]] + sd) - mx);
    }
    dn = wredsum(dn);
    float inv = deg > 0 ? 1.f / dn : 0.f;

    float acc0 = 0.f, acc1 = 0.f;
    for (int base = 0; base < deg; base += 32) {
        int j = base + lane;
        float w = 0.f;
        int s = 0;
        if (j < deg) {
            int e = g_eid[off0 + j];
            s = srcArr[e];
            w = __expf(lrelu(g_s2src[s] + sd) - mx) * inv;
        }
        int cnt = min(32, deg - base);
        for (int k = 0; k < cnt; k++) {
            int sk = __shfl_sync(FULLMASK, s, k);
            float wk = __shfl_sync(FULLMASK, w, k);
            const float* row = g_Wh2 + (size_t)sk * WH2LD;
            acc0 += wk * row[lane];
            if (lane < 8) acc1 += wk * row[32 + lane];
        }
    }

    // log_softmax over 40 classes (cols: lane in [0,32), lane+32 for lane<8)
    float z1 = (lane < 8) ? acc1 : -3e38f;
    float m = wredmax(fmaxf(acc0, z1));
    float se = __expf(acc0 - m) + ((lane < 8) ? __expf(z1 - m) : 0.f);
    se = wredsum(se);
    float lse = m + logf(se);
    out[(size_t)v * NCLASS + lane] = acc0 - lse;
    if (lane < 8) out[(size_t)v * NCLASS + 32 + lane] = acc1 - lse;
}

// ---------------- launcher ----------------
extern "C" void kernel_launch(void* const* d_in, const int* in_sizes, int n_in,
                              void* d_out, int out_size) {
    const float* h = (const float*)d_in[0];
    const int* ei = (const int*)d_in[1];
    const float* Wheads = (const float*)d_in[2];
    const float* aheads = (const float*)d_in[3];
    const float* Wout = (const float*)d_in[4];
    const float* aout = (const float*)d_in[5];
    const int* src = ei;
    const int* dst = ei + N_EDGES;
    float* out = (float*)d_out;

    float *pWcat, *pW2, *pWh1, *pX, *pWh2;
    cudaGetSymbolAddress((void**)&pWcat, g_Wcat);
    cudaGetSymbolAddress((void**)&pW2, g_W2);
    cudaGetSymbolAddress((void**)&pWh1, g_Wh1);
    cudaGetSymbolAddress((void**)&pX, g_x);
    cudaGetSymbolAddress((void**)&pWh2, g_Wh2);

    const int rowBlocks = (N_NODES + 127) / 128;  // 782

    pack_w1<<<256, 256>>>(Wheads);
    pack_w2<<<64, 256>>>(Wout);

    // GEMM1: Wh1 = h @ Wcat   [100000 x 256]
    sgemm_kernel<128, 8><<<dim3(2, rowBlocks), 256>>>(h, pWcat, pWh1, N_NODES, 256, 256, 256);

    // per-node per-head scores
    scores1_kernel<<<(N_NODES * NHEADS + 7) / 8, 256>>>(aheads);

    // CSR by dst
    zero_csr<<<(N_NODES + 256) / 256, 256>>>();
    count_kernel<<<N_EDGES / 256, 256>>>(dst);
    {
        int n = N_NODES + 1;
        int nb = (n + 1023) / 1024;  // 98
        scan1_kernel<<<nb, 1024>>>(n);
        scan2_kernel<<<1, 128>>>(nb);
        scan3_kernel<<<(n + 255) / 256, 256>>>(n);
    }
    fill_kernel<<<N_EDGES / 256, 256>>>(dst);

    // layer-1 aggregation -> x
    agg1_kernel<<<(N_NODES + 7) / 8, 256>>>(src);

    // GEMM2: Wh2 = x @ W2pad  [100000 x 64], cols >=40 are zero
    sgemm_kernel<64, 4><<<dim3(1, rowBlocks), 256>>>(pX, pW2, pWh2, N_NODES, 256, WH2LD, WH2LD);

    scores2_kernel<<<(N_NODES + 7) / 8, 256>>>(aout);

    // layer-2 aggregation + log_softmax -> out
    agg2_kernel<<<(N_NODES + 7) / 8, 256>>>(src, out);
}

// round 2
// speedup vs baseline: 1.7733x; 1.7733x over previous
#include <cuda_runtime.h>
#include <cuda_bf16.h>
#include <math.h>
#include <stdint.h>

#define N_NODES 100000
#define N_EDGES 1600000
#define NCLASS  40
#define WH2LD   64
#define LALPHA  0.2f
#define FULLMASK 0xffffffffu

// ---------------- scratch (static device globals) ----------------
__device__ __nv_bfloat16 g_W1t_hi[256 * 256];   // Wcat^T [c][k], hi part
__device__ __nv_bfloat16 g_W1t_lo[256 * 256];
__device__ __nv_bfloat16 g_W2t_hi[64 * 256];    // W_out^T padded [c][k]
__device__ __nv_bfloat16 g_W2t_lo[64 * 256];
__device__ float g_Wh1[(size_t)N_NODES * 256];
__device__ float g_x[(size_t)N_NODES * 256];
__device__ float g_Wh2[(size_t)N_NODES * WH2LD];
__device__ float4 g_s1src[N_NODES];
__device__ float4 g_s1dst[N_NODES];
__device__ float g_s2src[N_NODES];
__device__ float g_s2dst[N_NODES];
__device__ int g_deg[N_NODES + 1];
__device__ int g_off[N_NODES + 1];
__device__ int g_cursor[N_NODES];
__device__ int g_eid[N_EDGES];          // holds SRC node id per CSR slot
__device__ int g_bsum[128];
__device__ int g_bsum2[128];
__device__ unsigned g_gmax[10];         // 0-3 s1src max/head, 4-7 s1dst, 8 s2src, 9 s2dst

// ---------------- helpers ----------------
__device__ __forceinline__ float wredmax(float v) {
#pragma unroll
    for (int o = 16; o; o >>= 1) v = fmaxf(v, __shfl_xor_sync(FULLMASK, v, o));
    return v;
}
__device__ __forceinline__ float wredsum(float v) {
#pragma unroll
    for (int o = 16; o; o >>= 1) v += __shfl_xor_sync(FULLMASK, v, o);
    return v;
}
__device__ __forceinline__ float lrelu(float x) { return x > 0.f ? x : LALPHA * x; }
__device__ __forceinline__ unsigned encf(float f) {
    int i = __float_as_int(f);
    return (i < 0) ? ~(unsigned)i : ((unsigned)i | 0x80000000u);
}
__device__ __forceinline__ float decf(unsigned u) {
    int i = (u & 0x80000000u) ? (int)(u & 0x7fffffffu) : ~(int)u;
    return __int_as_float(i);
}
__device__ __forceinline__ void mma16816(float* c, const unsigned* a, const unsigned* b) {
    asm volatile(
        "mma.sync.aligned.m16n8k16.row.col.f32.bf16.bf16.f32 "
        "{%0,%1,%2,%3},{%4,%5,%6,%7},{%8,%9},{%0,%1,%2,%3};"
        : "+f"(c[0]), "+f"(c[1]), "+f"(c[2]), "+f"(c[3])
        : "r"(a[0]), "r"(a[1]), "r"(a[2]), "r"(a[3]), "r"(b[0]), "r"(b[1]));
}

// ---------------- weight packing (transposed, hi/lo split) ----------------
__global__ void pack_w1(const float* __restrict__ Wh) {
    int idx = blockIdx.x * blockDim.x + threadIdx.x;
    if (idx >= 256 * 256) return;
    int c = idx >> 8, k = idx & 255;
    int head = c >> 6, j = c & 63;
    float v = Wh[head * (256 * 64) + k * 64 + j];
    __nv_bfloat16 hi = __float2bfloat16_rn(v);
    g_W1t_hi[c * 256 + k] = hi;
    g_W1t_lo[c * 256 + k] = __float2bfloat16_rn(v - __bfloat162float(hi));
}
__global__ void pack_w2(const float* __restrict__ Wo) {
    int idx = blockIdx.x * blockDim.x + threadIdx.x;
    if (idx >= 64 * 256) return;
    int c = idx >> 8, k = idx & 255;
    float v = (c < NCLASS) ? Wo[k * NCLASS + c] : 0.f;
    __nv_bfloat16 hi = __float2bfloat16_rn(v);
    g_W2t_hi[c * 256 + k] = hi;
    g_W2t_lo[c * 256 + k] = __float2bfloat16_rn(v - __bfloat162float(hi));
}

// ---------------- split-bf16 tensor-core GEMM: C[M x BN*gridx] = A[M x 256] @ Bt^T ----------------
// A fp32 row-major (converted to hi/lo on the fly). Bt row-major [N][256] bf16 (hi & lo).
// BM=128, BK=32, 256 threads. 3-term: AhBh + AhBl + AlBh.
template <int BN, int WMW, int WNW>
__global__ __launch_bounds__(256) void gemm_bf16x3(
    const float* __restrict__ A, const __nv_bfloat16* __restrict__ Bth,
    const __nv_bfloat16* __restrict__ Btl, float* __restrict__ C, int M, int ldc) {
    constexpr int WM = 128 / WMW;
    constexpr int WN = BN / WNW;
    constexpr int MI = WM / 16;
    constexpr int NI = WN / 8;
    constexpr int LDS_ = 40;  // 32 + 8 pad (bf16 elems)

    __shared__ __nv_bfloat16 sAh[128 * LDS_];
    __shared__ __nv_bfloat16 sAl[128 * LDS_];
    __shared__ __nv_bfloat16 sBh[BN * LDS_];
    __shared__ __nv_bfloat16 sBl[BN * LDS_];

    const int tid = threadIdx.x, lane = tid & 31, wid = tid >> 5;
    const int wm = wid / WNW, wn = wid % WNW;
    const int brow = blockIdx.y * 128, bcol = blockIdx.x * BN;
    const int g = lane >> 2, t = lane & 3;

    float acc[MI][NI][4];
#pragma unroll
    for (int mi = 0; mi < MI; mi++)
#pragma unroll
        for (int ni = 0; ni < NI; ni++)
#pragma unroll
            for (int q = 0; q < 4; q++) acc[mi][ni][q] = 0.f;

    for (int k0 = 0; k0 < 256; k0 += 32) {
        // stage A (fp32 -> hi/lo bf16)
#pragma unroll
        for (int it = 0; it < 4; it++) {
            int idx = tid + it * 256;
            int row = idx >> 3, c4 = idx & 7;
            int gr = brow + row;
            float4 v = make_float4(0.f, 0.f, 0.f, 0.f);
            if (gr < M) v = *(const float4*)(A + (size_t)gr * 256 + k0 + c4 * 4);
            float vv[4] = {v.x, v.y, v.z, v.w};
            __nv_bfloat16 h[4], l[4];
#pragma unroll
            for (int j = 0; j < 4; j++) {
                h[j] = __float2bfloat16_rn(vv[j]);
                l[j] = __float2bfloat16_rn(vv[j] - __bfloat162float(h[j]));
            }
            __nv_bfloat162 h01, h23, l01, l23;
            h01.x = h[0]; h01.y = h[1]; h23.x = h[2]; h23.y = h[3];
            l01.x = l[0]; l01.y = l[1]; l23.x = l[2]; l23.y = l[3];
            int so = row * LDS_ + c4 * 4;
            *(__nv_bfloat162*)&sAh[so] = h01;
            *(__nv_bfloat162*)&sAh[so + 2] = h23;
            *(__nv_bfloat162*)&sAl[so] = l01;
            *(__nv_bfloat162*)&sAl[so + 2] = l23;
        }
        // stage B (bf16 uint4 copies)
#pragma unroll
        for (int it = 0; it < (BN * 4) / 256; it++) {
            int idx = tid + it * 256;
            int row = idx >> 2, c8 = idx & 3;
            int so = row * LDS_ + c8 * 8;
            size_t go = (size_t)(bcol + row) * 256 + k0 + c8 * 8;
            *(uint4*)&sBh[so] = *(const uint4*)(Bth + go);
            *(uint4*)&sBl[so] = *(const uint4*)(Btl + go);
        }
        __syncthreads();

#pragma unroll
        for (int kk = 0; kk < 32; kk += 16) {
            unsigned ah[MI][4], al[MI][4], bh[NI][2], bl[NI][2];
#pragma unroll
            for (int mi = 0; mi < MI; mi++) {
                int r0 = (wm * WM + mi * 16 + g) * LDS_ + kk + 2 * t;
                int r1 = r0 + 8 * LDS_;
                ah[mi][0] = *(const unsigned*)&sAh[r0];
                ah[mi][1] = *(const unsigned*)&sAh[r1];
                ah[mi][2] = *(const unsigned*)&sAh[r0 + 8];
                ah[mi][3] = *(const unsigned*)&sAh[r1 + 8];
                al[mi][0] = *(const unsigned*)&sAl[r0];
                al[mi][1] = *(const unsigned*)&sAl[r1];
                al[mi][2] = *(const unsigned*)&sAl[r0 + 8];
                al[mi][3] = *(const unsigned*)&sAl[r1 + 8];
            }
#pragma unroll
            for (int ni = 0; ni < NI; ni++) {
                int n0 = (wn * WN + ni * 8 + g) * LDS_ + kk + 2 * t;
                bh[ni][0] = *(const unsigned*)&sBh[n0];
                bh[ni][1] = *(const unsigned*)&sBh[n0 + 8];
                bl[ni][0] = *(const unsigned*)&sBl[n0];
                bl[ni][1] = *(const unsigned*)&sBl[n0 + 8];
            }
#pragma unroll
            for (int mi = 0; mi < MI; mi++)
#pragma unroll
                for (int ni = 0; ni < NI; ni++) {
                    mma16816(acc[mi][ni], ah[mi], bh[ni]);
                    mma16816(acc[mi][ni], ah[mi], bl[ni]);
                    mma16816(acc[mi][ni], al[mi], bh[ni]);
                }
        }
        __syncthreads();
    }

#pragma unroll
    for (int mi = 0; mi < MI; mi++) {
        int r = brow + wm * WM + mi * 16 + g;
#pragma unroll
        for (int ni = 0; ni < NI; ni++) {
            int c = bcol + wn * WN + ni * 8 + 2 * t;
            if (r < M) {
                C[(size_t)r * ldc + c] = acc[mi][ni][0];
                C[(size_t)r * ldc + c + 1] = acc[mi][ni][1];
            }
            if (r + 8 < M) {
                C[(size_t)(r + 8) * ldc + c] = acc[mi][ni][2];
                C[(size_t)(r + 8) * ldc + c + 1] = acc[mi][ni][3];
            }
        }
    }
}

// ---------------- layer-1 scores: warp per node, all 4 heads ----------------
__global__ void scores1_kernel(const float* __restrict__ a_heads) {
    int node = blockIdx.x * 8 + (threadIdx.x >> 5);
    int lane = threadIdx.x & 31;
    if (node >= N_NODES) return;
    const float4* rp = (const float4*)(g_Wh1 + (size_t)node * 256);
    float4 u0 = rp[lane * 2];
    float4 u1 = rp[lane * 2 + 1];
    int head = lane >> 3;
    int loc = (lane & 7) * 8;
    const float* ah = a_heads + head * 128;
    float4 s0 = *(const float4*)(ah + loc);
    float4 s1 = *(const float4*)(ah + loc + 4);
    float4 d0 = *(const float4*)(ah + 64 + loc);
    float4 d1 = *(const float4*)(ah + 64 + loc + 4);
    float p = u0.x * s0.x + u0.y * s0.y + u0.z * s0.z + u0.w * s0.w +
              u1.x * s1.x + u1.y * s1.y + u1.z * s1.z + u1.w * s1.w;
    float q = u0.x * d0.x + u0.y * d0.y + u0.z * d0.z + u0.w * d0.w +
              u1.x * d1.x + u1.y * d1.y + u1.z * d1.z + u1.w * d1.w;
#pragma unroll
    for (int o = 4; o; o >>= 1) {
        p += __shfl_xor_sync(FULLMASK, p, o);
        q += __shfl_xor_sync(FULLMASK, q, o);
    }
    if ((lane & 7) == 0) {
        ((float*)g_s1src)[node * 4 + head] = p;
        ((float*)g_s1dst)[node * 4 + head] = q;
    }
}

// ---------------- global max reductions ----------------
__global__ void maxred1_kernel() {
    int tid = blockIdx.x * 256 + threadIdx.x;
    int stride = gridDim.x * 256;
    float ms[4], md[4];
#pragma unroll
    for (int h = 0; h < 4; h++) { ms[h] = -3e38f; md[h] = -3e38f; }
    for (int i = tid; i < N_NODES; i += stride) {
        float4 v = g_s1src[i];
        ms[0] = fmaxf(ms[0], v.x); ms[1] = fmaxf(ms[1], v.y);
        ms[2] = fmaxf(ms[2], v.z); ms[3] = fmaxf(ms[3], v.w);
        float4 d = g_s1dst[i];
        md[0] = fmaxf(md[0], d.x); md[1] = fmaxf(md[1], d.y);
        md[2] = fmaxf(md[2], d.z); md[3] = fmaxf(md[3], d.w);
    }
#pragma unroll
    for (int h = 0; h < 4; h++) { ms[h] = wredmax(ms[h]); md[h] = wredmax(md[h]); }
    if ((threadIdx.x & 31) == 0) {
#pragma unroll
        for (int h = 0; h < 4; h++) {
            atomicMax(&g_gmax[h], encf(ms[h]));
            atomicMax(&g_gmax[4 + h], encf(md[h]));
        }
    }
}
__global__ void maxred2_kernel() {
    int tid = blockIdx.x * 256 + threadIdx.x;
    int stride = gridDim.x * 256;
    float ms = -3e38f, md = -3e38f;
    for (int i = tid; i < N_NODES; i += stride) {
        ms = fmaxf(ms, g_s2src[i]);
        md = fmaxf(md, g_s2dst[i]);
    }
    ms = wredmax(ms);
    md = wredmax(md);
    if ((threadIdx.x & 31) == 0) {
        atomicMax(&g_gmax[8], encf(ms));
        atomicMax(&g_gmax[9], encf(md));
    }
}

// ---------------- CSR build ----------------
__global__ void zero_csr() {
    int i = blockIdx.x * blockDim.x + threadIdx.x;
    if (i <= N_NODES) g_deg[i] = 0;
    if (i < N_NODES) g_cursor[i] = 0;
    if (i < 10) g_gmax[i] = encf(-3e38f);
}
__global__ void count_kernel(const int* __restrict__ dst) {
    int e = blockIdx.x * blockDim.x + threadIdx.x;
    if (e < N_EDGES) atomicAdd(&g_deg[dst[e]], 1);
}
__global__ void scan1_kernel(int n) {
    __shared__ int s[1024];
    int tid = threadIdx.x;
    int gid = blockIdx.x * 1024 + tid;
    int v = (gid < n) ? g_deg[gid] : 0;
    s[tid] = v;
    __syncthreads();
    int t = v;
    for (int d = 1; d < 1024; d <<= 1) {
        int add = (tid >= d) ? s[tid - d] : 0;
        __syncthreads();
        t += add;
        s[tid] = t;
        __syncthreads();
    }
    if (gid < n) g_off[gid] = t - v;
    if (tid == 1023) g_bsum[blockIdx.x] = t;
}
__global__ void scan2_kernel(int nb) {
    __shared__ int s[128];
    int tid = threadIdx.x;
    int v = (tid < nb) ? g_bsum[tid] : 0;
    s[tid] = v;
    __syncthreads();
    int t = v;
    for (int d = 1; d < 128; d <<= 1) {
        int add = (tid >= d) ? s[tid - d] : 0;
        __syncthreads();
        t += add;
        s[tid] = t;
        __syncthreads();
    }
    if (tid < nb) g_bsum2[tid] = t - v;
}
__global__ void scan3_kernel(int n) {
    int i = blockIdx.x * blockDim.x + threadIdx.x;
    if (i < n) g_off[i] += g_bsum2[i >> 10];
}
__global__ void fill_kernel(const int* __restrict__ dst, const int* __restrict__ src) {
    int e = blockIdx.x * blockDim.x + threadIdx.x;
    if (e >= N_EDGES) return;
    int d = dst[e];
    int pos = g_off[d] + atomicAdd(&g_cursor[d], 1);
    g_eid[pos] = src[e];  // store src node directly
}

// ---------------- layer-1 aggregation: single pass, warp per dst node ----------------
__global__ void agg1_kernel() {
    __shared__ float4 sw[8][32];
    __shared__ int ssm[8][32];
    int gw = blockIdx.x * 8 + (threadIdx.x >> 5);
    int lane = threadIdx.x & 31;
    int wl = threadIdx.x >> 5;
    if (gw >= N_NODES) return;
    const int v = gw;
    const int off0 = g_off[v];
    const int deg = g_off[v + 1] - off0;
    const float4 sd = g_s1dst[v];

    float4 mx;
    mx.x = lrelu(decf(g_gmax[0]) + decf(g_gmax[4]));
    mx.y = lrelu(decf(g_gmax[1]) + decf(g_gmax[5]));
    mx.z = lrelu(decf(g_gmax[2]) + decf(g_gmax[6]));
    mx.w = lrelu(decf(g_gmax[3]) + decf(g_gmax[7]));

    float4 dn = make_float4(0.f, 0.f, 0.f, 0.f);
    float4 a0 = make_float4(0.f, 0.f, 0.f, 0.f);
    float4 a1 = make_float4(0.f, 0.f, 0.f, 0.f);
    const int hsel = lane >> 3;
    const float4* whbase = (const float4*)g_Wh1;

    for (int base = 0; base < deg; base += 32) {
        int j = base + lane;
        float4 w4 = make_float4(0.f, 0.f, 0.f, 0.f);
        int s = 0;
        if (j < deg) {
            s = g_eid[off0 + j];
            float4 ss = g_s1src[s];
            w4.x = __expf(lrelu(ss.x + sd.x) - mx.x);
            w4.y = __expf(lrelu(ss.y + sd.y) - mx.y);
            w4.z = __expf(lrelu(ss.z + sd.z) - mx.z);
            w4.w = __expf(lrelu(ss.w + sd.w) - mx.w);
            dn.x += w4.x; dn.y += w4.y; dn.z += w4.z; dn.w += w4.w;
        }
        sw[wl][lane] = w4;
        ssm[wl][lane] = s;
        __syncwarp();
        int cnt = min(32, deg - base);
        for (int k = 0; k < cnt; k++) {
            int sk = ssm[wl][k];
            float wk = ((const float*)(sw[wl] + k))[hsel];
            const float4* row = whbase + (size_t)sk * 64 + lane * 2;
            float4 r0 = row[0];
            float4 r1 = row[1];
            a0.x += wk * r0.x; a0.y += wk * r0.y; a0.z += wk * r0.z; a0.w += wk * r0.w;
            a1.x += wk * r1.x; a1.y += wk * r1.y; a1.z += wk * r1.z; a1.w += wk * r1.w;
        }
        __syncwarp();
    }

    dn.x = wredsum(dn.x); dn.y = wredsum(dn.y);
    dn.z = wredsum(dn.z); dn.w = wredsum(dn.w);
    float inv0 = (deg > 0) ? 1.f / dn.x : 0.f;
    float inv1 = (deg > 0) ? 1.f / dn.y : 0.f;
    float inv2 = (deg > 0) ? 1.f / dn.z : 0.f;
    float inv3 = (deg > 0) ? 1.f / dn.w : 0.f;
    float invh = (hsel == 0) ? inv0 : (hsel == 1) ? inv1 : (hsel == 2) ? inv2 : inv3;

    a0.x *= invh; a0.y *= invh; a0.z *= invh; a0.w *= invh;
    a1.x *= invh; a1.y *= invh; a1.z *= invh; a1.w *= invh;

    a0.x = a0.x > 0.f ? a0.x : expm1f(a0.x);
    a0.y = a0.y > 0.f ? a0.y : expm1f(a0.y);
    a0.z = a0.z > 0.f ? a0.z : expm1f(a0.z);
    a0.w = a0.w > 0.f ? a0.w : expm1f(a0.w);
    a1.x = a1.x > 0.f ? a1.x : expm1f(a1.x);
    a1.y = a1.y > 0.f ? a1.y : expm1f(a1.y);
    a1.z = a1.z > 0.f ? a1.z : expm1f(a1.z);
    a1.w = a1.w > 0.f ? a1.w : expm1f(a1.w);
    float4* xr = (float4*)(g_x + (size_t)v * 256) + lane * 2;
    xr[0] = a0;
    xr[1] = a1;
}

// ---------------- layer-2 scores ----------------
__global__ void scores2_kernel(const float* __restrict__ a_out) {
    int gw = blockIdx.x * 8 + (threadIdx.x >> 5);
    int lane = threadIdx.x & 31;
    if (gw >= N_NODES) return;
    int v = gw;
    float w0 = g_Wh2[(size_t)v * WH2LD + lane];
    float w1 = (lane < 8) ? g_Wh2[(size_t)v * WH2LD + 32 + lane] : 0.f;
    float p = w0 * a_out[lane] + ((lane < 8) ? w1 * a_out[32 + lane] : 0.f);
    float q = w0 * a_out[NCLASS + lane] + ((lane < 8) ? w1 * a_out[NCLASS + 32 + lane] : 0.f);
    p = wredsum(p);
    q = wredsum(q);
    if (lane == 0) {
        g_s2src[v] = p;
        g_s2dst[v] = q;
    }
}

// ---------------- layer-2 aggregation + log_softmax: single pass ----------------
__global__ void agg2_kernel(float* __restrict__ out) {
    int gw = blockIdx.x * 8 + (threadIdx.x >> 5);
    int lane = threadIdx.x & 31;
    if (gw >= N_NODES) return;
    const int v = gw;
    const int off0 = g_off[v];
    const int deg = g_off[v + 1] - off0;
    const float sd = g_s2dst[v];
    const float mx = lrelu(decf(g_gmax[8]) + decf(g_gmax[9]));

    float dn = 0.f;
    float acc0 = 0.f, acc1 = 0.f;
    for (int base = 0; base < deg; base += 32) {
        int j = base + lane;
        float w = 0.f;
        int s = 0;
        if (j < deg) {
            s = g_eid[off0 + j];
            w = __expf(lrelu(g_s2src[s] + sd) - mx);
            dn += w;
        }
        int cnt = min(32, deg - base);
        for (int k = 0; k < cnt; k++) {
            int sk = __shfl_sync(FULLMASK, s, k);
            float wk = __shfl_sync(FULLMASK, w, k);
            const float* row = g_Wh2 + (size_t)sk * WH2LD;
            acc0 += wk * row[lane];
            if (lane < 8) acc1 += wk * row[32 + lane];
        }
    }
    dn = wredsum(dn);
    float inv = (deg > 0) ? 1.f / dn : 0.f;
    acc0 *= inv;
    acc1 *= inv;

    float z1 = (lane < 8) ? acc1 : -3e38f;
    float m = wredmax(fmaxf(acc0, z1));
    float se = __expf(acc0 - m) + ((lane < 8) ? __expf(z1 - m) : 0.f);
    se = wredsum(se);
    float lse = m + logf(se);
    out[(size_t)v * NCLASS + lane] = acc0 - lse;
    if (lane < 8) out[(size_t)v * NCLASS + 32 + lane] = acc1 - lse;
}

// ---------------- launcher ----------------
extern "C" void kernel_launch(void* const* d_in, const int* in_sizes, int n_in,
                              void* d_out, int out_size) {
    const float* h = (const float*)d_in[0];
    const int* ei = (const int*)d_in[1];
    const float* Wheads = (const float*)d_in[2];
    const float* aheads = (const float*)d_in[3];
    const float* Wout = (const float*)d_in[4];
    const float* aout = (const float*)d_in[5];
    const int* src = ei;
    const int* dst = ei + N_EDGES;
    float* out = (float*)d_out;

    float *pWh1, *pX, *pWh2;
    __nv_bfloat16 *pW1h, *pW1l, *pW2h, *pW2l;
    cudaGetSymbolAddress((void**)&pWh1, g_Wh1);
    cudaGetSymbolAddress((void**)&pX, g_x);
    cudaGetSymbolAddress((void**)&pWh2, g_Wh2);
    cudaGetSymbolAddress((void**)&pW1h, g_W1t_hi);
    cudaGetSymbolAddress((void**)&pW1l, g_W1t_lo);
    cudaGetSymbolAddress((void**)&pW2h, g_W2t_hi);
    cudaGetSymbolAddress((void**)&pW2l, g_W2t_lo);

    const int rowBlocks = (N_NODES + 127) / 128;  // 782

    pack_w1<<<256, 256>>>(Wheads);
    pack_w2<<<64, 256>>>(Wout);
    zero_csr<<<(N_NODES + 256) / 256, 256>>>();

    // GEMM1: Wh1 = h @ Wcat   [100000 x 256]   (warp tile 64x32, 8 warps)
    gemm_bf16x3<128, 2, 4><<<dim3(2, rowBlocks), 256>>>(h, pW1h, pW1l, pWh1, N_NODES, 256);

    scores1_kernel<<<(N_NODES + 7) / 8, 256>>>(aheads);
    maxred1_kernel<<<96, 256>>>();

    count_kernel<<<N_EDGES / 256, 256>>>(dst);
    {
        int n = N_NODES + 1;
        int nb = (n + 1023) / 1024;  // 98
        scan1_kernel<<<nb, 1024>>>(n);
        scan2_kernel<<<1, 128>>>(nb);
        scan3_kernel<<<(n + 255) / 256, 256>>>(n);
    }
    fill_kernel<<<N_EDGES / 256, 256>>>(dst, src);

    agg1_kernel<<<(N_NODES + 7) / 8, 256>>>();

    // GEMM2: Wh2 = x @ W2pad  [100000 x 64]   (warp tile 32x32, 8 warps)
    gemm_bf16x3<64, 4, 2><<<dim3(1, rowBlocks), 256>>>(pX, pW2h, pW2l, pWh2, N_NODES, WH2LD);

    scores2_kernel<<<(N_NODES + 7) / 8, 256>>>(aout);
    maxred2_kernel<<<96, 256>>>();

    agg2_kernel<<<(N_NODES + 7) / 8, 256>>>(out);
}

// round 3
// speedup vs baseline: 1.7865x; 1.0075x over previous
#include <cuda_runtime.h>
#include <cuda_bf16.h>
#include <math.h>
#include <stdint.h>

#define N_NODES 100000
#define N_EDGES 1600000
#define NCLASS  40
#define WH2LD   64
#define LALPHA  0.2f
#define FULLMASK 0xffffffffu

// ---------------- scratch (static device globals) ----------------
__device__ __nv_bfloat16 g_W1t_hi[256 * 256];   // Wcat^T [c][k], hi part
__device__ __nv_bfloat16 g_W1t_lo[256 * 256];
__device__ __nv_bfloat16 g_W2t_hi[64 * 256];    // W_out^T padded [c][k]
__device__ __nv_bfloat16 g_W2t_lo[64 * 256];
__device__ __nv_bfloat16 g_Ah[(size_t)N_NODES * 256];   // h in hi/lo bf16
__device__ __nv_bfloat16 g_Al[(size_t)N_NODES * 256];
__device__ __nv_bfloat16 g_Xh[(size_t)N_NODES * 256];   // layer-1 output hi/lo
__device__ __nv_bfloat16 g_Xl[(size_t)N_NODES * 256];
__device__ float g_Wh1[(size_t)N_NODES * 256];
__device__ float g_Wh2[(size_t)N_NODES * WH2LD];
__device__ float4 g_s1src[N_NODES];
__device__ float4 g_s1dst[N_NODES];
__device__ float g_s2src[N_NODES];
__device__ float g_s2dst[N_NODES];
__device__ int g_deg[N_NODES + 1];
__device__ int g_off[N_NODES + 1];
__device__ int g_cursor[N_NODES];
__device__ int g_eid[N_EDGES];          // holds SRC node id per CSR slot
__device__ int g_bsum[128];
__device__ int g_bsum2[128];
__device__ unsigned g_gmax[10];

// ---------------- helpers ----------------
__device__ __forceinline__ float wredmax(float v) {
#pragma unroll
    for (int o = 16; o; o >>= 1) v = fmaxf(v, __shfl_xor_sync(FULLMASK, v, o));
    return v;
}
__device__ __forceinline__ float wredsum(float v) {
#pragma unroll
    for (int o = 16; o; o >>= 1) v += __shfl_xor_sync(FULLMASK, v, o);
    return v;
}
__device__ __forceinline__ float lrelu(float x) { return x > 0.f ? x : LALPHA * x; }
__device__ __forceinline__ unsigned encf(float f) {
    int i = __float_as_int(f);
    return (i < 0) ? ~(unsigned)i : ((unsigned)i | 0x80000000u);
}
__device__ __forceinline__ float decf(unsigned u) {
    int i = (u & 0x80000000u) ? (int)(u & 0x7fffffffu) : ~(int)u;
    return __int_as_float(i);
}
__device__ __forceinline__ void mma16816(float* c, const unsigned* a, const unsigned* b) {
    asm volatile(
        "mma.sync.aligned.m16n8k16.row.col.f32.bf16.bf16.f32 "
        "{%0,%1,%2,%3},{%4,%5,%6,%7},{%8,%9},{%0,%1,%2,%3};"
        : "+f"(c[0]), "+f"(c[1]), "+f"(c[2]), "+f"(c[3])
        : "r"(a[0]), "r"(a[1]), "r"(a[2]), "r"(a[3]), "r"(b[0]), "r"(b[1]));
}
__device__ __forceinline__ void ldsm_x4(unsigned* r, unsigned a) {
    asm volatile("ldmatrix.sync.aligned.m8n8.x4.shared.b16 {%0,%1,%2,%3}, [%4];"
                 : "=r"(r[0]), "=r"(r[1]), "=r"(r[2]), "=r"(r[3]) : "r"(a));
}
__device__ __forceinline__ void cp16(unsigned d, const void* s, int sz) {
    asm volatile("cp.async.cg.shared.global [%0], [%1], 16, %2;" :: "r"(d), "l"(s), "r"(sz));
}
__device__ __forceinline__ void cp_commit() { asm volatile("cp.async.commit_group;"); }
template <int NW> __device__ __forceinline__ void cp_wait() {
    asm volatile("cp.async.wait_group %0;" :: "n"(NW));
}

// ---------------- weight packing (transposed, hi/lo split) ----------------
__global__ void pack_w1(const float* __restrict__ Wh) {
    int idx = blockIdx.x * blockDim.x + threadIdx.x;
    if (idx >= 256 * 256) return;
    int c = idx >> 8, k = idx & 255;
    int head = c >> 6, j = c & 63;
    float v = Wh[head * (256 * 64) + k * 64 + j];
    __nv_bfloat16 hi = __float2bfloat16_rn(v);
    g_W1t_hi[c * 256 + k] = hi;
    g_W1t_lo[c * 256 + k] = __float2bfloat16_rn(v - __bfloat162float(hi));
}
__global__ void pack_w2(const float* __restrict__ Wo) {
    int idx = blockIdx.x * blockDim.x + threadIdx.x;
    if (idx >= 64 * 256) return;
    int c = idx >> 8, k = idx & 255;
    float v = (c < NCLASS) ? Wo[k * NCLASS + c] : 0.f;
    __nv_bfloat16 hi = __float2bfloat16_rn(v);
    g_W2t_hi[c * 256 + k] = hi;
    g_W2t_lo[c * 256 + k] = __float2bfloat16_rn(v - __bfloat162float(hi));
}

// ---------------- fp32 -> hi/lo bf16 convert (for h) ----------------
__global__ void convert_hilo(const float* __restrict__ A, __nv_bfloat16* __restrict__ H,
                             __nv_bfloat16* __restrict__ L, int n4) {
    int i = blockIdx.x * blockDim.x + threadIdx.x;
    if (i >= n4) return;
    float4 v = ((const float4*)A)[i];
    float vv[4] = {v.x, v.y, v.z, v.w};
    __nv_bfloat16 h[4], l[4];
#pragma unroll
    for (int j = 0; j < 4; j++) {
        h[j] = __float2bfloat16_rn(vv[j]);
        l[j] = __float2bfloat16_rn(vv[j] - __bfloat162float(h[j]));
    }
    __nv_bfloat162 h01, h23, l01, l23;
    h01.x = h[0]; h01.y = h[1]; h23.x = h[2]; h23.y = h[3];
    l01.x = l[0]; l01.y = l[1]; l23.x = l[2]; l23.y = l[3];
    uint2 hp, lp;
    hp.x = *(unsigned*)&h01; hp.y = *(unsigned*)&h23;
    lp.x = *(unsigned*)&l01; lp.y = *(unsigned*)&l23;
    ((uint2*)H)[i] = hp;
    ((uint2*)L)[i] = lp;
}

// ---------------- pipelined split-bf16 tensor-core GEMM ----------------
// C[M x BN] = A[M x 256] @ Bt^T; A,B given as hi/lo bf16. 2-stage cp.async,
// ldmatrix fragments, 3-term mma (AhBh + AhBl + AlBh). BM=128, BK=32.
template <int BN, int THREADS, int WMW, int WNW>
__global__ __launch_bounds__(THREADS, 1) void gemm_pipe(
    const __nv_bfloat16* __restrict__ Ah, const __nv_bfloat16* __restrict__ Al,
    const __nv_bfloat16* __restrict__ Bth, const __nv_bfloat16* __restrict__ Btl,
    float* __restrict__ C, int M, int ldc) {
    constexpr int WM = 128 / WMW;
    constexpr int WN = BN / WNW;
    constexpr int MI = WM / 16;
    constexpr int NI = WN / 8;
    constexpr int LDSB = 40;                 // padded row (bf16 elems)
    constexpr int SZA = 128 * LDSB * 2;      // bytes per A stage per array
    constexpr int SZB = BN * LDSB * 2;

    extern __shared__ char smem[];
    char* pAh = smem;
    char* pAl = smem + 2 * SZA;
    char* pBh = smem + 4 * SZA;
    char* pBl = smem + 4 * SZA + 2 * SZB;
    const unsigned uAh = (unsigned)__cvta_generic_to_shared(pAh);
    const unsigned uAl = (unsigned)__cvta_generic_to_shared(pAl);
    const unsigned uBh = (unsigned)__cvta_generic_to_shared(pBh);
    const unsigned uBl = (unsigned)__cvta_generic_to_shared(pBl);

    const int tid = threadIdx.x, lane = tid & 31, wid = tid >> 5;
    const int wm = wid / WNW, wn = wid % WNW;
    const int brow = blockIdx.y * 128;
    const int bcol = blockIdx.x * BN;

    float acc[MI][NI][4];
#pragma unroll
    for (int mi = 0; mi < MI; mi++)
#pragma unroll
        for (int ni = 0; ni < NI; ni++)
#pragma unroll
            for (int q = 0; q < 4; q++) acc[mi][ni][q] = 0.f;

    auto stage = [&](int s, int k0) {
#pragma unroll
        for (int i = tid; i < 512; i += THREADS) {
            int row = i >> 2, c = i & 3;
            int gr = brow + row;
            int ok = (gr < M) ? 16 : 0;
            size_t go = (size_t)min(gr, M - 1) * 256 + k0 + c * 8;
            unsigned dof = (unsigned)(s * SZA + (row * LDSB + c * 8) * 2);
            cp16(uAh + dof, Ah + go, ok);
            cp16(uAl + dof, Al + go, ok);
        }
#pragma unroll
        for (int i = tid; i < BN * 4; i += THREADS) {
            int row = i >> 2, c = i & 3;
            size_t go = (size_t)(bcol + row) * 256 + k0 + c * 8;
            unsigned dof = (unsigned)(s * SZB + (row * LDSB + c * 8) * 2);
            cp16(uBh + dof, Bth + go, 16);
            cp16(uBl + dof, Btl + go, 16);
        }
    };

    stage(0, 0);
    cp_commit();

#pragma unroll
    for (int it = 0; it < 8; it++) {
        const int s = it & 1;
        if (it < 7) {
            stage(s ^ 1, (it + 1) * 32);
            cp_commit();
            cp_wait<1>();
        } else {
            cp_wait<0>();
        }
        __syncthreads();

#pragma unroll
        for (int kk = 0; kk < 32; kk += 16) {
            unsigned ah[MI][4], al[MI][4], bh[NI][2], bl[NI][2];
            const int ra = lane & 15;
            const int kca = (lane >> 4) << 3;
#pragma unroll
            for (int mi = 0; mi < MI; mi++) {
                unsigned off = (unsigned)(((wm * WM + mi * 16 + ra) * LDSB + kk + kca) * 2) +
                               (unsigned)(s * SZA);
                ldsm_x4(ah[mi], uAh + off);
                ldsm_x4(al[mi], uAl + off);
            }
            const int rb = (lane & 7) + ((lane >> 4) << 3);
            const int kcb = ((lane >> 3) & 1) << 3;
#pragma unroll
            for (int nb = 0; nb < NI / 2; nb++) {
                unsigned off = (unsigned)(((wn * WN + nb * 16 + rb) * LDSB + kk + kcb) * 2) +
                               (unsigned)(s * SZB);
                unsigned t4[4];
                ldsm_x4(t4, uBh + off);
                bh[2 * nb][0] = t4[0]; bh[2 * nb][1] = t4[1];
                bh[2 * nb + 1][0] = t4[2]; bh[2 * nb + 1][1] = t4[3];
                ldsm_x4(t4, uBl + off);
                bl[2 * nb][0] = t4[0]; bl[2 * nb][1] = t4[1];
                bl[2 * nb + 1][0] = t4[2]; bl[2 * nb + 1][1] = t4[3];
            }
#pragma unroll
            for (int mi = 0; mi < MI; mi++)
#pragma unroll
                for (int ni = 0; ni < NI; ni++) {
                    mma16816(acc[mi][ni], ah[mi], bh[ni]);
                    mma16816(acc[mi][ni], ah[mi], bl[ni]);
                    mma16816(acc[mi][ni], al[mi], bh[ni]);
                }
        }
        __syncthreads();
    }

    const int g = lane >> 2, t = lane & 3;
#pragma unroll
    for (int mi = 0; mi < MI; mi++) {
        int r = brow + wm * WM + mi * 16 + g;
#pragma unroll
        for (int ni = 0; ni < NI; ni++) {
            int c = bcol + wn * WN + ni * 8 + 2 * t;
            if (r < M) {
                C[(size_t)r * ldc + c] = acc[mi][ni][0];
                C[(size_t)r * ldc + c + 1] = acc[mi][ni][1];
            }
            if (r + 8 < M) {
                C[(size_t)(r + 8) * ldc + c] = acc[mi][ni][2];
                C[(size_t)(r + 8) * ldc + c + 1] = acc[mi][ni][3];
            }
        }
    }
}

// ---------------- layer-1 scores: warp per node, all 4 heads ----------------
__global__ void scores1_kernel(const float* __restrict__ a_heads) {
    int node = blockIdx.x * 8 + (threadIdx.x >> 5);
    int lane = threadIdx.x & 31;
    if (node >= N_NODES) return;
    const float4* rp = (const float4*)(g_Wh1 + (size_t)node * 256);
    float4 u0 = rp[lane * 2];
    float4 u1 = rp[lane * 2 + 1];
    int head = lane >> 3;
    int loc = (lane & 7) * 8;
    const float* ah = a_heads + head * 128;
    float4 s0 = *(const float4*)(ah + loc);
    float4 s1 = *(const float4*)(ah + loc + 4);
    float4 d0 = *(const float4*)(ah + 64 + loc);
    float4 d1 = *(const float4*)(ah + 64 + loc + 4);
    float p = u0.x * s0.x + u0.y * s0.y + u0.z * s0.z + u0.w * s0.w +
              u1.x * s1.x + u1.y * s1.y + u1.z * s1.z + u1.w * s1.w;
    float q = u0.x * d0.x + u0.y * d0.y + u0.z * d0.z + u0.w * d0.w +
              u1.x * d1.x + u1.y * d1.y + u1.z * d1.z + u1.w * d1.w;
#pragma unroll
    for (int o = 4; o; o >>= 1) {
        p += __shfl_xor_sync(FULLMASK, p, o);
        q += __shfl_xor_sync(FULLMASK, q, o);
    }
    if ((lane & 7) == 0) {
        ((float*)g_s1src)[node * 4 + head] = p;
        ((float*)g_s1dst)[node * 4 + head] = q;
    }
}

// ---------------- global max reductions ----------------
__global__ void maxred1_kernel() {
    int tid = blockIdx.x * 256 + threadIdx.x;
    int stride = gridDim.x * 256;
    float ms[4], md[4];
#pragma unroll
    for (int h = 0; h < 4; h++) { ms[h] = -3e38f; md[h] = -3e38f; }
    for (int i = tid; i < N_NODES; i += stride) {
        float4 v = g_s1src[i];
        ms[0] = fmaxf(ms[0], v.x); ms[1] = fmaxf(ms[1], v.y);
        ms[2] = fmaxf(ms[2], v.z); ms[3] = fmaxf(ms[3], v.w);
        float4 d = g_s1dst[i];
        md[0] = fmaxf(md[0], d.x); md[1] = fmaxf(md[1], d.y);
        md[2] = fmaxf(md[2], d.z); md[3] = fmaxf(md[3], d.w);
    }
#pragma unroll
    for (int h = 0; h < 4; h++) { ms[h] = wredmax(ms[h]); md[h] = wredmax(md[h]); }
    if ((threadIdx.x & 31) == 0) {
#pragma unroll
        for (int h = 0; h < 4; h++) {
            atomicMax(&g_gmax[h], encf(ms[h]));
            atomicMax(&g_gmax[4 + h], encf(md[h]));
        }
    }
}
__global__ void maxred2_kernel() {
    int tid = blockIdx.x * 256 + threadIdx.x;
    int stride = gridDim.x * 256;
    float ms = -3e38f, md = -3e38f;
    for (int i = tid; i < N_NODES; i += stride) {
        ms = fmaxf(ms, g_s2src[i]);
        md = fmaxf(md, g_s2dst[i]);
    }
    ms = wredmax(ms);
    md = wredmax(md);
    if ((threadIdx.x & 31) == 0) {
        atomicMax(&g_gmax[8], encf(ms));
        atomicMax(&g_gmax[9], encf(md));
    }
}

// ---------------- CSR build ----------------
__global__ void zero_csr() {
    int i = blockIdx.x * blockDim.x + threadIdx.x;
    if (i <= N_NODES) g_deg[i] = 0;
    if (i < N_NODES) g_cursor[i] = 0;
    if (i < 10) g_gmax[i] = encf(-3e38f);
}
__global__ void count_kernel(const int* __restrict__ dst) {
    int e = blockIdx.x * blockDim.x + threadIdx.x;
    if (e < N_EDGES) atomicAdd(&g_deg[dst[e]], 1);
}
__global__ void scan1_kernel(int n) {
    __shared__ int s[1024];
    int tid = threadIdx.x;
    int gid = blockIdx.x * 1024 + tid;
    int v = (gid < n) ? g_deg[gid] : 0;
    s[tid] = v;
    __syncthreads();
    int t = v;
    for (int d = 1; d < 1024; d <<= 1) {
        int add = (tid >= d) ? s[tid - d] : 0;
        __syncthreads();
        t += add;
        s[tid] = t;
        __syncthreads();
    }
    if (gid < n) g_off[gid] = t - v;
    if (tid == 1023) g_bsum[blockIdx.x] = t;
}
__global__ void scan2_kernel(int nb) {
    __shared__ int s[128];
    int tid = threadIdx.x;
    int v = (tid < nb) ? g_bsum[tid] : 0;
    s[tid] = v;
    __syncthreads();
    int t = v;
    for (int d = 1; d < 128; d <<= 1) {
        int add = (tid >= d) ? s[tid - d] : 0;
        __syncthreads();
        t += add;
        s[tid] = t;
        __syncthreads();
    }
    if (tid < nb) g_bsum2[tid] = t - v;
}
__global__ void scan3_kernel(int n) {
    int i = blockIdx.x * blockDim.x + threadIdx.x;
    if (i < n) g_off[i] += g_bsum2[i >> 10];
}
__global__ void fill_kernel(const int* __restrict__ dst, const int* __restrict__ src) {
    int e = blockIdx.x * blockDim.x + threadIdx.x;
    if (e >= N_EDGES) return;
    int d = dst[e];
    int pos = g_off[d] + atomicAdd(&g_cursor[d], 1);
    g_eid[pos] = src[e];
}

// ---------------- layer-1 aggregation: single pass, warp per dst node ----------------
__global__ void agg1_kernel() {
    __shared__ float4 sw[8][32];
    __shared__ int ssm[8][32];
    int gw = blockIdx.x * 8 + (threadIdx.x >> 5);
    int lane = threadIdx.x & 31;
    int wl = threadIdx.x >> 5;
    if (gw >= N_NODES) return;
    const int v = gw;
    const int off0 = g_off[v];
    const int deg = g_off[v + 1] - off0;
    const float4 sd = g_s1dst[v];

    float4 mx;
    mx.x = lrelu(decf(g_gmax[0]) + decf(g_gmax[4]));
    mx.y = lrelu(decf(g_gmax[1]) + decf(g_gmax[5]));
    mx.z = lrelu(decf(g_gmax[2]) + decf(g_gmax[6]));
    mx.w = lrelu(decf(g_gmax[3]) + decf(g_gmax[7]));

    float4 dn = make_float4(0.f, 0.f, 0.f, 0.f);
    float4 a0 = make_float4(0.f, 0.f, 0.f, 0.f);
    float4 a1 = make_float4(0.f, 0.f, 0.f, 0.f);
    const int hsel = lane >> 3;
    const float4* whbase = (const float4*)g_Wh1;

    for (int base = 0; base < deg; base += 32) {
        int j = base + lane;
        float4 w4 = make_float4(0.f, 0.f, 0.f, 0.f);
        int s = 0;
        if (j < deg) {
            s = g_eid[off0 + j];
            float4 ss = g_s1src[s];
            w4.x = __expf(lrelu(ss.x + sd.x) - mx.x);
            w4.y = __expf(lrelu(ss.y + sd.y) - mx.y);
            w4.z = __expf(lrelu(ss.z + sd.z) - mx.z);
            w4.w = __expf(lrelu(ss.w + sd.w) - mx.w);
            dn.x += w4.x; dn.y += w4.y; dn.z += w4.z; dn.w += w4.w;
        }
        sw[wl][lane] = w4;
        ssm[wl][lane] = s;
        __syncwarp();
        int cnt = min(32, deg - base);
        for (int k = 0; k < cnt; k++) {
            int sk = ssm[wl][k];
            float wk = ((const float*)(sw[wl] + k))[hsel];
            const float4* row = whbase + (size_t)sk * 64 + lane * 2;
            float4 r0 = row[0];
            float4 r1 = row[1];
            a0.x += wk * r0.x; a0.y += wk * r0.y; a0.z += wk * r0.z; a0.w += wk * r0.w;
            a1.x += wk * r1.x; a1.y += wk * r1.y; a1.z += wk * r1.z; a1.w += wk * r1.w;
        }
        __syncwarp();
    }

    dn.x = wredsum(dn.x); dn.y = wredsum(dn.y);
    dn.z = wredsum(dn.z); dn.w = wredsum(dn.w);
    float inv0 = (deg > 0) ? 1.f / dn.x : 0.f;
    float inv1 = (deg > 0) ? 1.f / dn.y : 0.f;
    float inv2 = (deg > 0) ? 1.f / dn.z : 0.f;
    float inv3 = (deg > 0) ? 1.f / dn.w : 0.f;
    float invh = (hsel == 0) ? inv0 : (hsel == 1) ? inv1 : (hsel == 2) ? inv2 : inv3;

    float vv[8];
    vv[0] = a0.x * invh; vv[1] = a0.y * invh; vv[2] = a0.z * invh; vv[3] = a0.w * invh;
    vv[4] = a1.x * invh; vv[5] = a1.y * invh; vv[6] = a1.z * invh; vv[7] = a1.w * invh;
#pragma unroll
    for (int j = 0; j < 8; j++) vv[j] = vv[j] > 0.f ? vv[j] : expm1f(vv[j]);

    // write x as hi/lo bf16 (16B per lane per array)
    __nv_bfloat16 hh[8], ll[8];
#pragma unroll
    for (int j = 0; j < 8; j++) {
        hh[j] = __float2bfloat16_rn(vv[j]);
        ll[j] = __float2bfloat16_rn(vv[j] - __bfloat162float(hh[j]));
    }
    size_t o = (size_t)v * 256 + lane * 8;
    *(uint4*)(g_Xh + o) = *(uint4*)hh;
    *(uint4*)(g_Xl + o) = *(uint4*)ll;
}

// ---------------- layer-2 scores ----------------
__global__ void scores2_kernel(const float* __restrict__ a_out) {
    int gw = blockIdx.x * 8 + (threadIdx.x >> 5);
    int lane = threadIdx.x & 31;
    if (gw >= N_NODES) return;
    int v = gw;
    float w0 = g_Wh2[(size_t)v * WH2LD + lane];
    float w1 = (lane < 8) ? g_Wh2[(size_t)v * WH2LD + 32 + lane] : 0.f;
    float p = w0 * a_out[lane] + ((lane < 8) ? w1 * a_out[32 + lane] : 0.f);
    float q = w0 * a_out[NCLASS + lane] + ((lane < 8) ? w1 * a_out[NCLASS + 32 + lane] : 0.f);
    p = wredsum(p);
    q = wredsum(q);
    if (lane == 0) {
        g_s2src[v] = p;
        g_s2dst[v] = q;
    }
}

// ---------------- layer-2 aggregation + log_softmax: single pass ----------------
__global__ void agg2_kernel(float* __restrict__ out) {
    int gw = blockIdx.x * 8 + (threadIdx.x >> 5);
    int lane = threadIdx.x & 31;
    if (gw >= N_NODES) return;
    const int v = gw;
    const int off0 = g_off[v];
    const int deg = g_off[v + 1] - off0;
    const float sd = g_s2dst[v];
    const float mx = lrelu(decf(g_gmax[8]) + decf(g_gmax[9]));

    float dn = 0.f;
    float acc0 = 0.f, acc1 = 0.f;
    for (int base = 0; base < deg; base += 32) {
        int j = base + lane;
        float w = 0.f;
        int s = 0;
        if (j < deg) {
            s = g_eid[off0 + j];
            w = __expf(lrelu(g_s2src[s] + sd) - mx);
            dn += w;
        }
        int cnt = min(32, deg - base);
        for (int k = 0; k < cnt; k++) {
            int sk = __shfl_sync(FULLMASK, s, k);
            float wk = __shfl_sync(FULLMASK, w, k);
            const float* row = g_Wh2 + (size_t)sk * WH2LD;
            acc0 += wk * row[lane];
            if (lane < 8) acc1 += wk * row[32 + lane];
        }
    }
    dn = wredsum(dn);
    float inv = (deg > 0) ? 1.f / dn : 0.f;
    acc0 *= inv;
    acc1 *= inv;

    float z1 = (lane < 8) ? acc1 : -3e38f;
    float m = wredmax(fmaxf(acc0, z1));
    float se = __expf(acc0 - m) + ((lane < 8) ? __expf(z1 - m) : 0.f);
    se = wredsum(se);
    float lse = m + logf(se);
    out[(size_t)v * NCLASS + lane] = acc0 - lse;
    if (lane < 8) out[(size_t)v * NCLASS + 32 + lane] = acc1 - lse;
}

// ---------------- launcher ----------------
extern "C" void kernel_launch(void* const* d_in, const int* in_sizes, int n_in,
                              void* d_out, int out_size) {
    const float* h = (const float*)d_in[0];
    const int* ei = (const int*)d_in[1];
    const float* Wheads = (const float*)d_in[2];
    const float* aheads = (const float*)d_in[3];
    const float* Wout = (const float*)d_in[4];
    const float* aout = (const float*)d_in[5];
    const int* src = ei;
    const int* dst = ei + N_EDGES;
    float* out = (float*)d_out;

    float *pWh1, *pWh2;
    __nv_bfloat16 *pW1h, *pW1l, *pW2h, *pW2l, *pAh, *pAl, *pXh, *pXl;
    cudaGetSymbolAddress((void**)&pWh1, g_Wh1);
    cudaGetSymbolAddress((void**)&pWh2, g_Wh2);
    cudaGetSymbolAddress((void**)&pW1h, g_W1t_hi);
    cudaGetSymbolAddress((void**)&pW1l, g_W1t_lo);
    cudaGetSymbolAddress((void**)&pW2h, g_W2t_hi);
    cudaGetSymbolAddress((void**)&pW2l, g_W2t_lo);
    cudaGetSymbolAddress((void**)&pAh, g_Ah);
    cudaGetSymbolAddress((void**)&pAl, g_Al);
    cudaGetSymbolAddress((void**)&pXh, g_Xh);
    cudaGetSymbolAddress((void**)&pXl, g_Xl);

    const int rowBlocks = (N_NODES + 127) / 128;  // 782
    constexpr int SMEM1 = 4 * (128 * 40 * 2) + 4 * (256 * 40 * 2);  // 122880
    constexpr int SMEM2 = 4 * (128 * 40 * 2) + 4 * (64 * 40 * 2);   // 61440

    cudaFuncSetAttribute((const void*)gemm_pipe<256, 512, 2, 8>,
                         cudaFuncAttributeMaxDynamicSharedMemorySize, SMEM1);
    cudaFuncSetAttribute((const void*)gemm_pipe<64, 256, 2, 4>,
                         cudaFuncAttributeMaxDynamicSharedMemorySize, SMEM2);

    pack_w1<<<256, 256>>>(Wheads);
    pack_w2<<<64, 256>>>(Wout);
    zero_csr<<<(N_NODES + 256) / 256, 256>>>();
    convert_hilo<<<(N_NODES * 64 + 255) / 256, 256>>>(h, pAh, pAl, N_NODES * 64);

    // GEMM1: Wh1 = h @ Wcat   [100000 x 256]
    gemm_pipe<256, 512, 2, 8><<<dim3(1, rowBlocks), 512, SMEM1>>>(
        pAh, pAl, pW1h, pW1l, pWh1, N_NODES, 256);

    scores1_kernel<<<(N_NODES + 7) / 8, 256>>>(aheads);
    maxred1_kernel<<<96, 256>>>();

    count_kernel<<<N_EDGES / 256, 256>>>(dst);
    {
        int n = N_NODES + 1;
        int nb = (n + 1023) / 1024;  // 98
        scan1_kernel<<<nb, 1024>>>(n);
        scan2_kernel<<<1, 128>>>(nb);
        scan3_kernel<<<(n + 255) / 256, 256>>>(n);
    }
    fill_kernel<<<N_EDGES / 256, 256>>>(dst, src);

    agg1_kernel<<<(N_NODES + 7) / 8, 256>>>();

    // GEMM2: Wh2 = x @ W2pad  [100000 x 64]
    gemm_pipe<64, 256, 2, 4><<<dim3(1, rowBlocks), 256, SMEM2>>>(
        pXh, pXl, pW2h, pW2l, pWh2, N_NODES, WH2LD);

    scores2_kernel<<<(N_NODES + 7) / 8, 256>>>(aout);
    maxred2_kernel<<<96, 256>>>();

    agg2_kernel<<<(N_NODES + 7) / 8, 256>>>(out);
}

// round 5
// speedup vs baseline: 2.4372x; 1.3642x over previous
#include <cuda_runtime.h>
#include <cuda_bf16.h>
#include <cuda_fp16.h>
#include <math.h>
#include <stdint.h>

#define N_NODES 100000
#define N_EDGES 1600000
#define NCLASS  40
#define LALPHA  0.2f
#define FULLMASK 0xffffffffu

// ---------------- scratch (static device globals) ----------------
__device__ __align__(16) __nv_bfloat16 g_W1t_hi[256 * 256];
__device__ __align__(16) __nv_bfloat16 g_W1t_lo[256 * 256];
__device__ __align__(16) __half g_W2f[64 * 256];               // W_out^T padded, fp16
__device__ __align__(16) __nv_bfloat16 g_Ah[(size_t)N_NODES * 256];
__device__ __align__(16) __nv_bfloat16 g_Al[(size_t)N_NODES * 256];
__device__ __align__(16) __half g_Wh1f[(size_t)N_NODES * 256]; // layer1 features fp16
__device__ __align__(16) __half g_Xf[(size_t)N_NODES * 256];   // layer1 output fp16
__device__ __align__(16) __half g_Wh2f[(size_t)N_NODES * 40];  // layer2 logits fp16, stride 40
__device__ float4 g_s1src[N_NODES];
__device__ float4 g_s1dst[N_NODES];
__device__ float g_s2src[N_NODES];
__device__ float g_s2dst[N_NODES];
__device__ int g_deg[N_NODES + 1];
__device__ int g_off[N_NODES + 1];
__device__ int g_cursor[N_NODES];
__device__ int g_eid[N_EDGES];
__device__ int g_bsum[128];
__device__ int g_bsum2[128];
__device__ unsigned g_gmax[10];

// ---------------- helpers ----------------
__device__ __forceinline__ float wredmax(float v) {
#pragma unroll
    for (int o = 16; o; o >>= 1) v = fmaxf(v, __shfl_xor_sync(FULLMASK, v, o));
    return v;
}
__device__ __forceinline__ float wredsum(float v) {
#pragma unroll
    for (int o = 16; o; o >>= 1) v += __shfl_xor_sync(FULLMASK, v, o);
    return v;
}
__device__ __forceinline__ float lrelu(float x) { return x > 0.f ? x : LALPHA * x; }
__device__ __forceinline__ unsigned encf(float f) {
    int i = __float_as_int(f);
    return (i < 0) ? ~(unsigned)i : ((unsigned)i | 0x80000000u);
}
__device__ __forceinline__ float decf(unsigned u) {
    int i = (u & 0x80000000u) ? (int)(u & 0x7fffffffu) : ~(int)u;
    return __int_as_float(i);
}
__device__ __forceinline__ void mma_bf16(float* c, const unsigned* a, const unsigned* b) {
    asm volatile(
        "mma.sync.aligned.m16n8k16.row.col.f32.bf16.bf16.f32 "
        "{%0,%1,%2,%3},{%4,%5,%6,%7},{%8,%9},{%0,%1,%2,%3};"
        : "+f"(c[0]), "+f"(c[1]), "+f"(c[2]), "+f"(c[3])
        : "r"(a[0]), "r"(a[1]), "r"(a[2]), "r"(a[3]), "r"(b[0]), "r"(b[1]));
}
__device__ __forceinline__ void mma_f16(float* c, const unsigned* a, const unsigned* b) {
    asm volatile(
        "mma.sync.aligned.m16n8k16.row.col.f32.f16.f16.f32 "
        "{%0,%1,%2,%3},{%4,%5,%6,%7},{%8,%9},{%0,%1,%2,%3};"
        : "+f"(c[0]), "+f"(c[1]), "+f"(c[2]), "+f"(c[3])
        : "r"(a[0]), "r"(a[1]), "r"(a[2]), "r"(a[3]), "r"(b[0]), "r"(b[1]));
}
__device__ __forceinline__ void ldsm_x4(unsigned* r, unsigned a) {
    asm volatile("ldmatrix.sync.aligned.m8n8.x4.shared.b16 {%0,%1,%2,%3}, [%4];"
                 : "=r"(r[0]), "=r"(r[1]), "=r"(r[2]), "=r"(r[3]) : "r"(a));
}
__device__ __forceinline__ void ldsm_x2(unsigned* r, unsigned a) {
    asm volatile("ldmatrix.sync.aligned.m8n8.x2.shared.b16 {%0,%1}, [%2];"
                 : "=r"(r[0]), "=r"(r[1]) : "r"(a));
}
__device__ __forceinline__ void cp16(unsigned d, const void* s, int sz) {
    asm volatile("cp.async.cg.shared.global [%0], [%1], 16, %2;" :: "r"(d), "l"(s), "r"(sz));
}
__device__ __forceinline__ void cp_commit() { asm volatile("cp.async.commit_group;"); }
template <int NW> __device__ __forceinline__ void cp_wait() {
    asm volatile("cp.async.wait_group %0;" :: "n"(NW));
}

// ---------------- weight packing ----------------
__global__ void pack_w1(const float* __restrict__ Wh) {
    int idx = blockIdx.x * blockDim.x + threadIdx.x;
    if (idx >= 256 * 256) return;
    int c = idx >> 8, k = idx & 255;
    int head = c >> 6, j = c & 63;
    float v = Wh[head * (256 * 64) + k * 64 + j];
    __nv_bfloat16 hi = __float2bfloat16_rn(v);
    g_W1t_hi[c * 256 + k] = hi;
    g_W1t_lo[c * 256 + k] = __float2bfloat16_rn(v - __bfloat162float(hi));
}
__global__ void pack_w2(const float* __restrict__ Wo) {
    int idx = blockIdx.x * blockDim.x + threadIdx.x;
    if (idx >= 64 * 256) return;
    int c = idx >> 8, k = idx & 255;
    float v = (c < NCLASS) ? Wo[k * NCLASS + c] : 0.f;
    g_W2f[c * 256 + k] = __float2half_rn(v);
}

// ---------------- fp32 -> hi/lo bf16 convert (for h) ----------------
__global__ void convert_hilo(const float* __restrict__ A, __nv_bfloat16* __restrict__ H,
                             __nv_bfloat16* __restrict__ L, int n4) {
    int i = blockIdx.x * blockDim.x + threadIdx.x;
    if (i >= n4) return;
    float4 v = ((const float4*)A)[i];
    float vv[4] = {v.x, v.y, v.z, v.w};
    __nv_bfloat16 h[4], l[4];
#pragma unroll
    for (int j = 0; j < 4; j++) {
        h[j] = __float2bfloat16_rn(vv[j]);
        l[j] = __float2bfloat16_rn(vv[j] - __bfloat162float(h[j]));
    }
    __nv_bfloat162 h01, h23, l01, l23;
    h01.x = h[0]; h01.y = h[1]; h23.x = h[2]; h23.y = h[3];
    l01.x = l[0]; l01.y = l[1]; l23.x = l[2]; l23.y = l[3];
    uint2 hp, lp;
    hp.x = *(unsigned*)&h01; hp.y = *(unsigned*)&h23;
    lp.x = *(unsigned*)&l01; lp.y = *(unsigned*)&l23;
    ((uint2*)H)[i] = hp;
    ((uint2*)L)[i] = lp;
}

// ---------------- GEMM1: Wh1 = h @ Wcat (split-bf16 3-term) + fused scores1 ----------------
// BM=128, BN=128, 256 threads, warp grid 2x4 (WM=64, WN=32).
__global__ __launch_bounds__(256, 2) void gemm1_kernel(
    const __nv_bfloat16* __restrict__ Ah, const __nv_bfloat16* __restrict__ Al,
    const __nv_bfloat16* __restrict__ Bth, const __nv_bfloat16* __restrict__ Btl,
    __half* __restrict__ Whf, const float* __restrict__ a_heads, int M) {
    constexpr int WM = 64, WN = 32, MI = 4, NI = 4, WNW = 4;
    constexpr int LDSB = 40;
    constexpr int SZA = 128 * LDSB * 2;
    constexpr int SZB = 128 * LDSB * 2;

    extern __shared__ char smem[];
    const unsigned uAh = (unsigned)__cvta_generic_to_shared(smem);
    const unsigned uAl = uAh + 2 * SZA;
    const unsigned uBh = uAh + 4 * SZA;
    const unsigned uBl = uBh + 2 * SZB;
    __shared__ float sAS[128], sAD[128];
    __shared__ float sP[128][4], sQ[128][4];

    const int tid = threadIdx.x, lane = tid & 31, wid = tid >> 5;
    const int wm = wid / WNW, wn = wid % WNW;
    const int brow = blockIdx.y * 128, bcol = blockIdx.x * 128;

    if (tid < 128) {
        int cg = bcol + tid;
        sAS[tid] = a_heads[(cg >> 6) * 128 + (cg & 63)];
        sAD[tid] = a_heads[(cg >> 6) * 128 + 64 + (cg & 63)];
    }

    float acc[MI][NI][4];
#pragma unroll
    for (int mi = 0; mi < MI; mi++)
#pragma unroll
        for (int ni = 0; ni < NI; ni++)
#pragma unroll
            for (int q = 0; q < 4; q++) acc[mi][ni][q] = 0.f;

    auto stage = [&](int s, int k0) {
#pragma unroll
        for (int i = tid; i < 512; i += 256) {
            int row = i >> 2, c = i & 3;
            int gr = brow + row;
            int ok = (gr < M) ? 16 : 0;
            size_t go = (size_t)min(gr, M - 1) * 256 + k0 + c * 8;
            unsigned dof = (unsigned)(s * SZA + (row * LDSB + c * 8) * 2);
            cp16(uAh + dof, Ah + go, ok);
            cp16(uAl + dof, Al + go, ok);
        }
#pragma unroll
        for (int i = tid; i < 512; i += 256) {
            int row = i >> 2, c = i & 3;
            size_t go = (size_t)(bcol + row) * 256 + k0 + c * 8;
            unsigned dof = (unsigned)(s * SZB + (row * LDSB + c * 8) * 2);
            cp16(uBh + dof, Bth + go, 16);
            cp16(uBl + dof, Btl + go, 16);
        }
    };

    stage(0, 0);
    cp_commit();

#pragma unroll
    for (int it = 0; it < 8; it++) {
        const int s = it & 1;
        if (it < 7) {
            stage(s ^ 1, (it + 1) * 32);
            cp_commit();
            cp_wait<1>();
        } else {
            cp_wait<0>();
        }
        __syncthreads();

#pragma unroll
        for (int kk = 0; kk < 32; kk += 16) {
            unsigned ah[MI][4], al[MI][4], bh[NI][2], bl[NI][2];
            const int ra = lane & 15;
            const int kca = (lane >> 4) << 3;
#pragma unroll
            for (int mi = 0; mi < MI; mi++) {
                unsigned off = (unsigned)(((wm * WM + mi * 16 + ra) * LDSB + kk + kca) * 2) +
                               (unsigned)(s * SZA);
                ldsm_x4(ah[mi], uAh + off);
                ldsm_x4(al[mi], uAl + off);
            }
            const int rb = (lane & 7) + ((lane >> 4) << 3);
            const int kcb = ((lane >> 3) & 1) << 3;
#pragma unroll
            for (int nb = 0; nb < NI / 2; nb++) {
                unsigned off = (unsigned)(((wn * WN + nb * 16 + rb) * LDSB + kk + kcb) * 2) +
                               (unsigned)(s * SZB);
                unsigned t4[4];
                ldsm_x4(t4, uBh + off);
                bh[2 * nb][0] = t4[0]; bh[2 * nb][1] = t4[1];
                bh[2 * nb + 1][0] = t4[2]; bh[2 * nb + 1][1] = t4[3];
                ldsm_x4(t4, uBl + off);
                bl[2 * nb][0] = t4[0]; bl[2 * nb][1] = t4[1];
                bl[2 * nb + 1][0] = t4[2]; bl[2 * nb + 1][1] = t4[3];
            }
#pragma unroll
            for (int mi = 0; mi < MI; mi++)
#pragma unroll
                for (int ni = 0; ni < NI; ni++) {
                    mma_bf16(acc[mi][ni], ah[mi], bh[ni]);
                    mma_bf16(acc[mi][ni], ah[mi], bl[ni]);
                    mma_bf16(acc[mi][ni], al[mi], bh[ni]);
                }
        }
        __syncthreads();
    }

    // epilogue: fused scores + fp16 store
    const int g = lane >> 2, t = lane & 3;
#pragma unroll
    for (int mi = 0; mi < MI; mi++) {
        float p0 = 0.f, q0 = 0.f, p1 = 0.f, q1 = 0.f;
#pragma unroll
        for (int ni = 0; ni < NI; ni++)
#pragma unroll
            for (int qq = 0; qq < 2; qq++) {
                int cl = wn * WN + ni * 8 + 2 * t + qq;
                float as = sAS[cl], ad = sAD[cl];
                p0 += acc[mi][ni][qq] * as;
                q0 += acc[mi][ni][qq] * ad;
                p1 += acc[mi][ni][2 + qq] * as;
                q1 += acc[mi][ni][2 + qq] * ad;
            }
#pragma unroll
        for (int o = 1; o <= 2; o <<= 1) {
            p0 += __shfl_xor_sync(FULLMASK, p0, o);
            q0 += __shfl_xor_sync(FULLMASK, q0, o);
            p1 += __shfl_xor_sync(FULLMASK, p1, o);
            q1 += __shfl_xor_sync(FULLMASK, q1, o);
        }
        int r0 = wm * WM + mi * 16 + g;
        if (t == 0) {
            sP[r0][wn] = p0; sQ[r0][wn] = q0;
            sP[r0 + 8][wn] = p1; sQ[r0 + 8][wn] = q1;
        }
        int gr0 = brow + r0;
#pragma unroll
        for (int ni = 0; ni < NI; ni++) {
            int c = bcol + wn * WN + ni * 8 + 2 * t;
            if (gr0 < M)
                *(__half2*)(Whf + (size_t)gr0 * 256 + c) =
                    __floats2half2_rn(acc[mi][ni][0], acc[mi][ni][1]);
            if (gr0 + 8 < M)
                *(__half2*)(Whf + (size_t)(gr0 + 8) * 256 + c) =
                    __floats2half2_rn(acc[mi][ni][2], acc[mi][ni][3]);
        }
    }
    __syncthreads();
    {
        int row = tid >> 1, hl = tid & 1;
        int gr = brow + row;
        if (gr < M) {
            float p = sP[row][2 * hl] + sP[row][2 * hl + 1];
            float q = sQ[row][2 * hl] + sQ[row][2 * hl + 1];
            int gh = (bcol >> 6) + hl;
            ((float*)g_s1src)[gr * 4 + gh] = p;
            ((float*)g_s1dst)[gr * 4 + gh] = q;
        }
    }
}

// ---------------- GEMM2: Wh2 = x @ W2 (fp16 1-term) + fused scores2 ----------------
// BM=128, BN=64, 256 threads, warp grid 2x4 (WM=64, WN=16, MI=4, NI=2).
__global__ __launch_bounds__(256, 2) void gemm2_kernel(
    const __half* __restrict__ A, const __half* __restrict__ Bt,
    __half* __restrict__ Whf, const float* __restrict__ a_out, int M) {
    constexpr int WM = 64, WN = 16, MI = 4, NI = 2, WNW = 4;
    constexpr int LDSB = 40;
    constexpr int SZA = 128 * LDSB * 2;
    constexpr int SZB = 64 * LDSB * 2;

    extern __shared__ char smem[];
    const unsigned uA = (unsigned)__cvta_generic_to_shared(smem);
    const unsigned uB = uA + 2 * SZA;
    __shared__ float sAS[64], sAD[64];
    __shared__ float sP[128][4], sQ[128][4];

    const int tid = threadIdx.x, lane = tid & 31, wid = tid >> 5;
    const int wm = wid / WNW, wn = wid % WNW;
    const int brow = blockIdx.y * 128;

    if (tid < 64) {
        sAS[tid] = (tid < NCLASS) ? a_out[tid] : 0.f;
        sAD[tid] = (tid < NCLASS) ? a_out[NCLASS + tid] : 0.f;
    }

    float acc[MI][NI][4];
#pragma unroll
    for (int mi = 0; mi < MI; mi++)
#pragma unroll
        for (int ni = 0; ni < NI; ni++)
#pragma unroll
            for (int q = 0; q < 4; q++) acc[mi][ni][q] = 0.f;

    auto stage = [&](int s, int k0) {
#pragma unroll
        for (int i = tid; i < 512; i += 256) {
            int row = i >> 2, c = i & 3;
            int gr = brow + row;
            int ok = (gr < M) ? 16 : 0;
            size_t go = (size_t)min(gr, M - 1) * 256 + k0 + c * 8;
            cp16(uA + (unsigned)(s * SZA + (row * LDSB + c * 8) * 2), A + go, ok);
        }
        if (tid < 256) {
            int row = tid >> 2, c = tid & 3;
            size_t go = (size_t)row * 256 + k0 + c * 8;
            cp16(uB + (unsigned)(s * SZB + (row * LDSB + c * 8) * 2), Bt + go, 16);
        }
    };

    stage(0, 0);
    cp_commit();

#pragma unroll
    for (int it = 0; it < 8; it++) {
        const int s = it & 1;
        if (it < 7) {
            stage(s ^ 1, (it + 1) * 32);
            cp_commit();
            cp_wait<1>();
        } else {
            cp_wait<0>();
        }
        __syncthreads();

#pragma unroll
        for (int kk = 0; kk < 32; kk += 16) {
            unsigned af[MI][4], bf[NI][2];
            const int ra = lane & 15;
            const int kca = (lane >> 4) << 3;
#pragma unroll
            for (int mi = 0; mi < MI; mi++) {
                unsigned off = (unsigned)(((wm * WM + mi * 16 + ra) * LDSB + kk + kca) * 2) +
                               (unsigned)(s * SZA);
                ldsm_x4(af[mi], uA + off);
            }
            // B fragment: 16 rows (wn*16 + rb), both k-halves
            const int rb = (lane & 7) + ((lane >> 4) << 3);
            const int kcb = ((lane >> 3) & 1) << 3;
            {
                unsigned off = (unsigned)(((wn * WN + rb) * LDSB + kk + kcb) * 2) +
                               (unsigned)(s * SZB);
                unsigned t4[4];
                ldsm_x4(t4, uB + off);
                bf[0][0] = t4[0]; bf[0][1] = t4[1];
                bf[1][0] = t4[2]; bf[1][1] = t4[3];
            }
#pragma unroll
            for (int mi = 0; mi < MI; mi++)
#pragma unroll
                for (int ni = 0; ni < NI; ni++)
                    mma_f16(acc[mi][ni], af[mi], bf[ni]);
        }
        __syncthreads();
    }

    const int g = lane >> 2, t = lane & 3;
#pragma unroll
    for (int mi = 0; mi < MI; mi++) {
        float p0 = 0.f, q0 = 0.f, p1 = 0.f, q1 = 0.f;
#pragma unroll
        for (int ni = 0; ni < NI; ni++)
#pragma unroll
            for (int qq = 0; qq < 2; qq++) {
                int cl = wn * WN + ni * 8 + 2 * t + qq;
                float as = sAS[cl], ad = sAD[cl];
                p0 += acc[mi][ni][qq] * as;
                q0 += acc[mi][ni][qq] * ad;
                p1 += acc[mi][ni][2 + qq] * as;
                q1 += acc[mi][ni][2 + qq] * ad;
            }
#pragma unroll
        for (int o = 1; o <= 2; o <<= 1) {
            p0 += __shfl_xor_sync(FULLMASK, p0, o);
            q0 += __shfl_xor_sync(FULLMASK, q0, o);
            p1 += __shfl_xor_sync(FULLMASK, p1, o);
            q1 += __shfl_xor_sync(FULLMASK, q1, o);
        }
        int r0 = wm * WM + mi * 16 + g;
        if (t == 0) {
            sP[r0][wn] = p0; sQ[r0][wn] = q0;
            sP[r0 + 8][wn] = p1; sQ[r0 + 8][wn] = q1;
        }
        int gr0 = brow + r0;
#pragma unroll
        for (int ni = 0; ni < NI; ni++) {
            int c = wn * WN + ni * 8 + 2 * t;
            if (c < NCLASS) {
                if (gr0 < M)
                    *(__half2*)(Whf + (size_t)gr0 * 40 + c) =
                        __floats2half2_rn(acc[mi][ni][0], acc[mi][ni][1]);
                if (gr0 + 8 < M)
                    *(__half2*)(Whf + (size_t)(gr0 + 8) * 40 + c) =
                        __floats2half2_rn(acc[mi][ni][2], acc[mi][ni][3]);
            }
        }
    }
    __syncthreads();
    if (tid < 128) {
        int gr = brow + tid;
        if (gr < M) {
            g_s2src[gr] = sP[tid][0] + sP[tid][1] + sP[tid][2] + sP[tid][3];
            g_s2dst[gr] = sQ[tid][0] + sQ[tid][1] + sQ[tid][2] + sQ[tid][3];
        }
    }
}

// ---------------- global max reductions ----------------
__global__ void maxred1_kernel() {
    int tid = blockIdx.x * 256 + threadIdx.x;
    int stride = gridDim.x * 256;
    float ms[4], md[4];
#pragma unroll
    for (int h = 0; h < 4; h++) { ms[h] = -3e38f; md[h] = -3e38f; }
    for (int i = tid; i < N_NODES; i += stride) {
        float4 v = g_s1src[i];
        ms[0] = fmaxf(ms[0], v.x); ms[1] = fmaxf(ms[1], v.y);
        ms[2] = fmaxf(ms[2], v.z); ms[3] = fmaxf(ms[3], v.w);
        float4 d = g_s1dst[i];
        md[0] = fmaxf(md[0], d.x); md[1] = fmaxf(md[1], d.y);
        md[2] = fmaxf(md[2], d.z); md[3] = fmaxf(md[3], d.w);
    }
#pragma unroll
    for (int h = 0; h < 4; h++) { ms[h] = wredmax(ms[h]); md[h] = wredmax(md[h]); }
    if ((threadIdx.x & 31) == 0) {
#pragma unroll
        for (int h = 0; h < 4; h++) {
            atomicMax(&g_gmax[h], encf(ms[h]));
            atomicMax(&g_gmax[4 + h], encf(md[h]));
        }
    }
}
__global__ void maxred2_kernel() {
    int tid = blockIdx.x * 256 + threadIdx.x;
    int stride = gridDim.x * 256;
    float ms = -3e38f, md = -3e38f;
    for (int i = tid; i < N_NODES; i += stride) {
        ms = fmaxf(ms, g_s2src[i]);
        md = fmaxf(md, g_s2dst[i]);
    }
    ms = wredmax(ms);
    md = wredmax(md);
    if ((threadIdx.x & 31) == 0) {
        atomicMax(&g_gmax[8], encf(ms));
        atomicMax(&g_gmax[9], encf(md));
    }
}

// ---------------- CSR build ----------------
__global__ void zero_csr() {
    int i = blockIdx.x * blockDim.x + threadIdx.x;
    if (i <= N_NODES) g_deg[i] = 0;
    if (i < N_NODES) g_cursor[i] = 0;
    if (i < 10) g_gmax[i] = encf(-3e38f);
}
__global__ void count_kernel(const int* __restrict__ dst) {
    int e = blockIdx.x * blockDim.x + threadIdx.x;
    if (e < N_EDGES) atomicAdd(&g_deg[dst[e]], 1);
}
__global__ void scan1_kernel(int n) {
    __shared__ int s[1024];
    int tid = threadIdx.x;
    int gid = blockIdx.x * 1024 + tid;
    int v = (gid < n) ? g_deg[gid] : 0;
    s[tid] = v;
    __syncthreads();
    int t = v;
    for (int d = 1; d < 1024; d <<= 1) {
        int add = (tid >= d) ? s[tid - d] : 0;
        __syncthreads();
        t += add;
        s[tid] = t;
        __syncthreads();
    }
    if (gid < n) g_off[gid] = t - v;
    if (tid == 1023) g_bsum[blockIdx.x] = t;
}
__global__ void scan2_kernel(int nb) {
    __shared__ int s[128];
    int tid = threadIdx.x;
    int v = (tid < nb) ? g_bsum[tid] : 0;
    s[tid] = v;
    __syncthreads();
    int t = v;
    for (int d = 1; d < 128; d <<= 1) {
        int add = (tid >= d) ? s[tid - d] : 0;
        __syncthreads();
        t += add;
        s[tid] = t;
        __syncthreads();
    }
    if (tid < nb) g_bsum2[tid] = t - v;
}
__global__ void scan3_kernel(int n) {
    int i = blockIdx.x * blockDim.x + threadIdx.x;
    if (i < n) g_off[i] += g_bsum2[i >> 10];
}
__global__ void fill_kernel(const int* __restrict__ dst, const int* __restrict__ src) {
    int e = blockIdx.x * blockDim.x + threadIdx.x;
    if (e >= N_EDGES) return;
    int d = dst[e];
    int pos = g_off[d] + atomicAdd(&g_cursor[d], 1);
    g_eid[pos] = src[e];
}

// ---------------- layer-1 aggregation: fp16 gather, single pass ----------------
__global__ void agg1_kernel() {
    __shared__ float4 sw[8][32];
    __shared__ int ssm[8][32];
    int gw = blockIdx.x * 8 + (threadIdx.x >> 5);
    int lane = threadIdx.x & 31;
    int wl = threadIdx.x >> 5;
    if (gw >= N_NODES) return;
    const int v = gw;
    const int off0 = g_off[v];
    const int deg = g_off[v + 1] - off0;
    const float4 sd = g_s1dst[v];

    float4 mx;
    mx.x = lrelu(decf(g_gmax[0]) + decf(g_gmax[4]));
    mx.y = lrelu(decf(g_gmax[1]) + decf(g_gmax[5]));
    mx.z = lrelu(decf(g_gmax[2]) + decf(g_gmax[6]));
    mx.w = lrelu(decf(g_gmax[3]) + decf(g_gmax[7]));

    float4 dn = make_float4(0.f, 0.f, 0.f, 0.f);
    float a[8];
#pragma unroll
    for (int j = 0; j < 8; j++) a[j] = 0.f;
    const int hsel = lane >> 3;
    const uint4* whb = (const uint4*)g_Wh1f;  // row stride = 32 uint4

    for (int base = 0; base < deg; base += 32) {
        int j = base + lane;
        float4 w4 = make_float4(0.f, 0.f, 0.f, 0.f);
        int s = 0;
        if (j < deg) {
            s = g_eid[off0 + j];
            float4 ss = g_s1src[s];
            w4.x = __expf(lrelu(ss.x + sd.x) - mx.x);
            w4.y = __expf(lrelu(ss.y + sd.y) - mx.y);
            w4.z = __expf(lrelu(ss.z + sd.z) - mx.z);
            w4.w = __expf(lrelu(ss.w + sd.w) - mx.w);
            dn.x += w4.x; dn.y += w4.y; dn.z += w4.z; dn.w += w4.w;
        }
        sw[wl][lane] = w4;
        ssm[wl][lane] = s;
        __syncwarp();
        int cnt = min(32, deg - base);
        for (int k = 0; k < cnt; k++) {
            int sk = ssm[wl][k];
            float wk = ((const float*)(sw[wl] + k))[hsel];
            uint4 rv = whb[(size_t)sk * 32 + lane];
            const __half2* hp = (const __half2*)&rv;
            float2 f0 = __half22float2(hp[0]);
            float2 f1 = __half22float2(hp[1]);
            float2 f2 = __half22float2(hp[2]);
            float2 f3 = __half22float2(hp[3]);
            a[0] += wk * f0.x; a[1] += wk * f0.y;
            a[2] += wk * f1.x; a[3] += wk * f1.y;
            a[4] += wk * f2.x; a[5] += wk * f2.y;
            a[6] += wk * f3.x; a[7] += wk * f3.y;
        }
        __syncwarp();
    }

    dn.x = wredsum(dn.x); dn.y = wredsum(dn.y);
    dn.z = wredsum(dn.z); dn.w = wredsum(dn.w);
    float invs[4];
    invs[0] = (deg > 0) ? 1.f / dn.x : 0.f;
    invs[1] = (deg > 0) ? 1.f / dn.y : 0.f;
    invs[2] = (deg > 0) ? 1.f / dn.z : 0.f;
    invs[3] = (deg > 0) ? 1.f / dn.w : 0.f;
    float invh = invs[hsel];

    __half hh[8];
#pragma unroll
    for (int j = 0; j < 8; j++) {
        float vv = a[j] * invh;
        vv = vv > 0.f ? vv : expm1f(vv);
        hh[j] = __float2half_rn(vv);
    }
    *(uint4*)(g_Xf + (size_t)v * 256 + lane * 8) = *(uint4*)hh;
}

// ---------------- layer-2 aggregation + log_softmax: fp16 gather ----------------
__global__ void agg2_kernel(float* __restrict__ out) {
    int gw = blockIdx.x * 8 + (threadIdx.x >> 5);
    int lane = threadIdx.x & 31;
    if (gw >= N_NODES) return;
    const int v = gw;
    const int off0 = g_off[v];
    const int deg = g_off[v + 1] - off0;
    const float sd = g_s2dst[v];
    const float mx = lrelu(decf(g_gmax[8]) + decf(g_gmax[9]));
    const bool valid = lane < 20;  // cols 2*lane, 2*lane+1 < 40

    float dn = 0.f;
    float ax = 0.f, ay = 0.f;
    for (int base = 0; base < deg; base += 32) {
        int j = base + lane;
        float w = 0.f;
        int s = 0;
        if (j < deg) {
            s = g_eid[off0 + j];
            w = __expf(lrelu(g_s2src[s] + sd) - mx);
            dn += w;
        }
        int cnt = min(32, deg - base);
        for (int k = 0; k < cnt; k++) {
            int sk = __shfl_sync(FULLMASK, s, k);
            float wk = __shfl_sync(FULLMASK, w, k);
            if (valid) {
                __half2 hv = *((const __half2*)(g_Wh2f + (size_t)sk * 40) + lane);
                float2 f = __half22float2(hv);
                ax += wk * f.x;
                ay += wk * f.y;
            }
        }
    }
    dn = wredsum(dn);
    float inv = (deg > 0) ? 1.f / dn : 0.f;
    ax *= inv;
    ay *= inv;

    float m = wredmax(valid ? fmaxf(ax, ay) : -3e38f);
    float se = wredsum(valid ? (__expf(ax - m) + __expf(ay - m)) : 0.f);
    float lse = m + logf(se);
    if (valid) {
        out[(size_t)v * NCLASS + 2 * lane] = ax - lse;
        out[(size_t)v * NCLASS + 2 * lane + 1] = ay - lse;
    }
}

// ---------------- launcher ----------------
extern "C" void kernel_launch(void* const* d_in, const int* in_sizes, int n_in,
                              void* d_out, int out_size) {
    const float* h = (const float*)d_in[0];
    const int* ei = (const int*)d_in[1];
    const float* Wheads = (const float*)d_in[2];
    const float* aheads = (const float*)d_in[3];
    const float* Wout = (const float*)d_in[4];
    const float* aout = (const float*)d_in[5];
    const int* src = ei;
    const int* dst = ei + N_EDGES;
    float* out = (float*)d_out;

    __nv_bfloat16 *pW1h, *pW1l, *pAh, *pAl;
    __half *pW2f, *pWh1f, *pXf, *pWh2f;
    cudaGetSymbolAddress((void**)&pW1h, g_W1t_hi);
    cudaGetSymbolAddress((void**)&pW1l, g_W1t_lo);
    cudaGetSymbolAddress((void**)&pW2f, g_W2f);
    cudaGetSymbolAddress((void**)&pAh, g_Ah);
    cudaGetSymbolAddress((void**)&pAl, g_Al);
    cudaGetSymbolAddress((void**)&pWh1f, g_Wh1f);
    cudaGetSymbolAddress((void**)&pXf, g_Xf);
    cudaGetSymbolAddress((void**)&pWh2f, g_Wh2f);

    const int rowBlocks = (N_NODES + 127) / 128;  // 782
    constexpr int SMEM1 = 8 * 128 * 40 * 2;       // 81920
    constexpr int SMEM2 = 2 * 128 * 40 * 2 + 2 * 64 * 40 * 2;  // 30720

    cudaFuncSetAttribute((const void*)gemm1_kernel,
                         cudaFuncAttributeMaxDynamicSharedMemorySize, SMEM1);
    cudaFuncSetAttribute((const void*)gemm2_kernel,
                         cudaFuncAttributeMaxDynamicSharedMemorySize, SMEM2);

    pack_w1<<<256, 256>>>(Wheads);
    pack_w2<<<64, 256>>>(Wout);
    zero_csr<<<(N_NODES + 256) / 256, 256>>>();
    convert_hilo<<<(N_NODES * 64 + 255) / 256, 256>>>(h, pAh, pAl, N_NODES * 64);

    count_kernel<<<N_EDGES / 256, 256>>>(dst);
    {
        int n = N_NODES + 1;
        int nb = (n + 1023) / 1024;  // 98
        scan1_kernel<<<nb, 1024>>>(n);
        scan2_kernel<<<1, 128>>>(nb);
        scan3_kernel<<<(n + 255) / 256, 256>>>(n);
    }
    fill_kernel<<<N_EDGES / 256, 256>>>(dst, src);

    gemm1_kernel<<<dim3(2, rowBlocks), 256, SMEM1>>>(
        pAh, pAl, pW1h, pW1l, pWh1f, aheads, N_NODES);
    maxred1_kernel<<<96, 256>>>();

    agg1_kernel<<<(N_NODES + 7) / 8, 256>>>();

    gemm2_kernel<<<dim3(1, rowBlocks), 256, SMEM2>>>(pXf, pW2f, pWh2f, aout, N_NODES);
    maxred2_kernel<<<96, 256>>>();

    agg2_kernel<<<(N_NODES + 7) / 8, 256>>>(out);
}

// round 6
// speedup vs baseline: 2.4615x; 1.0100x over previous
#include <cuda_runtime.h>
#include <cuda_bf16.h>
#include <cuda_fp16.h>
#include <math.h>
#include <stdint.h>

#define N_NODES 100000
#define N_EDGES 1600000
#define NCLASS  40
#define LALPHA  0.2f
#define FULLMASK 0xffffffffu

// ---------------- scratch (static device globals) ----------------
__device__ __align__(16) __nv_bfloat16 g_W1t_hi[256 * 256];
__device__ __align__(16) __nv_bfloat16 g_W1t_lo[256 * 256];
__device__ __align__(16) __half g_W2f[64 * 256];               // W_out^T padded, fp16
__device__ __align__(16) __nv_bfloat16 g_Ah[(size_t)N_NODES * 256];
__device__ __align__(16) __nv_bfloat16 g_Al[(size_t)N_NODES * 256];
__device__ __align__(16) __half g_Wh1f[(size_t)N_NODES * 256]; // layer1 features fp16
__device__ __align__(16) __half g_Xf[(size_t)N_NODES * 256];   // layer1 output fp16
__device__ __align__(16) __half g_Wh2f[(size_t)N_NODES * 40];  // layer2 logits fp16, stride 40
__device__ float4 g_s1src[N_NODES];
__device__ float4 g_s1dst[N_NODES];
__device__ float g_s2src[N_NODES];
__device__ float g_s2dst[N_NODES];
__device__ int g_deg[N_NODES + 1];
__device__ int g_off[N_NODES + 1];
__device__ int g_rank[N_EDGES];
__device__ int g_eid[N_EDGES];
__device__ int g_bsum[128];
__device__ int g_bsum2[128];
__device__ unsigned g_gmax[10];

// ---------------- helpers ----------------
__device__ __forceinline__ float wredmax(float v) {
#pragma unroll
    for (int o = 16; o; o >>= 1) v = fmaxf(v, __shfl_xor_sync(FULLMASK, v, o));
    return v;
}
__device__ __forceinline__ float wredsum(float v) {
#pragma unroll
    for (int o = 16; o; o >>= 1) v += __shfl_xor_sync(FULLMASK, v, o);
    return v;
}
__device__ __forceinline__ float lrelu(float x) { return x > 0.f ? x : LALPHA * x; }
__device__ __forceinline__ unsigned encf(float f) {
    int i = __float_as_int(f);
    return (i < 0) ? ~(unsigned)i : ((unsigned)i | 0x80000000u);
}
__device__ __forceinline__ float decf(unsigned u) {
    int i = (u & 0x80000000u) ? (int)(u & 0x7fffffffu) : ~(int)u;
    return __int_as_float(i);
}
__device__ __forceinline__ void mma_bf16(float* c, const unsigned* a, const unsigned* b) {
    asm volatile(
        "mma.sync.aligned.m16n8k16.row.col.f32.bf16.bf16.f32 "
        "{%0,%1,%2,%3},{%4,%5,%6,%7},{%8,%9},{%0,%1,%2,%3};"
        : "+f"(c[0]), "+f"(c[1]), "+f"(c[2]), "+f"(c[3])
        : "r"(a[0]), "r"(a[1]), "r"(a[2]), "r"(a[3]), "r"(b[0]), "r"(b[1]));
}
__device__ __forceinline__ void mma_f16(float* c, const unsigned* a, const unsigned* b) {
    asm volatile(
        "mma.sync.aligned.m16n8k16.row.col.f32.f16.f16.f32 "
        "{%0,%1,%2,%3},{%4,%5,%6,%7},{%8,%9},{%0,%1,%2,%3};"
        : "+f"(c[0]), "+f"(c[1]), "+f"(c[2]), "+f"(c[3])
        : "r"(a[0]), "r"(a[1]), "r"(a[2]), "r"(a[3]), "r"(b[0]), "r"(b[1]));
}
__device__ __forceinline__ void ldsm_x4(unsigned* r, unsigned a) {
    asm volatile("ldmatrix.sync.aligned.m8n8.x4.shared.b16 {%0,%1,%2,%3}, [%4];"
                 : "=r"(r[0]), "=r"(r[1]), "=r"(r[2]), "=r"(r[3]) : "r"(a));
}
__device__ __forceinline__ void cp16(unsigned d, const void* s, int sz) {
    asm volatile("cp.async.cg.shared.global [%0], [%1], 16, %2;" :: "r"(d), "l"(s), "r"(sz));
}
__device__ __forceinline__ void cp_commit() { asm volatile("cp.async.commit_group;"); }
template <int NW> __device__ __forceinline__ void cp_wait() {
    asm volatile("cp.async.wait_group %0;" :: "n"(NW));
}

// ---------------- merged setup: pack W1 hi/lo, pack W2, zero deg/gmax ----------------
__global__ void setup_kernel(const float* __restrict__ Wh, const float* __restrict__ Wo) {
    int idx = blockIdx.x * blockDim.x + threadIdx.x;
    if (idx <= N_NODES) g_deg[idx] = 0;
    if (idx < 10) g_gmax[idx] = encf(-3e38f);
    if (idx < 256 * 256) {
        int c = idx >> 8, k = idx & 255;
        int head = c >> 6, j = c & 63;
        float v = Wh[head * (256 * 64) + k * 64 + j];
        __nv_bfloat16 hi = __float2bfloat16_rn(v);
        g_W1t_hi[c * 256 + k] = hi;
        g_W1t_lo[c * 256 + k] = __float2bfloat16_rn(v - __bfloat162float(hi));
    }
    if (idx < 64 * 256) {
        int c = idx >> 8, k = idx & 255;
        float v = (c < NCLASS) ? Wo[k * NCLASS + c] : 0.f;
        g_W2f[c * 256 + k] = __float2half_rn(v);
    }
}

// ---------------- fp32 -> hi/lo bf16 convert (for h) ----------------
__global__ void convert_hilo(const float* __restrict__ A, __nv_bfloat16* __restrict__ H,
                             __nv_bfloat16* __restrict__ L, int n4) {
    int i = blockIdx.x * blockDim.x + threadIdx.x;
    if (i >= n4) return;
    float4 v = ((const float4*)A)[i];
    float vv[4] = {v.x, v.y, v.z, v.w};
    __nv_bfloat16 h[4], l[4];
#pragma unroll
    for (int j = 0; j < 4; j++) {
        h[j] = __float2bfloat16_rn(vv[j]);
        l[j] = __float2bfloat16_rn(vv[j] - __bfloat162float(h[j]));
    }
    __nv_bfloat162 h01, h23, l01, l23;
    h01.x = h[0]; h01.y = h[1]; h23.x = h[2]; h23.y = h[3];
    l01.x = l[0]; l01.y = l[1]; l23.x = l[2]; l23.y = l[3];
    uint2 hp, lp;
    hp.x = *(unsigned*)&h01; hp.y = *(unsigned*)&h23;
    lp.x = *(unsigned*)&l01; lp.y = *(unsigned*)&l23;
    ((uint2*)H)[i] = hp;
    ((uint2*)L)[i] = lp;
}

// ---------------- GEMM1: Wh1 = h @ Wcat (split-bf16 3-term) + fused scores1 + max ----------------
// BM=64, BN=256, 256 threads, warp grid 1x8 (WM=64, WN=32). A read once from DRAM.
__global__ __launch_bounds__(256, 2) void gemm1_kernel(
    const __nv_bfloat16* __restrict__ Ah, const __nv_bfloat16* __restrict__ Al,
    const __nv_bfloat16* __restrict__ Bth, const __nv_bfloat16* __restrict__ Btl,
    __half* __restrict__ Whf, const float* __restrict__ a_heads, int M) {
    constexpr int MI = 4, NI = 4;
    constexpr int LDSB = 40;
    constexpr int SZA = 64 * LDSB * 2;     // 5120 per stage per array
    constexpr int SZB = 256 * LDSB * 2;    // 20480 per stage per array

    extern __shared__ char smem[];
    const unsigned uAh = (unsigned)__cvta_generic_to_shared(smem);
    const unsigned uAl = uAh + 2 * SZA;
    const unsigned uBh = uAh + 4 * SZA;
    const unsigned uBl = uBh + 2 * SZB;
    __shared__ float sAS[256], sAD[256];
    __shared__ float sP[64][8], sQ[64][8];
    __shared__ float sMp[8][4], sMq[8][4];

    const int tid = threadIdx.x, lane = tid & 31, wid = tid >> 5;
    const int wn = wid;  // warp grid 1 x 8
    const int brow = blockIdx.y * 64;

    {
        int cg = tid;  // global col 0..255
        sAS[tid] = a_heads[(cg >> 6) * 128 + (cg & 63)];
        sAD[tid] = a_heads[(cg >> 6) * 128 + 64 + (cg & 63)];
    }

    float acc[MI][NI][4];
#pragma unroll
    for (int mi = 0; mi < MI; mi++)
#pragma unroll
        for (int ni = 0; ni < NI; ni++)
#pragma unroll
            for (int q = 0; q < 4; q++) acc[mi][ni][q] = 0.f;

    auto stage = [&](int s, int k0) {
        {
            int row = tid >> 2, c = tid & 3;  // 64 rows x 4 chunks = 256
            int gr = brow + row;
            int ok = (gr < M) ? 16 : 0;
            size_t go = (size_t)min(gr, M - 1) * 256 + k0 + c * 8;
            unsigned dof = (unsigned)(s * SZA + (row * LDSB + c * 8) * 2);
            cp16(uAh + dof, Ah + go, ok);
            cp16(uAl + dof, Al + go, ok);
        }
#pragma unroll
        for (int it = 0; it < 4; it++) {
            int i = tid + it * 256;
            int row = i >> 2, c = i & 3;  // 256 rows x 4 chunks
            size_t go = (size_t)row * 256 + k0 + c * 8;
            unsigned dof = (unsigned)(s * SZB + (row * LDSB + c * 8) * 2);
            cp16(uBh + dof, Bth + go, 16);
            cp16(uBl + dof, Btl + go, 16);
        }
    };

    stage(0, 0);
    cp_commit();

#pragma unroll
    for (int it = 0; it < 8; it++) {
        const int s = it & 1;
        if (it < 7) {
            stage(s ^ 1, (it + 1) * 32);
            cp_commit();
            cp_wait<1>();
        } else {
            cp_wait<0>();
        }
        __syncthreads();

#pragma unroll
        for (int kk = 0; kk < 32; kk += 16) {
            unsigned ah[MI][4], al[MI][4], bh[NI][2], bl[NI][2];
            const int ra = lane & 15;
            const int kca = (lane >> 4) << 3;
#pragma unroll
            for (int mi = 0; mi < MI; mi++) {
                unsigned off = (unsigned)(((mi * 16 + ra) * LDSB + kk + kca) * 2) +
                               (unsigned)(s * SZA);
                ldsm_x4(ah[mi], uAh + off);
                ldsm_x4(al[mi], uAl + off);
            }
            const int rb = (lane & 7) + ((lane >> 4) << 3);
            const int kcb = ((lane >> 3) & 1) << 3;
#pragma unroll
            for (int nb = 0; nb < NI / 2; nb++) {
                unsigned off = (unsigned)(((wn * 32 + nb * 16 + rb) * LDSB + kk + kcb) * 2) +
                               (unsigned)(s * SZB);
                unsigned t4[4];
                ldsm_x4(t4, uBh + off);
                bh[2 * nb][0] = t4[0]; bh[2 * nb][1] = t4[1];
                bh[2 * nb + 1][0] = t4[2]; bh[2 * nb + 1][1] = t4[3];
                ldsm_x4(t4, uBl + off);
                bl[2 * nb][0] = t4[0]; bl[2 * nb][1] = t4[1];
                bl[2 * nb + 1][0] = t4[2]; bl[2 * nb + 1][1] = t4[3];
            }
#pragma unroll
            for (int mi = 0; mi < MI; mi++)
#pragma unroll
                for (int ni = 0; ni < NI; ni++) {
                    mma_bf16(acc[mi][ni], ah[mi], bh[ni]);
                    mma_bf16(acc[mi][ni], ah[mi], bl[ni]);
                    mma_bf16(acc[mi][ni], al[mi], bh[ni]);
                }
        }
        __syncthreads();
    }

    // epilogue: fused scores + fp16 store
    const int g = lane >> 2, t = lane & 3;
#pragma unroll
    for (int mi = 0; mi < MI; mi++) {
        float p0 = 0.f, q0 = 0.f, p1 = 0.f, q1 = 0.f;
#pragma unroll
        for (int ni = 0; ni < NI; ni++)
#pragma unroll
            for (int qq = 0; qq < 2; qq++) {
                int cl = wn * 32 + ni * 8 + 2 * t + qq;
                float as = sAS[cl], ad = sAD[cl];
                p0 += acc[mi][ni][qq] * as;
                q0 += acc[mi][ni][qq] * ad;
                p1 += acc[mi][ni][2 + qq] * as;
                q1 += acc[mi][ni][2 + qq] * ad;
            }
#pragma unroll
        for (int o = 1; o <= 2; o <<= 1) {
            p0 += __shfl_xor_sync(FULLMASK, p0, o);
            q0 += __shfl_xor_sync(FULLMASK, q0, o);
            p1 += __shfl_xor_sync(FULLMASK, p1, o);
            q1 += __shfl_xor_sync(FULLMASK, q1, o);
        }
        int r0 = mi * 16 + g;
        if (t == 0) {
            sP[r0][wn] = p0; sQ[r0][wn] = q0;
            sP[r0 + 8][wn] = p1; sQ[r0 + 8][wn] = q1;
        }
        int gr0 = brow + r0;
#pragma unroll
        for (int ni = 0; ni < NI; ni++) {
            int c = wn * 32 + ni * 8 + 2 * t;
            if (gr0 < M)
                *(__half2*)(Whf + (size_t)gr0 * 256 + c) =
                    __floats2half2_rn(acc[mi][ni][0], acc[mi][ni][1]);
            if (gr0 + 8 < M)
                *(__half2*)(Whf + (size_t)(gr0 + 8) * 256 + c) =
                    __floats2half2_rn(acc[mi][ni][2], acc[mi][ni][3]);
        }
    }
    __syncthreads();
    // combine per-(row,head) scores, write, and block-reduce max for g_gmax
    {
        int row = tid >> 2, hd = tid & 3;  // 64 rows x 4 heads
        int gr = brow + row;
        float p = -3e38f, q = -3e38f;
        float pv = sP[row][2 * hd] + sP[row][2 * hd + 1];
        float qv = sQ[row][2 * hd] + sQ[row][2 * hd + 1];
        if (gr < M) {
            ((float*)g_s1src)[gr * 4 + hd] = pv;
            ((float*)g_s1dst)[gr * 4 + hd] = qv;
            p = pv; q = qv;
        }
#pragma unroll
        for (int o = 4; o <= 16; o <<= 1) {
            p = fmaxf(p, __shfl_xor_sync(FULLMASK, p, o));
            q = fmaxf(q, __shfl_xor_sync(FULLMASK, q, o));
        }
        if (lane < 4) {
            sMp[wid][lane] = p;
            sMq[wid][lane] = q;
        }
    }
    __syncthreads();
    if (tid < 32) {
        int w = tid >> 2, h = tid & 3;
        float p = sMp[w][h], q = sMq[w][h];
#pragma unroll
        for (int o = 4; o <= 16; o <<= 1) {
            p = fmaxf(p, __shfl_xor_sync(FULLMASK, p, o));
            q = fmaxf(q, __shfl_xor_sync(FULLMASK, q, o));
        }
        if (tid < 4) {
            atomicMax(&g_gmax[h], encf(p));
            atomicMax(&g_gmax[4 + h], encf(q));
        }
    }
}

// ---------------- GEMM2: Wh2 = x @ W2 (fp16 1-term) + fused scores2 + max ----------------
// BM=128, BN=64, 256 threads, warp grid 2x4 (WM=64, WN=16, MI=4, NI=2).
__global__ __launch_bounds__(256, 2) void gemm2_kernel(
    const __half* __restrict__ A, const __half* __restrict__ Bt,
    __half* __restrict__ Whf, const float* __restrict__ a_out, int M) {
    constexpr int WM = 64, WN = 16, MI = 4, NI = 2, WNW = 4;
    constexpr int LDSB = 40;
    constexpr int SZA = 128 * LDSB * 2;
    constexpr int SZB = 64 * LDSB * 2;

    extern __shared__ char smem[];
    const unsigned uA = (unsigned)__cvta_generic_to_shared(smem);
    const unsigned uB = uA + 2 * SZA;
    __shared__ float sAS[64], sAD[64];
    __shared__ float sP[128][4], sQ[128][4];
    __shared__ float sMp[8], sMq[8];

    const int tid = threadIdx.x, lane = tid & 31, wid = tid >> 5;
    const int wm = wid / WNW, wn = wid % WNW;
    const int brow = blockIdx.y * 128;

    if (tid < 64) {
        sAS[tid] = (tid < NCLASS) ? a_out[tid] : 0.f;
        sAD[tid] = (tid < NCLASS) ? a_out[NCLASS + tid] : 0.f;
    }

    float acc[MI][NI][4];
#pragma unroll
    for (int mi = 0; mi < MI; mi++)
#pragma unroll
        for (int ni = 0; ni < NI; ni++)
#pragma unroll
            for (int q = 0; q < 4; q++) acc[mi][ni][q] = 0.f;

    auto stage = [&](int s, int k0) {
#pragma unroll
        for (int i = tid; i < 512; i += 256) {
            int row = i >> 2, c = i & 3;
            int gr = brow + row;
            int ok = (gr < M) ? 16 : 0;
            size_t go = (size_t)min(gr, M - 1) * 256 + k0 + c * 8;
            cp16(uA + (unsigned)(s * SZA + (row * LDSB + c * 8) * 2), A + go, ok);
        }
        if (tid < 256) {
            int row = tid >> 2, c = tid & 3;
            size_t go = (size_t)row * 256 + k0 + c * 8;
            cp16(uB + (unsigned)(s * SZB + (row * LDSB + c * 8) * 2), Bt + go, 16);
        }
    };

    stage(0, 0);
    cp_commit();

#pragma unroll
    for (int it = 0; it < 8; it++) {
        const int s = it & 1;
        if (it < 7) {
            stage(s ^ 1, (it + 1) * 32);
            cp_commit();
            cp_wait<1>();
        } else {
            cp_wait<0>();
        }
        __syncthreads();

#pragma unroll
        for (int kk = 0; kk < 32; kk += 16) {
            unsigned af[MI][4], bf[NI][2];
            const int ra = lane & 15;
            const int kca = (lane >> 4) << 3;
#pragma unroll
            for (int mi = 0; mi < MI; mi++) {
                unsigned off = (unsigned)(((wm * WM + mi * 16 + ra) * LDSB + kk + kca) * 2) +
                               (unsigned)(s * SZA);
                ldsm_x4(af[mi], uA + off);
            }
            const int rb = (lane & 7) + ((lane >> 4) << 3);
            const int kcb = ((lane >> 3) & 1) << 3;
            {
                unsigned off = (unsigned)(((wn * WN + rb) * LDSB + kk + kcb) * 2) +
                               (unsigned)(s * SZB);
                unsigned t4[4];
                ldsm_x4(t4, uB + off);
                bf[0][0] = t4[0]; bf[0][1] = t4[1];
                bf[1][0] = t4[2]; bf[1][1] = t4[3];
            }
#pragma unroll
            for (int mi = 0; mi < MI; mi++)
#pragma unroll
                for (int ni = 0; ni < NI; ni++)
                    mma_f16(acc[mi][ni], af[mi], bf[ni]);
        }
        __syncthreads();
    }

    const int g = lane >> 2, t = lane & 3;
#pragma unroll
    for (int mi = 0; mi < MI; mi++) {
        float p0 = 0.f, q0 = 0.f, p1 = 0.f, q1 = 0.f;
#pragma unroll
        for (int ni = 0; ni < NI; ni++)
#pragma unroll
            for (int qq = 0; qq < 2; qq++) {
                int cl = wn * WN + ni * 8 + 2 * t + qq;
                float as = sAS[cl], ad = sAD[cl];
                p0 += acc[mi][ni][qq] * as;
                q0 += acc[mi][ni][qq] * ad;
                p1 += acc[mi][ni][2 + qq] * as;
                q1 += acc[mi][ni][2 + qq] * ad;
            }
#pragma unroll
        for (int o = 1; o <= 2; o <<= 1) {
            p0 += __shfl_xor_sync(FULLMASK, p0, o);
            q0 += __shfl_xor_sync(FULLMASK, q0, o);
            p1 += __shfl_xor_sync(FULLMASK, p1, o);
            q1 += __shfl_xor_sync(FULLMASK, q1, o);
        }
        int r0 = wm * WM + mi * 16 + g;
        if (t == 0) {
            sP[r0][wn] = p0; sQ[r0][wn] = q0;
            sP[r0 + 8][wn] = p1; sQ[r0 + 8][wn] = q1;
        }
        int gr0 = brow + r0;
#pragma unroll
        for (int ni = 0; ni < NI; ni++) {
            int c = wn * WN + ni * 8 + 2 * t;
            if (c < NCLASS) {
                if (gr0 < M)
                    *(__half2*)(Whf + (size_t)gr0 * 40 + c) =
                        __floats2half2_rn(acc[mi][ni][0], acc[mi][ni][1]);
                if (gr0 + 8 < M)
                    *(__half2*)(Whf + (size_t)(gr0 + 8) * 40 + c) =
                        __floats2half2_rn(acc[mi][ni][2], acc[mi][ni][3]);
            }
        }
    }
    __syncthreads();
    {
        float p = -3e38f, q = -3e38f;
        if (tid < 128) {
            int gr = brow + tid;
            float pv = sP[tid][0] + sP[tid][1] + sP[tid][2] + sP[tid][3];
            float qv = sQ[tid][0] + sQ[tid][1] + sQ[tid][2] + sQ[tid][3];
            if (gr < M) {
                g_s2src[gr] = pv;
                g_s2dst[gr] = qv;
                p = pv; q = qv;
            }
        }
        p = wredmax(p);
        q = wredmax(q);
        if (lane == 0) {
            sMp[wid] = p;
            sMq[wid] = q;
        }
    }
    __syncthreads();
    if (tid == 0) {
        float p = sMp[0], q = sMq[0];
#pragma unroll
        for (int w = 1; w < 8; w++) {
            p = fmaxf(p, sMp[w]);
            q = fmaxf(q, sMq[w]);
        }
        atomicMax(&g_gmax[8], encf(p));
        atomicMax(&g_gmax[9], encf(q));
    }
}

// ---------------- CSR build (single-atomic: count stores rank) ----------------
__global__ void count_kernel(const int* __restrict__ dst) {
    int e = blockIdx.x * blockDim.x + threadIdx.x;
    if (e < N_EDGES) g_rank[e] = atomicAdd(&g_deg[dst[e]], 1);
}
__global__ void scan1_kernel(int n) {
    __shared__ int s[1024];
    int tid = threadIdx.x;
    int gid = blockIdx.x * 1024 + tid;
    int v = (gid < n) ? g_deg[gid] : 0;
    s[tid] = v;
    __syncthreads();
    int t = v;
    for (int d = 1; d < 1024; d <<= 1) {
        int add = (tid >= d) ? s[tid - d] : 0;
        __syncthreads();
        t += add;
        s[tid] = t;
        __syncthreads();
    }
    if (gid < n) g_off[gid] = t - v;
    if (tid == 1023) g_bsum[blockIdx.x] = t;
}
__global__ void scan2_kernel(int nb) {
    __shared__ int s[128];
    int tid = threadIdx.x;
    int v = (tid < nb) ? g_bsum[tid] : 0;
    s[tid] = v;
    __syncthreads();
    int t = v;
    for (int d = 1; d < 128; d <<= 1) {
        int add = (tid >= d) ? s[tid - d] : 0;
        __syncthreads();
        t += add;
        s[tid] = t;
        __syncthreads();
    }
    if (tid < nb) g_bsum2[tid] = t - v;
}
__global__ void scan3_kernel(int n) {
    int i = blockIdx.x * blockDim.x + threadIdx.x;
    if (i < n) g_off[i] += g_bsum2[i >> 10];
}
__global__ void fill_kernel(const int* __restrict__ dst, const int* __restrict__ src) {
    int e = blockIdx.x * blockDim.x + threadIdx.x;
    if (e >= N_EDGES) return;
    int pos = g_off[dst[e]] + g_rank[e];
    g_eid[pos] = src[e];
}

// ---------------- layer-1 aggregation: fp16 gather, single pass ----------------
__global__ void agg1_kernel() {
    __shared__ float4 sw[8][32];
    __shared__ int ssm[8][32];
    int gw = blockIdx.x * 8 + (threadIdx.x >> 5);
    int lane = threadIdx.x & 31;
    int wl = threadIdx.x >> 5;
    if (gw >= N_NODES) return;
    const int v = gw;
    const int off0 = g_off[v];
    const int deg = g_off[v + 1] - off0;
    const float4 sd = g_s1dst[v];

    float4 mx;
    mx.x = lrelu(decf(g_gmax[0]) + decf(g_gmax[4]));
    mx.y = lrelu(decf(g_gmax[1]) + decf(g_gmax[5]));
    mx.z = lrelu(decf(g_gmax[2]) + decf(g_gmax[6]));
    mx.w = lrelu(decf(g_gmax[3]) + decf(g_gmax[7]));

    float4 dn = make_float4(0.f, 0.f, 0.f, 0.f);
    float a[8];
#pragma unroll
    for (int j = 0; j < 8; j++) a[j] = 0.f;
    const int hsel = lane >> 3;
    const uint4* whb = (const uint4*)g_Wh1f;

    for (int base = 0; base < deg; base += 32) {
        int j = base + lane;
        float4 w4 = make_float4(0.f, 0.f, 0.f, 0.f);
        int s = 0;
        if (j < deg) {
            s = g_eid[off0 + j];
            float4 ss = g_s1src[s];
            w4.x = __expf(lrelu(ss.x + sd.x) - mx.x);
            w4.y = __expf(lrelu(ss.y + sd.y) - mx.y);
            w4.z = __expf(lrelu(ss.z + sd.z) - mx.z);
            w4.w = __expf(lrelu(ss.w + sd.w) - mx.w);
            dn.x += w4.x; dn.y += w4.y; dn.z += w4.z; dn.w += w4.w;
        }
        sw[wl][lane] = w4;
        ssm[wl][lane] = s;
        __syncwarp();
        int cnt = min(32, deg - base);
        for (int k = 0; k < cnt; k++) {
            int sk = ssm[wl][k];
            float wk = ((const float*)(sw[wl] + k))[hsel];
            uint4 rv = whb[(size_t)sk * 32 + lane];
            const __half2* hp = (const __half2*)&rv;
            float2 f0 = __half22float2(hp[0]);
            float2 f1 = __half22float2(hp[1]);
            float2 f2 = __half22float2(hp[2]);
            float2 f3 = __half22float2(hp[3]);
            a[0] += wk * f0.x; a[1] += wk * f0.y;
            a[2] += wk * f1.x; a[3] += wk * f1.y;
            a[4] += wk * f2.x; a[5] += wk * f2.y;
            a[6] += wk * f3.x; a[7] += wk * f3.y;
        }
        __syncwarp();
    }

    dn.x = wredsum(dn.x); dn.y = wredsum(dn.y);
    dn.z = wredsum(dn.z); dn.w = wredsum(dn.w);
    float invs[4];
    invs[0] = (deg > 0) ? 1.f / dn.x : 0.f;
    invs[1] = (deg > 0) ? 1.f / dn.y : 0.f;
    invs[2] = (deg > 0) ? 1.f / dn.z : 0.f;
    invs[3] = (deg > 0) ? 1.f / dn.w : 0.f;
    float invh = invs[hsel];

    __half hh[8];
#pragma unroll
    for (int j = 0; j < 8; j++) {
        float vv = a[j] * invh;
        vv = vv > 0.f ? vv : expm1f(vv);
        hh[j] = __float2half_rn(vv);
    }
    *(uint4*)(g_Xf + (size_t)v * 256 + lane * 8) = *(uint4*)hh;
}

// ---------------- layer-2 aggregation + log_softmax: fp16 gather ----------------
__global__ void agg2_kernel(float* __restrict__ out) {
    int gw = blockIdx.x * 8 + (threadIdx.x >> 5);
    int lane = threadIdx.x & 31;
    if (gw >= N_NODES) return;
    const int v = gw;
    const int off0 = g_off[v];
    const int deg = g_off[v + 1] - off0;
    const float sd = g_s2dst[v];
    const float mx = lrelu(decf(g_gmax[8]) + decf(g_gmax[9]));
    const bool valid = lane < 20;

    float dn = 0.f;
    float ax = 0.f, ay = 0.f;
    for (int base = 0; base < deg; base += 32) {
        int j = base + lane;
        float w = 0.f;
        int s = 0;
        if (j < deg) {
            s = g_eid[off0 + j];
            w = __expf(lrelu(g_s2src[s] + sd) - mx);
            dn += w;
        }
        int cnt = min(32, deg - base);
        for (int k = 0; k < cnt; k++) {
            int sk = __shfl_sync(FULLMASK, s, k);
            float wk = __shfl_sync(FULLMASK, w, k);
            if (valid) {
                __half2 hv = *((const __half2*)(g_Wh2f + (size_t)sk * 40) + lane);
                float2 f = __half22float2(hv);
                ax += wk * f.x;
                ay += wk * f.y;
            }
        }
    }
    dn = wredsum(dn);
    float inv = (deg > 0) ? 1.f / dn : 0.f;
    ax *= inv;
    ay *= inv;

    float m = wredmax(valid ? fmaxf(ax, ay) : -3e38f);
    float se = wredsum(valid ? (__expf(ax - m) + __expf(ay - m)) : 0.f);
    float lse = m + logf(se);
    if (valid) {
        out[(size_t)v * NCLASS + 2 * lane] = ax - lse;
        out[(size_t)v * NCLASS + 2 * lane + 1] = ay - lse;
    }
}

// ---------------- launcher ----------------
extern "C" void kernel_launch(void* const* d_in, const int* in_sizes, int n_in,
                              void* d_out, int out_size) {
    const float* h = (const float*)d_in[0];
    const int* ei = (const int*)d_in[1];
    const float* Wheads = (const float*)d_in[2];
    const float* aheads = (const float*)d_in[3];
    const float* Wout = (const float*)d_in[4];
    const float* aout = (const float*)d_in[5];
    const int* src = ei;
    const int* dst = ei + N_EDGES;
    float* out = (float*)d_out;

    __nv_bfloat16 *pW1h, *pW1l, *pAh, *pAl;
    __half *pW2f, *pWh1f, *pXf, *pWh2f;
    cudaGetSymbolAddress((void**)&pW1h, g_W1t_hi);
    cudaGetSymbolAddress((void**)&pW1l, g_W1t_lo);
    cudaGetSymbolAddress((void**)&pW2f, g_W2f);
    cudaGetSymbolAddress((void**)&pAh, g_Ah);
    cudaGetSymbolAddress((void**)&pAl, g_Al);
    cudaGetSymbolAddress((void**)&pWh1f, g_Wh1f);
    cudaGetSymbolAddress((void**)&pXf, g_Xf);
    cudaGetSymbolAddress((void**)&pWh2f, g_Wh2f);

    constexpr int SMEM1 = 4 * (64 * 40 * 2) + 4 * (256 * 40 * 2);   // 102400
    constexpr int SMEM2 = 2 * (128 * 40 * 2) + 2 * (64 * 40 * 2);   // 30720

    cudaFuncSetAttribute((const void*)gemm1_kernel,
                         cudaFuncAttributeMaxDynamicSharedMemorySize, SMEM1);
    cudaFuncSetAttribute((const void*)gemm2_kernel,
                         cudaFuncAttributeMaxDynamicSharedMemorySize, SMEM2);

    setup_kernel<<<(N_NODES + 256) / 256, 256>>>(Wheads, Wout);
    convert_hilo<<<(N_NODES * 64 + 255) / 256, 256>>>(h, pAh, pAl, N_NODES * 64);

    count_kernel<<<N_EDGES / 256, 256>>>(dst);
    {
        int n = N_NODES + 1;
        int nb = (n + 1023) / 1024;  // 98
        scan1_kernel<<<nb, 1024>>>(n);
        scan2_kernel<<<1, 128>>>(nb);
        scan3_kernel<<<(n + 255) / 256, 256>>>(n);
    }
    fill_kernel<<<N_EDGES / 256, 256>>>(dst, src);

    gemm1_kernel<<<dim3(1, (N_NODES + 63) / 64), 256, SMEM1>>>(
        pAh, pAl, pW1h, pW1l, pWh1f, aheads, N_NODES);

    agg1_kernel<<<(N_NODES + 7) / 8, 256>>>();

    gemm2_kernel<<<dim3(1, (N_NODES + 127) / 128), 256, SMEM2>>>(
        pXf, pW2f, pWh2f, aout, N_NODES);

    agg2_kernel<<<(N_NODES + 7) / 8, 256>>>(out);
}

// round 7
// speedup vs baseline: 2.7195x; 1.1048x over previous
#include <cuda_runtime.h>
#include <cuda_bf16.h>
#include <cuda_fp16.h>
#include <math.h>
#include <stdint.h>

#define N_NODES 100000
#define N_EDGES 1600000
#define NCLASS  40
#define LALPHA  0.2f
#define FULLMASK 0xffffffffu

// ---------------- scratch (static device globals) ----------------
__device__ __align__(16) __nv_bfloat16 g_W1t_hi[256 * 256];
__device__ __align__(16) __nv_bfloat16 g_W1t_lo[256 * 256];
__device__ __align__(16) __half g_W2f[64 * 256];               // W_out^T padded, fp16
__device__ __align__(16) __half g_Wh1f[(size_t)N_NODES * 256]; // layer1 features fp16
__device__ __align__(16) __half g_Xf[(size_t)N_NODES * 256];   // layer1 output fp16
__device__ __align__(16) __half g_Wh2f[(size_t)N_NODES * 40];  // layer2 logits fp16, stride 40
__device__ float4 g_s1src[N_NODES];
__device__ float4 g_s1dst[N_NODES];
__device__ float g_s2src[N_NODES];
__device__ float g_s2dst[N_NODES];
__device__ int g_deg[N_NODES + 1];
__device__ int g_off[N_NODES + 1];
__device__ int g_rank[N_EDGES];
__device__ int g_eid[N_EDGES];
__device__ int g_bsum[128];
__device__ int g_bsum2[128];
__device__ unsigned g_gmax[10];

// ---------------- helpers ----------------
__device__ __forceinline__ float wredmax(float v) {
#pragma unroll
    for (int o = 16; o; o >>= 1) v = fmaxf(v, __shfl_xor_sync(FULLMASK, v, o));
    return v;
}
__device__ __forceinline__ float wredsum(float v) {
#pragma unroll
    for (int o = 16; o; o >>= 1) v += __shfl_xor_sync(FULLMASK, v, o);
    return v;
}
__device__ __forceinline__ float lrelu(float x) { return x > 0.f ? x : LALPHA * x; }
__device__ __forceinline__ unsigned encf(float f) {
    int i = __float_as_int(f);
    return (i < 0) ? ~(unsigned)i : ((unsigned)i | 0x80000000u);
}
__device__ __forceinline__ float decf(unsigned u) {
    int i = (u & 0x80000000u) ? (int)(u & 0x7fffffffu) : ~(int)u;
    return __int_as_float(i);
}
__device__ __forceinline__ void mma_bf16(float* c, const unsigned* a, const unsigned* b) {
    asm volatile(
        "mma.sync.aligned.m16n8k16.row.col.f32.bf16.bf16.f32 "
        "{%0,%1,%2,%3},{%4,%5,%6,%7},{%8,%9},{%0,%1,%2,%3};"
        : "+f"(c[0]), "+f"(c[1]), "+f"(c[2]), "+f"(c[3])
        : "r"(a[0]), "r"(a[1]), "r"(a[2]), "r"(a[3]), "r"(b[0]), "r"(b[1]));
}
__device__ __forceinline__ void mma_f16(float* c, const unsigned* a, const unsigned* b) {
    asm volatile(
        "mma.sync.aligned.m16n8k16.row.col.f32.f16.f16.f32 "
        "{%0,%1,%2,%3},{%4,%5,%6,%7},{%8,%9},{%0,%1,%2,%3};"
        : "+f"(c[0]), "+f"(c[1]), "+f"(c[2]), "+f"(c[3])
        : "r"(a[0]), "r"(a[1]), "r"(a[2]), "r"(a[3]), "r"(b[0]), "r"(b[1]));
}
__device__ __forceinline__ void ldsm_x4(unsigned* r, unsigned a) {
    asm volatile("ldmatrix.sync.aligned.m8n8.x4.shared.b16 {%0,%1,%2,%3}, [%4];"
                 : "=r"(r[0]), "=r"(r[1]), "=r"(r[2]), "=r"(r[3]) : "r"(a));
}
__device__ __forceinline__ void cp16(unsigned d, const void* s, int sz) {
    asm volatile("cp.async.cg.shared.global [%0], [%1], 16, %2;" :: "r"(d), "l"(s), "r"(sz));
}
__device__ __forceinline__ void cp_commit() { asm volatile("cp.async.commit_group;"); }
template <int NW> __device__ __forceinline__ void cp_wait() {
    asm volatile("cp.async.wait_group %0;" :: "n"(NW));
}

// ---------------- merged setup: pack W1 hi/lo, pack W2, zero deg/gmax ----------------
__global__ void setup_kernel(const float* __restrict__ Wh, const float* __restrict__ Wo) {
    int idx = blockIdx.x * blockDim.x + threadIdx.x;
    if (idx <= N_NODES) g_deg[idx] = 0;
    if (idx < 10) g_gmax[idx] = encf(-3e38f);
    if (idx < 256 * 256) {
        int c = idx >> 8, k = idx & 255;
        int head = c >> 6, j = c & 63;
        float v = Wh[head * (256 * 64) + k * 64 + j];
        __nv_bfloat16 hi = __float2bfloat16_rn(v);
        g_W1t_hi[c * 256 + k] = hi;
        g_W1t_lo[c * 256 + k] = __float2bfloat16_rn(v - __bfloat162float(hi));
    }
    if (idx < 64 * 256) {
        int c = idx >> 8, k = idx & 255;
        float v = (c < NCLASS) ? Wo[k * NCLASS + c] : 0.f;
        g_W2f[c * 256 + k] = __float2half_rn(v);
    }
}

// ---------------- GEMM1: Wh1 = h @ Wcat, A fp32 staged + in-kernel hi/lo split ----------------
// BM=64, BN=256, 256 threads, warp grid 1x8 (WM=64, WN=32). 3-term split-bf16 mma.
// Fused: scores1 (Wh.a_src / Wh.a_dst) + global max atomics. Epilogue reuses A-f32 smem.
__global__ __launch_bounds__(256, 2) void gemm1_kernel(
    const float* __restrict__ A,
    const __nv_bfloat16* __restrict__ Bth, const __nv_bfloat16* __restrict__ Btl,
    __half* __restrict__ Whf, const float* __restrict__ a_heads, int M) {
    constexpr int MI = 4, NI = 4;
    constexpr int LDSB = 40;                 // bf16 row stride (80B, 16B-aligned)
    constexpr int LDSAF = 36;                // fp32 row stride (144B, 16B-aligned)
    constexpr int SZAF = 64 * LDSAF * 4;     // 9216 B per fp32 A stage
    constexpr int OFF_AH = 2 * SZAF;         // 18432
    constexpr int OFF_AL = OFF_AH + 64 * LDSB * 2;  // 23552
    constexpr int OFF_B = OFF_AL + 64 * LDSB * 2;   // 28672
    constexpr int SZB = 256 * LDSB * 2;      // 20480 per B stage per array
    // total dynamic: 28672 + 4*20480 = 110592

    extern __shared__ char smem[];
    const unsigned uS = (unsigned)__cvta_generic_to_shared(smem);
    const unsigned uAf = uS;
    const unsigned uAh = uS + OFF_AH;
    const unsigned uAl = uS + OFF_AL;
    const unsigned uBh = uS + OFF_B;
    const unsigned uBl = uS + OFF_B + 2 * SZB;
    // epilogue aliases (A-f32 region is dead by then)
    float* sP = (float*)smem;                 // [64][8]
    float* sQ = (float*)(smem + 2048);        // [64][8]
    float* sMp = (float*)(smem + 4096);       // [8][4]
    float* sMq = (float*)(smem + 4224);       // [8][4]

    const int tid = threadIdx.x, lane = tid & 31, wid = tid >> 5;
    const int wn = wid;  // warp grid 1 x 8
    const int brow = blockIdx.y * 64;

    float acc[MI][NI][4];
#pragma unroll
    for (int mi = 0; mi < MI; mi++)
#pragma unroll
        for (int ni = 0; ni < NI; ni++)
#pragma unroll
            for (int q = 0; q < 4; q++) acc[mi][ni][q] = 0.f;

    auto stage = [&](int s, int k0) {
        // A fp32: 64 rows x 32 floats = 8 x 16B chunks per row
#pragma unroll
        for (int it = 0; it < 2; it++) {
            int i = tid + it * 256;
            int row = i >> 3, c = i & 7;
            int gr = brow + row;
            int ok = (gr < M) ? 16 : 0;
            const float* srcp = A + (size_t)min(gr, M - 1) * 256 + k0 + c * 4;
            cp16(uAf + (unsigned)(s * SZAF + (row * LDSAF + c * 4) * 4), srcp, ok);
        }
        // B hi/lo: 256 rows x 4 chunks
#pragma unroll
        for (int it = 0; it < 4; it++) {
            int i = tid + it * 256;
            int row = i >> 2, c = i & 3;
            size_t go = (size_t)row * 256 + k0 + c * 8;
            unsigned dof = (unsigned)(s * SZB + (row * LDSB + c * 8) * 2);
            cp16(uBh + dof, Bth + go, 16);
            cp16(uBl + dof, Btl + go, 16);
        }
    };

    stage(0, 0);
    cp_commit();

#pragma unroll
    for (int it = 0; it < 8; it++) {
        const int s = it & 1;
        if (it < 7) {
            stage(s ^ 1, (it + 1) * 32);
            cp_commit();
            cp_wait<1>();
        } else {
            cp_wait<0>();
        }
        __syncthreads();

        // convert A fp32 stage s -> hi/lo bf16 (single-stage buffers)
        {
            int row = tid >> 2, seg = tid & 3;
            const char* pf = smem + s * SZAF + (row * LDSAF + seg * 8) * 4;
            float4 v0 = *(const float4*)pf;
            float4 v1 = *(const float4*)(pf + 16);
            float vv[8] = {v0.x, v0.y, v0.z, v0.w, v1.x, v1.y, v1.z, v1.w};
            __nv_bfloat16 hh[8], ll[8];
#pragma unroll
            for (int j = 0; j < 8; j++) {
                hh[j] = __float2bfloat16_rn(vv[j]);
                ll[j] = __float2bfloat16_rn(vv[j] - __bfloat162float(hh[j]));
            }
            char* ph = smem + OFF_AH + (row * LDSB + seg * 8) * 2;
            char* pl = smem + OFF_AL + (row * LDSB + seg * 8) * 2;
            *(uint4*)ph = *(uint4*)hh;
            *(uint4*)pl = *(uint4*)ll;
        }
        __syncthreads();

#pragma unroll
        for (int kk = 0; kk < 32; kk += 16) {
            unsigned ah[MI][4], al[MI][4], bh[NI][2], bl[NI][2];
            const int ra = lane & 15;
            const int kca = (lane >> 4) << 3;
#pragma unroll
            for (int mi = 0; mi < MI; mi++) {
                unsigned off = (unsigned)(((mi * 16 + ra) * LDSB + kk + kca) * 2);
                ldsm_x4(ah[mi], uAh + off);
                ldsm_x4(al[mi], uAl + off);
            }
            const int rb = (lane & 7) + ((lane >> 4) << 3);
            const int kcb = ((lane >> 3) & 1) << 3;
#pragma unroll
            for (int nb = 0; nb < NI / 2; nb++) {
                unsigned off = (unsigned)(((wn * 32 + nb * 16 + rb) * LDSB + kk + kcb) * 2) +
                               (unsigned)(s * SZB);
                unsigned t4[4];
                ldsm_x4(t4, uBh + off);
                bh[2 * nb][0] = t4[0]; bh[2 * nb][1] = t4[1];
                bh[2 * nb + 1][0] = t4[2]; bh[2 * nb + 1][1] = t4[3];
                ldsm_x4(t4, uBl + off);
                bl[2 * nb][0] = t4[0]; bl[2 * nb][1] = t4[1];
                bl[2 * nb + 1][0] = t4[2]; bl[2 * nb + 1][1] = t4[3];
            }
#pragma unroll
            for (int mi = 0; mi < MI; mi++)
#pragma unroll
                for (int ni = 0; ni < NI; ni++) {
                    mma_bf16(acc[mi][ni], ah[mi], bh[ni]);
                    mma_bf16(acc[mi][ni], ah[mi], bl[ni]);
                    mma_bf16(acc[mi][ni], al[mi], bh[ni]);
                }
        }
        __syncthreads();
    }

    // epilogue: fused scores + fp16 store (a_heads read direct; L1-resident)
    const int g = lane >> 2, t = lane & 3;
    float asr[NI][2], adr[NI][2];
#pragma unroll
    for (int ni = 0; ni < NI; ni++)
#pragma unroll
        for (int qq = 0; qq < 2; qq++) {
            int cl = wn * 32 + ni * 8 + 2 * t + qq;  // global col (BN=256 = all cols)
            asr[ni][qq] = a_heads[(cl >> 6) * 128 + (cl & 63)];
            adr[ni][qq] = a_heads[(cl >> 6) * 128 + 64 + (cl & 63)];
        }
#pragma unroll
    for (int mi = 0; mi < MI; mi++) {
        float p0 = 0.f, q0 = 0.f, p1 = 0.f, q1 = 0.f;
#pragma unroll
        for (int ni = 0; ni < NI; ni++)
#pragma unroll
            for (int qq = 0; qq < 2; qq++) {
                p0 += acc[mi][ni][qq] * asr[ni][qq];
                q0 += acc[mi][ni][qq] * adr[ni][qq];
                p1 += acc[mi][ni][2 + qq] * asr[ni][qq];
                q1 += acc[mi][ni][2 + qq] * adr[ni][qq];
            }
#pragma unroll
        for (int o = 1; o <= 2; o <<= 1) {
            p0 += __shfl_xor_sync(FULLMASK, p0, o);
            q0 += __shfl_xor_sync(FULLMASK, q0, o);
            p1 += __shfl_xor_sync(FULLMASK, p1, o);
            q1 += __shfl_xor_sync(FULLMASK, q1, o);
        }
        int r0 = mi * 16 + g;
        if (t == 0) {
            sP[r0 * 8 + wn] = p0; sQ[r0 * 8 + wn] = q0;
            sP[(r0 + 8) * 8 + wn] = p1; sQ[(r0 + 8) * 8 + wn] = q1;
        }
        int gr0 = brow + r0;
#pragma unroll
        for (int ni = 0; ni < NI; ni++) {
            int c = wn * 32 + ni * 8 + 2 * t;
            if (gr0 < M)
                *(__half2*)(Whf + (size_t)gr0 * 256 + c) =
                    __floats2half2_rn(acc[mi][ni][0], acc[mi][ni][1]);
            if (gr0 + 8 < M)
                *(__half2*)(Whf + (size_t)(gr0 + 8) * 256 + c) =
                    __floats2half2_rn(acc[mi][ni][2], acc[mi][ni][3]);
        }
    }
    __syncthreads();
    {
        int row = tid >> 2, hd = tid & 3;  // 64 rows x 4 heads
        int gr = brow + row;
        float p = -3e38f, q = -3e38f;
        float pv = sP[row * 8 + 2 * hd] + sP[row * 8 + 2 * hd + 1];
        float qv = sQ[row * 8 + 2 * hd] + sQ[row * 8 + 2 * hd + 1];
        if (gr < M) {
            ((float*)g_s1src)[gr * 4 + hd] = pv;
            ((float*)g_s1dst)[gr * 4 + hd] = qv;
            p = pv; q = qv;
        }
#pragma unroll
        for (int o = 4; o <= 16; o <<= 1) {
            p = fmaxf(p, __shfl_xor_sync(FULLMASK, p, o));
            q = fmaxf(q, __shfl_xor_sync(FULLMASK, q, o));
        }
        if (lane < 4) {
            sMp[wid * 4 + lane] = p;
            sMq[wid * 4 + lane] = q;
        }
    }
    __syncthreads();
    if (tid < 32) {
        int h = tid & 3;
        float p = sMp[tid], q = sMq[tid];
#pragma unroll
        for (int o = 4; o <= 16; o <<= 1) {
            p = fmaxf(p, __shfl_xor_sync(FULLMASK, p, o));
            q = fmaxf(q, __shfl_xor_sync(FULLMASK, q, o));
        }
        if (tid < 4) {
            atomicMax(&g_gmax[h], encf(p));
            atomicMax(&g_gmax[4 + h], encf(q));
        }
    }
}

// ---------------- GEMM2: Wh2 = x @ W2 (fp16 1-term) + fused scores2 + max ----------------
__global__ __launch_bounds__(256, 2) void gemm2_kernel(
    const __half* __restrict__ A, const __half* __restrict__ Bt,
    __half* __restrict__ Whf, const float* __restrict__ a_out, int M) {
    constexpr int WM = 64, WN = 16, MI = 4, NI = 2, WNW = 4;
    constexpr int LDSB = 40;
    constexpr int SZA = 128 * LDSB * 2;
    constexpr int SZB = 64 * LDSB * 2;

    extern __shared__ char smem[];
    const unsigned uA = (unsigned)__cvta_generic_to_shared(smem);
    const unsigned uB = uA + 2 * SZA;
    __shared__ float sAS[64], sAD[64];
    __shared__ float sP[128][4], sQ[128][4];
    __shared__ float sMp[8], sMq[8];

    const int tid = threadIdx.x, lane = tid & 31, wid = tid >> 5;
    const int wm = wid / WNW, wn = wid % WNW;
    const int brow = blockIdx.y * 128;

    if (tid < 64) {
        sAS[tid] = (tid < NCLASS) ? a_out[tid] : 0.f;
        sAD[tid] = (tid < NCLASS) ? a_out[NCLASS + tid] : 0.f;
    }

    float acc[MI][NI][4];
#pragma unroll
    for (int mi = 0; mi < MI; mi++)
#pragma unroll
        for (int ni = 0; ni < NI; ni++)
#pragma unroll
            for (int q = 0; q < 4; q++) acc[mi][ni][q] = 0.f;

    auto stage = [&](int s, int k0) {
#pragma unroll
        for (int i = tid; i < 512; i += 256) {
            int row = i >> 2, c = i & 3;
            int gr = brow + row;
            int ok = (gr < M) ? 16 : 0;
            size_t go = (size_t)min(gr, M - 1) * 256 + k0 + c * 8;
            cp16(uA + (unsigned)(s * SZA + (row * LDSB + c * 8) * 2), A + go, ok);
        }
        if (tid < 256) {
            int row = tid >> 2, c = tid & 3;
            size_t go = (size_t)row * 256 + k0 + c * 8;
            cp16(uB + (unsigned)(s * SZB + (row * LDSB + c * 8) * 2), Bt + go, 16);
        }
    };

    stage(0, 0);
    cp_commit();

#pragma unroll
    for (int it = 0; it < 8; it++) {
        const int s = it & 1;
        if (it < 7) {
            stage(s ^ 1, (it + 1) * 32);
            cp_commit();
            cp_wait<1>();
        } else {
            cp_wait<0>();
        }
        __syncthreads();

#pragma unroll
        for (int kk = 0; kk < 32; kk += 16) {
            unsigned af[MI][4], bf[NI][2];
            const int ra = lane & 15;
            const int kca = (lane >> 4) << 3;
#pragma unroll
            for (int mi = 0; mi < MI; mi++) {
                unsigned off = (unsigned)(((wm * WM + mi * 16 + ra) * LDSB + kk + kca) * 2) +
                               (unsigned)(s * SZA);
                ldsm_x4(af[mi], uA + off);
            }
            const int rb = (lane & 7) + ((lane >> 4) << 3);
            const int kcb = ((lane >> 3) & 1) << 3;
            {
                unsigned off = (unsigned)(((wn * WN + rb) * LDSB + kk + kcb) * 2) +
                               (unsigned)(s * SZB);
                unsigned t4[4];
                ldsm_x4(t4, uB + off);
                bf[0][0] = t4[0]; bf[0][1] = t4[1];
                bf[1][0] = t4[2]; bf[1][1] = t4[3];
            }
#pragma unroll
            for (int mi = 0; mi < MI; mi++)
#pragma unroll
                for (int ni = 0; ni < NI; ni++)
                    mma_f16(acc[mi][ni], af[mi], bf[ni]);
        }
        __syncthreads();
    }

    const int g = lane >> 2, t = lane & 3;
#pragma unroll
    for (int mi = 0; mi < MI; mi++) {
        float p0 = 0.f, q0 = 0.f, p1 = 0.f, q1 = 0.f;
#pragma unroll
        for (int ni = 0; ni < NI; ni++)
#pragma unroll
            for (int qq = 0; qq < 2; qq++) {
                int cl = wn * WN + ni * 8 + 2 * t + qq;
                float as = sAS[cl], ad = sAD[cl];
                p0 += acc[mi][ni][qq] * as;
                q0 += acc[mi][ni][qq] * ad;
                p1 += acc[mi][ni][2 + qq] * as;
                q1 += acc[mi][ni][2 + qq] * ad;
            }
#pragma unroll
        for (int o = 1; o <= 2; o <<= 1) {
            p0 += __shfl_xor_sync(FULLMASK, p0, o);
            q0 += __shfl_xor_sync(FULLMASK, q0, o);
            p1 += __shfl_xor_sync(FULLMASK, p1, o);
            q1 += __shfl_xor_sync(FULLMASK, q1, o);
        }
        int r0 = wm * WM + mi * 16 + g;
        if (t == 0) {
            sP[r0][wn] = p0; sQ[r0][wn] = q0;
            sP[r0 + 8][wn] = p1; sQ[r0 + 8][wn] = q1;
        }
        int gr0 = brow + r0;
#pragma unroll
        for (int ni = 0; ni < NI; ni++) {
            int c = wn * WN + ni * 8 + 2 * t;
            if (c < NCLASS) {
                if (gr0 < M)
                    *(__half2*)(Whf + (size_t)gr0 * 40 + c) =
                        __floats2half2_rn(acc[mi][ni][0], acc[mi][ni][1]);
                if (gr0 + 8 < M)
                    *(__half2*)(Whf + (size_t)(gr0 + 8) * 40 + c) =
                        __floats2half2_rn(acc[mi][ni][2], acc[mi][ni][3]);
            }
        }
    }
    __syncthreads();
    {
        float p = -3e38f, q = -3e38f;
        if (tid < 128) {
            int gr = brow + tid;
            float pv = sP[tid][0] + sP[tid][1] + sP[tid][2] + sP[tid][3];
            float qv = sQ[tid][0] + sQ[tid][1] + sQ[tid][2] + sQ[tid][3];
            if (gr < M) {
                g_s2src[gr] = pv;
                g_s2dst[gr] = qv;
                p = pv; q = qv;
            }
        }
        p = wredmax(p);
        q = wredmax(q);
        if (lane == 0) {
            sMp[wid] = p;
            sMq[wid] = q;
        }
    }
    __syncthreads();
    if (tid == 0) {
        float p = sMp[0], q = sMq[0];
#pragma unroll
        for (int w = 1; w < 8; w++) {
            p = fmaxf(p, sMp[w]);
            q = fmaxf(q, sMq[w]);
        }
        atomicMax(&g_gmax[8], encf(p));
        atomicMax(&g_gmax[9], encf(q));
    }
}

// ---------------- CSR build (single-atomic: count stores rank) ----------------
__global__ void count_kernel(const int* __restrict__ dst) {
    int e = blockIdx.x * blockDim.x + threadIdx.x;
    if (e < N_EDGES) g_rank[e] = atomicAdd(&g_deg[dst[e]], 1);
}
__global__ void scan1_kernel(int n) {
    __shared__ int s[1024];
    int tid = threadIdx.x;
    int gid = blockIdx.x * 1024 + tid;
    int v = (gid < n) ? g_deg[gid] : 0;
    s[tid] = v;
    __syncthreads();
    int t = v;
    for (int d = 1; d < 1024; d <<= 1) {
        int add = (tid >= d) ? s[tid - d] : 0;
        __syncthreads();
        t += add;
        s[tid] = t;
        __syncthreads();
    }
    if (gid < n) g_off[gid] = t - v;
    if (tid == 1023) g_bsum[blockIdx.x] = t;
}
__global__ void scan2_kernel(int nb) {
    __shared__ int s[128];
    int tid = threadIdx.x;
    int v = (tid < nb) ? g_bsum[tid] : 0;
    s[tid] = v;
    __syncthreads();
    int t = v;
    for (int d = 1; d < 128; d <<= 1) {
        int add = (tid >= d) ? s[tid - d] : 0;
        __syncthreads();
        t += add;
        s[tid] = t;
        __syncthreads();
    }
    if (tid < nb) g_bsum2[tid] = t - v;
}
__global__ void scan3_kernel(int n) {
    int i = blockIdx.x * blockDim.x + threadIdx.x;
    if (i < n) g_off[i] += g_bsum2[i >> 10];
}
__global__ void fill_kernel(const int* __restrict__ dst, const int* __restrict__ src) {
    int e = blockIdx.x * blockDim.x + threadIdx.x;
    if (e >= N_EDGES) return;
    int pos = g_off[dst[e]] + g_rank[e];
    g_eid[pos] = src[e];
}

// ---------------- layer-1 aggregation: fp16 gather, single pass ----------------
__global__ void agg1_kernel() {
    __shared__ float4 sw[8][32];
    __shared__ int ssm[8][32];
    int gw = blockIdx.x * 8 + (threadIdx.x >> 5);
    int lane = threadIdx.x & 31;
    int wl = threadIdx.x >> 5;
    if (gw >= N_NODES) return;
    const int v = gw;
    const int off0 = g_off[v];
    const int deg = g_off[v + 1] - off0;
    const float4 sd = g_s1dst[v];

    float4 mx;
    mx.x = lrelu(decf(g_gmax[0]) + decf(g_gmax[4]));
    mx.y = lrelu(decf(g_gmax[1]) + decf(g_gmax[5]));
    mx.z = lrelu(decf(g_gmax[2]) + decf(g_gmax[6]));
    mx.w = lrelu(decf(g_gmax[3]) + decf(g_gmax[7]));

    float4 dn = make_float4(0.f, 0.f, 0.f, 0.f);
    float a[8];
#pragma unroll
    for (int j = 0; j < 8; j++) a[j] = 0.f;
    const int hsel = lane >> 3;
    const uint4* whb = (const uint4*)g_Wh1f;

    for (int base = 0; base < deg; base += 32) {
        int j = base + lane;
        float4 w4 = make_float4(0.f, 0.f, 0.f, 0.f);
        int s = 0;
        if (j < deg) {
            s = g_eid[off0 + j];
            float4 ss = g_s1src[s];
            w4.x = __expf(lrelu(ss.x + sd.x) - mx.x);
            w4.y = __expf(lrelu(ss.y + sd.y) - mx.y);
            w4.z = __expf(lrelu(ss.z + sd.z) - mx.z);
            w4.w = __expf(lrelu(ss.w + sd.w) - mx.w);
            dn.x += w4.x; dn.y += w4.y; dn.z += w4.z; dn.w += w4.w;
        }
        sw[wl][lane] = w4;
        ssm[wl][lane] = s;
        __syncwarp();
        int cnt = min(32, deg - base);
        for (int k = 0; k < cnt; k++) {
            int sk = ssm[wl][k];
            float wk = ((const float*)(sw[wl] + k))[hsel];
            uint4 rv = whb[(size_t)sk * 32 + lane];
            const __half2* hp = (const __half2*)&rv;
            float2 f0 = __half22float2(hp[0]);
            float2 f1 = __half22float2(hp[1]);
            float2 f2 = __half22float2(hp[2]);
            float2 f3 = __half22float2(hp[3]);
            a[0] += wk * f0.x; a[1] += wk * f0.y;
            a[2] += wk * f1.x; a[3] += wk * f1.y;
            a[4] += wk * f2.x; a[5] += wk * f2.y;
            a[6] += wk * f3.x; a[7] += wk * f3.y;
        }
        __syncwarp();
    }

    dn.x = wredsum(dn.x); dn.y = wredsum(dn.y);
    dn.z = wredsum(dn.z); dn.w = wredsum(dn.w);
    float invs[4];
    invs[0] = (deg > 0) ? 1.f / dn.x : 0.f;
    invs[1] = (deg > 0) ? 1.f / dn.y : 0.f;
    invs[2] = (deg > 0) ? 1.f / dn.z : 0.f;
    invs[3] = (deg > 0) ? 1.f / dn.w : 0.f;
    float invh = invs[hsel];

    __half hh[8];
#pragma unroll
    for (int j = 0; j < 8; j++) {
        float vv = a[j] * invh;
        vv = vv > 0.f ? vv : expm1f(vv);
        hh[j] = __float2half_rn(vv);
    }
    *(uint4*)(g_Xf + (size_t)v * 256 + lane * 8) = *(uint4*)hh;
}

// ---------------- layer-2 aggregation + log_softmax: fp16 gather ----------------
__global__ void agg2_kernel(float* __restrict__ out) {
    int gw = blockIdx.x * 8 + (threadIdx.x >> 5);
    int lane = threadIdx.x & 31;
    if (gw >= N_NODES) return;
    const int v = gw;
    const int off0 = g_off[v];
    const int deg = g_off[v + 1] - off0;
    const float sd = g_s2dst[v];
    const float mx = lrelu(decf(g_gmax[8]) + decf(g_gmax[9]));
    const bool valid = lane < 20;

    float dn = 0.f;
    float ax = 0.f, ay = 0.f;
    for (int base = 0; base < deg; base += 32) {
        int j = base + lane;
        float w = 0.f;
        int s = 0;
        if (j < deg) {
            s = g_eid[off0 + j];
            w = __expf(lrelu(g_s2src[s] + sd) - mx);
            dn += w;
        }
        int cnt = min(32, deg - base);
        for (int k = 0; k < cnt; k++) {
            int sk = __shfl_sync(FULLMASK, s, k);
            float wk = __shfl_sync(FULLMASK, w, k);
            if (valid) {
                __half2 hv = *((const __half2*)(g_Wh2f + (size_t)sk * 40) + lane);
                float2 f = __half22float2(hv);
                ax += wk * f.x;
                ay += wk * f.y;
            }
        }
    }
    dn = wredsum(dn);
    float inv = (deg > 0) ? 1.f / dn : 0.f;
    ax *= inv;
    ay *= inv;

    float m = wredmax(valid ? fmaxf(ax, ay) : -3e38f);
    float se = wredsum(valid ? (__expf(ax - m) + __expf(ay - m)) : 0.f);
    float lse = m + logf(se);
    if (valid) {
        out[(size_t)v * NCLASS + 2 * lane] = ax - lse;
        out[(size_t)v * NCLASS + 2 * lane + 1] = ay - lse;
    }
}

// ---------------- launcher ----------------
extern "C" void kernel_launch(void* const* d_in, const int* in_sizes, int n_in,
                              void* d_out, int out_size) {
    const float* h = (const float*)d_in[0];
    const int* ei = (const int*)d_in[1];
    const float* Wheads = (const float*)d_in[2];
    const float* aheads = (const float*)d_in[3];
    const float* Wout = (const float*)d_in[4];
    const float* aout = (const float*)d_in[5];
    const int* src = ei;
    const int* dst = ei + N_EDGES;
    float* out = (float*)d_out;

    __nv_bfloat16 *pW1h, *pW1l;
    __half *pW2f, *pWh1f, *pXf, *pWh2f;
    cudaGetSymbolAddress((void**)&pW1h, g_W1t_hi);
    cudaGetSymbolAddress((void**)&pW1l, g_W1t_lo);
    cudaGetSymbolAddress((void**)&pW2f, g_W2f);
    cudaGetSymbolAddress((void**)&pWh1f, g_Wh1f);
    cudaGetSymbolAddress((void**)&pXf, g_Xf);
    cudaGetSymbolAddress((void**)&pWh2f, g_Wh2f);

    constexpr int SMEM1 = 28672 + 4 * (256 * 40 * 2);             // 110592
    constexpr int SMEM2 = 2 * (128 * 40 * 2) + 2 * (64 * 40 * 2); // 30720

    cudaFuncSetAttribute((const void*)gemm1_kernel,
                         cudaFuncAttributeMaxDynamicSharedMemorySize, SMEM1);
    cudaFuncSetAttribute((const void*)gemm2_kernel,
                         cudaFuncAttributeMaxDynamicSharedMemorySize, SMEM2);

    // side stream + fork/join events (host-side handles only; created per call,
    // only capture-time cost — graph replay keeps the parallel branches)
    cudaStream_t s2;
    cudaStreamCreateWithFlags(&s2, cudaStreamNonBlocking);
    cudaEvent_t evF, evJ;
    cudaEventCreateWithFlags(&evF, cudaEventDisableTiming);
    cudaEventCreateWithFlags(&evJ, cudaEventDisableTiming);

    setup_kernel<<<(N_NODES + 256) / 256, 256>>>(Wheads, Wout);

    // fork: CSR chain on s2, concurrent with GEMM1 on the main stream
    cudaEventRecord(evF, cudaStreamPerThread);
    cudaStreamWaitEvent(s2, evF, 0);
    count_kernel<<<N_EDGES / 256, 256, 0, s2>>>(dst);
    {
        int n = N_NODES + 1;
        int nb = (n + 1023) / 1024;  // 98
        scan1_kernel<<<nb, 1024, 0, s2>>>(n);
        scan2_kernel<<<1, 128, 0, s2>>>(nb);
        scan3_kernel<<<(n + 255) / 256, 256, 0, s2>>>(n);
    }
    fill_kernel<<<N_EDGES / 256, 256, 0, s2>>>(dst, src);
    cudaEventRecord(evJ, s2);

    gemm1_kernel<<<dim3(1, (N_NODES + 63) / 64), 256, SMEM1>>>(
        h, pW1h, pW1l, pWh1f, aheads, N_NODES);

    // join: agg1 needs both CSR and GEMM1 results
    cudaStreamWaitEvent(cudaStreamPerThread, evJ, 0);

    agg1_kernel<<<(N_NODES + 7) / 8, 256>>>();

    gemm2_kernel<<<dim3(1, (N_NODES + 127) / 128), 256, SMEM2>>>(
        pXf, pW2f, pWh2f, aout, N_NODES);

    agg2_kernel<<<(N_NODES + 7) / 8, 256>>>(out);
}

// round 8
// speedup vs baseline: 2.9322x; 1.0782x over previous
#include <cuda_runtime.h>
#include <cuda_bf16.h>
#include <cuda_fp16.h>
#include <math.h>
#include <stdint.h>

#define N_NODES 100000
#define N_EDGES 1600000
#define NCLASS  40
#define LALPHA  0.2f
#define FULLMASK 0xffffffffu

// ---------------- scratch (static device globals) ----------------
__device__ __align__(16) __half g_W1t_hi[256 * 256];           // Wcat^T fp16 hi
__device__ __align__(16) __half g_W1t_lo[256 * 256];           // Wcat^T fp16 lo (residual)
__device__ __align__(16) __half g_W2f[64 * 256];               // W_out^T padded, fp16
__device__ __align__(16) __half g_Wh1f[(size_t)N_NODES * 256]; // layer1 features fp16
__device__ __align__(16) __half g_Xf[(size_t)N_NODES * 256];   // layer1 output fp16
__device__ __align__(16) __half g_Wh2f[(size_t)N_NODES * 40];  // layer2 logits fp16, stride 40
__device__ float4 g_s1src[N_NODES];
__device__ float4 g_s1dst[N_NODES];
__device__ float g_s2src[N_NODES];
__device__ float g_s2dst[N_NODES];
__device__ int g_deg[N_NODES + 1];
__device__ int g_off[N_NODES + 1];
__device__ int g_rank[N_EDGES];
__device__ int g_eid[N_EDGES];
__device__ int g_bsum[128];
__device__ int g_bsum2[128];
__device__ unsigned g_gmax[10];

// ---------------- helpers ----------------
__device__ __forceinline__ float wredmax(float v) {
#pragma unroll
    for (int o = 16; o; o >>= 1) v = fmaxf(v, __shfl_xor_sync(FULLMASK, v, o));
    return v;
}
__device__ __forceinline__ float wredsum(float v) {
#pragma unroll
    for (int o = 16; o; o >>= 1) v += __shfl_xor_sync(FULLMASK, v, o);
    return v;
}
__device__ __forceinline__ float lrelu(float x) { return x > 0.f ? x : LALPHA * x; }
__device__ __forceinline__ unsigned encf(float f) {
    int i = __float_as_int(f);
    return (i < 0) ? ~(unsigned)i : ((unsigned)i | 0x80000000u);
}
__device__ __forceinline__ float decf(unsigned u) {
    int i = (u & 0x80000000u) ? (int)(u & 0x7fffffffu) : ~(int)u;
    return __int_as_float(i);
}
__device__ __forceinline__ void mma_f16(float* c, const unsigned* a, const unsigned* b) {
    asm volatile(
        "mma.sync.aligned.m16n8k16.row.col.f32.f16.f16.f32 "
        "{%0,%1,%2,%3},{%4,%5,%6,%7},{%8,%9},{%0,%1,%2,%3};"
        : "+f"(c[0]), "+f"(c[1]), "+f"(c[2]), "+f"(c[3])
        : "r"(a[0]), "r"(a[1]), "r"(a[2]), "r"(a[3]), "r"(b[0]), "r"(b[1]));
}
__device__ __forceinline__ void ldsm_x4(unsigned* r, unsigned a) {
    asm volatile("ldmatrix.sync.aligned.m8n8.x4.shared.b16 {%0,%1,%2,%3}, [%4];"
                 : "=r"(r[0]), "=r"(r[1]), "=r"(r[2]), "=r"(r[3]) : "r"(a));
}
__device__ __forceinline__ void cp16(unsigned d, const void* s, int sz) {
    asm volatile("cp.async.cg.shared.global [%0], [%1], 16, %2;" :: "r"(d), "l"(s), "r"(sz));
}
__device__ __forceinline__ void cp_commit() { asm volatile("cp.async.commit_group;"); }
template <int NW> __device__ __forceinline__ void cp_wait() {
    asm volatile("cp.async.wait_group %0;" :: "n"(NW));
}

// ---------------- merged setup: pack W1 fp16 hi/lo, pack W2, zero deg/gmax ----------------
__global__ void setup_kernel(const float* __restrict__ Wh, const float* __restrict__ Wo) {
    int idx = blockIdx.x * blockDim.x + threadIdx.x;
    if (idx <= N_NODES) g_deg[idx] = 0;
    if (idx < 10) g_gmax[idx] = encf(-3e38f);
    if (idx < 256 * 256) {
        int c = idx >> 8, k = idx & 255;
        int head = c >> 6, j = c & 63;
        float v = Wh[head * (256 * 64) + k * 64 + j];
        __half hi = __float2half_rn(v);
        g_W1t_hi[c * 256 + k] = hi;
        g_W1t_lo[c * 256 + k] = __float2half_rn(v - __half2float(hi));
    }
    if (idx < 64 * 256) {
        int c = idx >> 8, k = idx & 255;
        float v = (c < NCLASS) ? Wo[k * NCLASS + c] : 0.f;
        g_W2f[c * 256 + k] = __float2half_rn(v);
    }
}

// ---------------- GEMM1: Wh1 = h @ Wcat, A fp32 staged -> fp16 in-kernel; 2-term fp16 mma ----
// BM=64, BN=256, 256 threads, warp grid 1x8 (WM=64, WN=32).
// Terms: A*Bh + A*Bl (B hi/lo fp16 exact; A single fp16).
// Fused: scores1 + global max atomics. Epilogue reuses A-f32 smem.
__global__ __launch_bounds__(256, 2) void gemm1_kernel(
    const float* __restrict__ A,
    const __half* __restrict__ Bth, const __half* __restrict__ Btl,
    __half* __restrict__ Whf, const float* __restrict__ a_heads, int M) {
    constexpr int MI = 4, NI = 4;
    constexpr int LDSB = 40;                 // fp16 row stride (80B)
    constexpr int LDSAF = 36;                // fp32 row stride (144B)
    constexpr int SZAF = 64 * LDSAF * 4;     // 9216 B per fp32 A stage
    constexpr int OFF_AH = 2 * SZAF;         // 18432 (single fp16 A buffer)
    constexpr int OFF_B = OFF_AH + 64 * LDSB * 2;   // 23552
    constexpr int SZB = 256 * LDSB * 2;      // 20480 per B stage per array
    // total dynamic: 23552 + 4*20480 = 105472

    extern __shared__ char smem[];
    const unsigned uS = (unsigned)__cvta_generic_to_shared(smem);
    const unsigned uAf = uS;
    const unsigned uAh = uS + OFF_AH;
    const unsigned uBh = uS + OFF_B;
    const unsigned uBl = uS + OFF_B + 2 * SZB;
    // epilogue aliases (A-f32 region is dead by then)
    float* sP = (float*)smem;                 // [64][8]
    float* sQ = (float*)(smem + 2048);        // [64][8]
    float* sMp = (float*)(smem + 4096);       // [8][4]
    float* sMq = (float*)(smem + 4224);       // [8][4]

    const int tid = threadIdx.x, lane = tid & 31, wid = tid >> 5;
    const int wn = wid;  // warp grid 1 x 8
    const int brow = blockIdx.y * 64;

    float acc[MI][NI][4];
#pragma unroll
    for (int mi = 0; mi < MI; mi++)
#pragma unroll
        for (int ni = 0; ni < NI; ni++)
#pragma unroll
            for (int q = 0; q < 4; q++) acc[mi][ni][q] = 0.f;

    auto stage = [&](int s, int k0) {
        // A fp32: 64 rows x 32 floats = 8 x 16B chunks per row
#pragma unroll
        for (int it = 0; it < 2; it++) {
            int i = tid + it * 256;
            int row = i >> 3, c = i & 7;
            int gr = brow + row;
            int ok = (gr < M) ? 16 : 0;
            const float* srcp = A + (size_t)min(gr, M - 1) * 256 + k0 + c * 4;
            cp16(uAf + (unsigned)(s * SZAF + (row * LDSAF + c * 4) * 4), srcp, ok);
        }
        // B hi/lo: 256 rows x 4 chunks
#pragma unroll
        for (int it = 0; it < 4; it++) {
            int i = tid + it * 256;
            int row = i >> 2, c = i & 3;
            size_t go = (size_t)row * 256 + k0 + c * 8;
            unsigned dof = (unsigned)(s * SZB + (row * LDSB + c * 8) * 2);
            cp16(uBh + dof, Bth + go, 16);
            cp16(uBl + dof, Btl + go, 16);
        }
    };

    stage(0, 0);
    cp_commit();

#pragma unroll
    for (int it = 0; it < 8; it++) {
        const int s = it & 1;
        if (it < 7) {
            stage(s ^ 1, (it + 1) * 32);
            cp_commit();
            cp_wait<1>();
        } else {
            cp_wait<0>();
        }
        __syncthreads();

        // convert A fp32 stage s -> single fp16 buffer
        {
            int row = tid >> 2, seg = tid & 3;
            const char* pf = smem + s * SZAF + (row * LDSAF + seg * 8) * 4;
            float4 v0 = *(const float4*)pf;
            float4 v1 = *(const float4*)(pf + 16);
            __half hh[8];
            hh[0] = __float2half_rn(v0.x); hh[1] = __float2half_rn(v0.y);
            hh[2] = __float2half_rn(v0.z); hh[3] = __float2half_rn(v0.w);
            hh[4] = __float2half_rn(v1.x); hh[5] = __float2half_rn(v1.y);
            hh[6] = __float2half_rn(v1.z); hh[7] = __float2half_rn(v1.w);
            *(uint4*)(smem + OFF_AH + (row * LDSB + seg * 8) * 2) = *(uint4*)hh;
        }
        __syncthreads();

#pragma unroll
        for (int kk = 0; kk < 32; kk += 16) {
            unsigned ah[MI][4], bh[NI][2], bl[NI][2];
            const int ra = lane & 15;
            const int kca = (lane >> 4) << 3;
#pragma unroll
            for (int mi = 0; mi < MI; mi++) {
                unsigned off = (unsigned)(((mi * 16 + ra) * LDSB + kk + kca) * 2);
                ldsm_x4(ah[mi], uAh + off);
            }
            const int rb = (lane & 7) + ((lane >> 4) << 3);
            const int kcb = ((lane >> 3) & 1) << 3;
#pragma unroll
            for (int nb = 0; nb < NI / 2; nb++) {
                unsigned off = (unsigned)(((wn * 32 + nb * 16 + rb) * LDSB + kk + kcb) * 2) +
                               (unsigned)(s * SZB);
                unsigned t4[4];
                ldsm_x4(t4, uBh + off);
                bh[2 * nb][0] = t4[0]; bh[2 * nb][1] = t4[1];
                bh[2 * nb + 1][0] = t4[2]; bh[2 * nb + 1][1] = t4[3];
                ldsm_x4(t4, uBl + off);
                bl[2 * nb][0] = t4[0]; bl[2 * nb][1] = t4[1];
                bl[2 * nb + 1][0] = t4[2]; bl[2 * nb + 1][1] = t4[3];
            }
#pragma unroll
            for (int mi = 0; mi < MI; mi++)
#pragma unroll
                for (int ni = 0; ni < NI; ni++) {
                    mma_f16(acc[mi][ni], ah[mi], bh[ni]);
                    mma_f16(acc[mi][ni], ah[mi], bl[ni]);
                }
        }
        __syncthreads();
    }

    // epilogue: fused scores + fp16 store (a_heads read direct; L1-resident)
    const int g = lane >> 2, t = lane & 3;
    float asr[NI][2], adr[NI][2];
#pragma unroll
    for (int ni = 0; ni < NI; ni++)
#pragma unroll
        for (int qq = 0; qq < 2; qq++) {
            int cl = wn * 32 + ni * 8 + 2 * t + qq;  // global col (BN=256 = all cols)
            asr[ni][qq] = a_heads[(cl >> 6) * 128 + (cl & 63)];
            adr[ni][qq] = a_heads[(cl >> 6) * 128 + 64 + (cl & 63)];
        }
#pragma unroll
    for (int mi = 0; mi < MI; mi++) {
        float p0 = 0.f, q0 = 0.f, p1 = 0.f, q1 = 0.f;
#pragma unroll
        for (int ni = 0; ni < NI; ni++)
#pragma unroll
            for (int qq = 0; qq < 2; qq++) {
                p0 += acc[mi][ni][qq] * asr[ni][qq];
                q0 += acc[mi][ni][qq] * adr[ni][qq];
                p1 += acc[mi][ni][2 + qq] * asr[ni][qq];
                q1 += acc[mi][ni][2 + qq] * adr[ni][qq];
            }
#pragma unroll
        for (int o = 1; o <= 2; o <<= 1) {
            p0 += __shfl_xor_sync(FULLMASK, p0, o);
            q0 += __shfl_xor_sync(FULLMASK, q0, o);
            p1 += __shfl_xor_sync(FULLMASK, p1, o);
            q1 += __shfl_xor_sync(FULLMASK, q1, o);
        }
        int r0 = mi * 16 + g;
        if (t == 0) {
            sP[r0 * 8 + wn] = p0; sQ[r0 * 8 + wn] = q0;
            sP[(r0 + 8) * 8 + wn] = p1; sQ[(r0 + 8) * 8 + wn] = q1;
        }
        int gr0 = brow + r0;
#pragma unroll
        for (int ni = 0; ni < NI; ni++) {
            int c = wn * 32 + ni * 8 + 2 * t;
            if (gr0 < M)
                *(__half2*)(Whf + (size_t)gr0 * 256 + c) =
                    __floats2half2_rn(acc[mi][ni][0], acc[mi][ni][1]);
            if (gr0 + 8 < M)
                *(__half2*)(Whf + (size_t)(gr0 + 8) * 256 + c) =
                    __floats2half2_rn(acc[mi][ni][2], acc[mi][ni][3]);
        }
    }
    __syncthreads();
    {
        int row = tid >> 2, hd = tid & 3;  // 64 rows x 4 heads
        int gr = brow + row;
        float p = -3e38f, q = -3e38f;
        float pv = sP[row * 8 + 2 * hd] + sP[row * 8 + 2 * hd + 1];
        float qv = sQ[row * 8 + 2 * hd] + sQ[row * 8 + 2 * hd + 1];
        if (gr < M) {
            ((float*)g_s1src)[gr * 4 + hd] = pv;
            ((float*)g_s1dst)[gr * 4 + hd] = qv;
            p = pv; q = qv;
        }
#pragma unroll
        for (int o = 4; o <= 16; o <<= 1) {
            p = fmaxf(p, __shfl_xor_sync(FULLMASK, p, o));
            q = fmaxf(q, __shfl_xor_sync(FULLMASK, q, o));
        }
        if (lane < 4) {
            sMp[wid * 4 + lane] = p;
            sMq[wid * 4 + lane] = q;
        }
    }
    __syncthreads();
    if (tid < 32) {
        int h = tid & 3;
        float p = sMp[tid], q = sMq[tid];
#pragma unroll
        for (int o = 4; o <= 16; o <<= 1) {
            p = fmaxf(p, __shfl_xor_sync(FULLMASK, p, o));
            q = fmaxf(q, __shfl_xor_sync(FULLMASK, q, o));
        }
        if (tid < 4) {
            atomicMax(&g_gmax[h], encf(p));
            atomicMax(&g_gmax[4 + h], encf(q));
        }
    }
}

// ---------------- GEMM2: Wh2 = x @ W2 (fp16 1-term) + fused scores2 + max ----------------
__global__ __launch_bounds__(256, 2) void gemm2_kernel(
    const __half* __restrict__ A, const __half* __restrict__ Bt,
    __half* __restrict__ Whf, const float* __restrict__ a_out, int M) {
    constexpr int WM = 64, WN = 16, MI = 4, NI = 2, WNW = 4;
    constexpr int LDSB = 40;
    constexpr int SZA = 128 * LDSB * 2;
    constexpr int SZB = 64 * LDSB * 2;

    extern __shared__ char smem[];
    const unsigned uA = (unsigned)__cvta_generic_to_shared(smem);
    const unsigned uB = uA + 2 * SZA;
    __shared__ float sAS[64], sAD[64];
    __shared__ float sP[128][4], sQ[128][4];
    __shared__ float sMp[8], sMq[8];

    const int tid = threadIdx.x, lane = tid & 31, wid = tid >> 5;
    const int wm = wid / WNW, wn = wid % WNW;
    const int brow = blockIdx.y * 128;

    if (tid < 64) {
        sAS[tid] = (tid < NCLASS) ? a_out[tid] : 0.f;
        sAD[tid] = (tid < NCLASS) ? a_out[NCLASS + tid] : 0.f;
    }

    float acc[MI][NI][4];
#pragma unroll
    for (int mi = 0; mi < MI; mi++)
#pragma unroll
        for (int ni = 0; ni < NI; ni++)
#pragma unroll
            for (int q = 0; q < 4; q++) acc[mi][ni][q] = 0.f;

    auto stage = [&](int s, int k0) {
#pragma unroll
        for (int i = tid; i < 512; i += 256) {
            int row = i >> 2, c = i & 3;
            int gr = brow + row;
            int ok = (gr < M) ? 16 : 0;
            size_t go = (size_t)min(gr, M - 1) * 256 + k0 + c * 8;
            cp16(uA + (unsigned)(s * SZA + (row * LDSB + c * 8) * 2), A + go, ok);
        }
        if (tid < 256) {
            int row = tid >> 2, c = tid & 3;
            size_t go = (size_t)row * 256 + k0 + c * 8;
            cp16(uB + (unsigned)(s * SZB + (row * LDSB + c * 8) * 2), Bt + go, 16);
        }
    };

    stage(0, 0);
    cp_commit();

#pragma unroll
    for (int it = 0; it < 8; it++) {
        const int s = it & 1;
        if (it < 7) {
            stage(s ^ 1, (it + 1) * 32);
            cp_commit();
            cp_wait<1>();
        } else {
            cp_wait<0>();
        }
        __syncthreads();

#pragma unroll
        for (int kk = 0; kk < 32; kk += 16) {
            unsigned af[MI][4], bf[NI][2];
            const int ra = lane & 15;
            const int kca = (lane >> 4) << 3;
#pragma unroll
            for (int mi = 0; mi < MI; mi++) {
                unsigned off = (unsigned)(((wm * WM + mi * 16 + ra) * LDSB + kk + kca) * 2) +
                               (unsigned)(s * SZA);
                ldsm_x4(af[mi], uA + off);
            }
            const int rb = (lane & 7) + ((lane >> 4) << 3);
            const int kcb = ((lane >> 3) & 1) << 3;
            {
                unsigned off = (unsigned)(((wn * WN + rb) * LDSB + kk + kcb) * 2) +
                               (unsigned)(s * SZB);
                unsigned t4[4];
                ldsm_x4(t4, uB + off);
                bf[0][0] = t4[0]; bf[0][1] = t4[1];
                bf[1][0] = t4[2]; bf[1][1] = t4[3];
            }
#pragma unroll
            for (int mi = 0; mi < MI; mi++)
#pragma unroll
                for (int ni = 0; ni < NI; ni++)
                    mma_f16(acc[mi][ni], af[mi], bf[ni]);
        }
        __syncthreads();
    }

    const int g = lane >> 2, t = lane & 3;
#pragma unroll
    for (int mi = 0; mi < MI; mi++) {
        float p0 = 0.f, q0 = 0.f, p1 = 0.f, q1 = 0.f;
#pragma unroll
        for (int ni = 0; ni < NI; ni++)
#pragma unroll
            for (int qq = 0; qq < 2; qq++) {
                int cl = wn * WN + ni * 8 + 2 * t + qq;
                float as = sAS[cl], ad = sAD[cl];
                p0 += acc[mi][ni][qq] * as;
                q0 += acc[mi][ni][qq] * ad;
                p1 += acc[mi][ni][2 + qq] * as;
                q1 += acc[mi][ni][2 + qq] * ad;
            }
#pragma unroll
        for (int o = 1; o <= 2; o <<= 1) {
            p0 += __shfl_xor_sync(FULLMASK, p0, o);
            q0 += __shfl_xor_sync(FULLMASK, q0, o);
            p1 += __shfl_xor_sync(FULLMASK, p1, o);
            q1 += __shfl_xor_sync(FULLMASK, q1, o);
        }
        int r0 = wm * WM + mi * 16 + g;
        if (t == 0) {
            sP[r0][wn] = p0; sQ[r0][wn] = q0;
            sP[r0 + 8][wn] = p1; sQ[r0 + 8][wn] = q1;
        }
        int gr0 = brow + r0;
#pragma unroll
        for (int ni = 0; ni < NI; ni++) {
            int c = wn * WN + ni * 8 + 2 * t;
            if (c < NCLASS) {
                if (gr0 < M)
                    *(__half2*)(Whf + (size_t)gr0 * 40 + c) =
                        __floats2half2_rn(acc[mi][ni][0], acc[mi][ni][1]);
                if (gr0 + 8 < M)
                    *(__half2*)(Whf + (size_t)(gr0 + 8) * 40 + c) =
                        __floats2half2_rn(acc[mi][ni][2], acc[mi][ni][3]);
            }
        }
    }
    __syncthreads();
    {
        float p = -3e38f, q = -3e38f;
        if (tid < 128) {
            int gr = brow + tid;
            float pv = sP[tid][0] + sP[tid][1] + sP[tid][2] + sP[tid][3];
            float qv = sQ[tid][0] + sQ[tid][1] + sQ[tid][2] + sQ[tid][3];
            if (gr < M) {
                g_s2src[gr] = pv;
                g_s2dst[gr] = qv;
                p = pv; q = qv;
            }
        }
        p = wredmax(p);
        q = wredmax(q);
        if (lane == 0) {
            sMp[wid] = p;
            sMq[wid] = q;
        }
    }
    __syncthreads();
    if (tid == 0) {
        float p = sMp[0], q = sMq[0];
#pragma unroll
        for (int w = 1; w < 8; w++) {
            p = fmaxf(p, sMp[w]);
            q = fmaxf(q, sMq[w]);
        }
        atomicMax(&g_gmax[8], encf(p));
        atomicMax(&g_gmax[9], encf(q));
    }
}

// ---------------- CSR build (single-atomic: count stores rank) ----------------
__global__ void count_kernel(const int* __restrict__ dst) {
    int e = blockIdx.x * blockDim.x + threadIdx.x;
    if (e < N_EDGES) g_rank[e] = atomicAdd(&g_deg[dst[e]], 1);
}
__global__ void scan1_kernel(int n) {
    __shared__ int s[1024];
    int tid = threadIdx.x;
    int gid = blockIdx.x * 1024 + tid;
    int v = (gid < n) ? g_deg[gid] : 0;
    s[tid] = v;
    __syncthreads();
    int t = v;
    for (int d = 1; d < 1024; d <<= 1) {
        int add = (tid >= d) ? s[tid - d] : 0;
        __syncthreads();
        t += add;
        s[tid] = t;
        __syncthreads();
    }
    if (gid < n) g_off[gid] = t - v;
    if (tid == 1023) g_bsum[blockIdx.x] = t;
}
__global__ void scan2_kernel(int nb) {
    __shared__ int s[128];
    int tid = threadIdx.x;
    int v = (tid < nb) ? g_bsum[tid] : 0;
    s[tid] = v;
    __syncthreads();
    int t = v;
    for (int d = 1; d < 128; d <<= 1) {
        int add = (tid >= d) ? s[tid - d] : 0;
        __syncthreads();
        t += add;
        s[tid] = t;
        __syncthreads();
    }
    if (tid < nb) g_bsum2[tid] = t - v;
}
__global__ void scan3_kernel(int n) {
    int i = blockIdx.x * blockDim.x + threadIdx.x;
    if (i < n) g_off[i] += g_bsum2[i >> 10];
}
__global__ void fill_kernel(const int* __restrict__ dst, const int* __restrict__ src) {
    int e = blockIdx.x * blockDim.x + threadIdx.x;
    if (e >= N_EDGES) return;
    int pos = g_off[dst[e]] + g_rank[e];
    g_eid[pos] = src[e];
}

// ---------------- layer-1 aggregation: fp16 gather, single pass ----------------
__global__ void agg1_kernel() {
    __shared__ float4 sw[8][32];
    __shared__ int ssm[8][32];
    int gw = blockIdx.x * 8 + (threadIdx.x >> 5);
    int lane = threadIdx.x & 31;
    int wl = threadIdx.x >> 5;
    if (gw >= N_NODES) return;
    const int v = gw;
    const int off0 = g_off[v];
    const int deg = g_off[v + 1] - off0;
    const float4 sd = g_s1dst[v];

    float4 mx;
    mx.x = lrelu(decf(g_gmax[0]) + decf(g_gmax[4]));
    mx.y = lrelu(decf(g_gmax[1]) + decf(g_gmax[5]));
    mx.z = lrelu(decf(g_gmax[2]) + decf(g_gmax[6]));
    mx.w = lrelu(decf(g_gmax[3]) + decf(g_gmax[7]));

    float4 dn = make_float4(0.f, 0.f, 0.f, 0.f);
    float a[8];
#pragma unroll
    for (int j = 0; j < 8; j++) a[j] = 0.f;
    const int hsel = lane >> 3;
    const uint4* whb = (const uint4*)g_Wh1f;

    for (int base = 0; base < deg; base += 32) {
        int j = base + lane;
        float4 w4 = make_float4(0.f, 0.f, 0.f, 0.f);
        int s = 0;
        if (j < deg) {
            s = g_eid[off0 + j];
            float4 ss = g_s1src[s];
            w4.x = __expf(lrelu(ss.x + sd.x) - mx.x);
            w4.y = __expf(lrelu(ss.y + sd.y) - mx.y);
            w4.z = __expf(lrelu(ss.z + sd.z) - mx.z);
            w4.w = __expf(lrelu(ss.w + sd.w) - mx.w);
            dn.x += w4.x; dn.y += w4.y; dn.z += w4.z; dn.w += w4.w;
        }
        sw[wl][lane] = w4;
        ssm[wl][lane] = s;
        __syncwarp();
        int cnt = min(32, deg - base);
        for (int k = 0; k < cnt; k++) {
            int sk = ssm[wl][k];
            float wk = ((const float*)(sw[wl] + k))[hsel];
            uint4 rv = whb[(size_t)sk * 32 + lane];
            const __half2* hp = (const __half2*)&rv;
            float2 f0 = __half22float2(hp[0]);
            float2 f1 = __half22float2(hp[1]);
            float2 f2 = __half22float2(hp[2]);
            float2 f3 = __half22float2(hp[3]);
            a[0] += wk * f0.x; a[1] += wk * f0.y;
            a[2] += wk * f1.x; a[3] += wk * f1.y;
            a[4] += wk * f2.x; a[5] += wk * f2.y;
            a[6] += wk * f3.x; a[7] += wk * f3.y;
        }
        __syncwarp();
    }

    dn.x = wredsum(dn.x); dn.y = wredsum(dn.y);
    dn.z = wredsum(dn.z); dn.w = wredsum(dn.w);
    float invs[4];
    invs[0] = (deg > 0) ? 1.f / dn.x : 0.f;
    invs[1] = (deg > 0) ? 1.f / dn.y : 0.f;
    invs[2] = (deg > 0) ? 1.f / dn.z : 0.f;
    invs[3] = (deg > 0) ? 1.f / dn.w : 0.f;
    float invh = invs[hsel];

    __half hh[8];
#pragma unroll
    for (int j = 0; j < 8; j++) {
        float vv = a[j] * invh;
        vv = vv > 0.f ? vv : expm1f(vv);
        hh[j] = __float2half_rn(vv);
    }
    *(uint4*)(g_Xf + (size_t)v * 256 + lane * 8) = *(uint4*)hh;
}

// ---------------- layer-2 aggregation + log_softmax: fp16 gather ----------------
__global__ void agg2_kernel(float* __restrict__ out) {
    int gw = blockIdx.x * 8 + (threadIdx.x >> 5);
    int lane = threadIdx.x & 31;
    if (gw >= N_NODES) return;
    const int v = gw;
    const int off0 = g_off[v];
    const int deg = g_off[v + 1] - off0;
    const float sd = g_s2dst[v];
    const float mx = lrelu(decf(g_gmax[8]) + decf(g_gmax[9]));
    const bool valid = lane < 20;

    float dn = 0.f;
    float ax = 0.f, ay = 0.f;
    for (int base = 0; base < deg; base += 32) {
        int j = base + lane;
        float w = 0.f;
        int s = 0;
        if (j < deg) {
            s = g_eid[off0 + j];
            w = __expf(lrelu(g_s2src[s] + sd) - mx);
            dn += w;
        }
        int cnt = min(32, deg - base);
        for (int k = 0; k < cnt; k++) {
            int sk = __shfl_sync(FULLMASK, s, k);
            float wk = __shfl_sync(FULLMASK, w, k);
            if (valid) {
                __half2 hv = *((const __half2*)(g_Wh2f + (size_t)sk * 40) + lane);
                float2 f = __half22float2(hv);
                ax += wk * f.x;
                ay += wk * f.y;
            }
        }
    }
    dn = wredsum(dn);
    float inv = (deg > 0) ? 1.f / dn : 0.f;
    ax *= inv;
    ay *= inv;

    float m = wredmax(valid ? fmaxf(ax, ay) : -3e38f);
    float se = wredsum(valid ? (__expf(ax - m) + __expf(ay - m)) : 0.f);
    float lse = m + logf(se);
    if (valid) {
        out[(size_t)v * NCLASS + 2 * lane] = ax - lse;
        out[(size_t)v * NCLASS + 2 * lane + 1] = ay - lse;
    }
}

// ---------------- launcher ----------------
extern "C" void kernel_launch(void* const* d_in, const int* in_sizes, int n_in,
                              void* d_out, int out_size) {
    const float* h = (const float*)d_in[0];
    const int* ei = (const int*)d_in[1];
    const float* Wheads = (const float*)d_in[2];
    const float* aheads = (const float*)d_in[3];
    const float* Wout = (const float*)d_in[4];
    const float* aout = (const float*)d_in[5];
    const int* src = ei;
    const int* dst = ei + N_EDGES;
    float* out = (float*)d_out;

    __half *pW1h, *pW1l, *pW2f, *pWh1f, *pXf, *pWh2f;
    cudaGetSymbolAddress((void**)&pW1h, g_W1t_hi);
    cudaGetSymbolAddress((void**)&pW1l, g_W1t_lo);
    cudaGetSymbolAddress((void**)&pW2f, g_W2f);
    cudaGetSymbolAddress((void**)&pWh1f, g_Wh1f);
    cudaGetSymbolAddress((void**)&pXf, g_Xf);
    cudaGetSymbolAddress((void**)&pWh2f, g_Wh2f);

    constexpr int SMEM1 = 23552 + 4 * (256 * 40 * 2);             // 105472
    constexpr int SMEM2 = 2 * (128 * 40 * 2) + 2 * (64 * 40 * 2); // 30720

    cudaFuncSetAttribute((const void*)gemm1_kernel,
                         cudaFuncAttributeMaxDynamicSharedMemorySize, SMEM1);
    cudaFuncSetAttribute((const void*)gemm2_kernel,
                         cudaFuncAttributeMaxDynamicSharedMemorySize, SMEM2);

    // side stream + fork/join events (capture-time handles; graph keeps parallel branches)
    cudaStream_t s2;
    cudaStreamCreateWithFlags(&s2, cudaStreamNonBlocking);
    cudaEvent_t evF, evJ;
    cudaEventCreateWithFlags(&evF, cudaEventDisableTiming);
    cudaEventCreateWithFlags(&evJ, cudaEventDisableTiming);

    setup_kernel<<<(N_NODES + 256) / 256, 256>>>(Wheads, Wout);

    // fork: CSR chain on s2, concurrent with GEMM1 on the main stream
    cudaEventRecord(evF, cudaStreamPerThread);
    cudaStreamWaitEvent(s2, evF, 0);
    count_kernel<<<N_EDGES / 256, 256, 0, s2>>>(dst);
    {
        int n = N_NODES + 1;
        int nb = (n + 1023) / 1024;  // 98
        scan1_kernel<<<nb, 1024, 0, s2>>>(n);
        scan2_kernel<<<1, 128, 0, s2>>>(nb);
        scan3_kernel<<<(n + 255) / 256, 256, 0, s2>>>(n);
    }
    fill_kernel<<<N_EDGES / 256, 256, 0, s2>>>(dst, src);
    cudaEventRecord(evJ, s2);

    gemm1_kernel<<<dim3(1, (N_NODES + 63) / 64), 256, SMEM1>>>(
        h, pW1h, pW1l, pWh1f, aheads, N_NODES);

    // join: agg1 needs both CSR and GEMM1 results
    cudaStreamWaitEvent(cudaStreamPerThread, evJ, 0);

    agg1_kernel<<<(N_NODES + 7) / 8, 256>>>();

    gemm2_kernel<<<dim3(1, (N_NODES + 127) / 128), 256, SMEM2>>>(
        pXf, pW2f, pWh2f, aout, N_NODES);

    agg2_kernel<<<(N_NODES + 7) / 8, 256>>>(out);
}